// round 2
// baseline (speedup 1.0000x reference)
#include <cuda_runtime.h>
#include <cstdint>

// ---------------------------------------------------------------------------
// Problem constants
// ---------------------------------------------------------------------------
#define BB   16
#define NN   1024
#define KK   512
#define DIN  64
#define HH   256
#define NHH  8
#define HD   32
#define FF   1024
#define LL   2
#define TOK  (BB * NN)   // 16384 tokens

// ---------------------------------------------------------------------------
// Device scratch (static globals: allocation-free rule)
// ---------------------------------------------------------------------------
__device__ float g_h   [TOK * HH];     // running hidden state
__device__ float g_tmp [TOK * HH];     // pre-LN buffer
__device__ float g_qkv [TOK * 3 * HH]; // qkv projections
__device__ float g_attn[TOK * HH];     // attention output
__device__ float g_ff  [TOK * FF];     // ffn hidden

// ---------------------------------------------------------------------------
// SGEMM: C[M,N] = A[M,K] @ W[K,N] + bias[N] (+ res[M,N]) (+ relu)
// 128x128 block tile, 8x8 per thread, BK=8. fp32 SIMT.
// Requires: M%128==0, N%128==0, K%8==0 (all shapes here satisfy this).
// ---------------------------------------------------------------------------
__global__ __launch_bounds__(256) void sgemm_kernel(
    const float* __restrict__ A, const float* __restrict__ W,
    const float* __restrict__ bias, const float* __restrict__ res,
    float* __restrict__ C, int M, int K, int N, int relu)
{
    __shared__ float As[8][128];
    __shared__ float Bs[8][128];

    const int tid  = threadIdx.x;
    const int m0   = blockIdx.y * 128;
    const int n0   = blockIdx.x * 128;
    const int trow = tid >> 4;        // 0..15 -> rows trow*8..+7
    const int tcol = tid & 15;        // 0..15 -> cols tcol*8..+7

    float acc[8][8];
    #pragma unroll
    for (int i = 0; i < 8; i++)
        #pragma unroll
        for (int j = 0; j < 8; j++) acc[i][j] = 0.f;

    // load assignments
    const int arow = tid >> 1;          // 0..127
    const int acol = (tid & 1) * 4;     // 0 or 4
    const int brow = tid >> 5;          // 0..7
    const int bcol = (tid & 31) * 4;    // 0..124

    const float* Aptr = A + (size_t)(m0 + arow) * K + acol;
    const float* Wptr = W + (size_t)brow * N + (n0 + bcol);

    for (int k0 = 0; k0 < K; k0 += 8) {
        float4 av = *(const float4*)(Aptr + k0);
        As[acol + 0][arow] = av.x;
        As[acol + 1][arow] = av.y;
        As[acol + 2][arow] = av.z;
        As[acol + 3][arow] = av.w;
        *(float4*)&Bs[brow][bcol] = *(const float4*)(Wptr + (size_t)k0 * N);
        __syncthreads();

        #pragma unroll
        for (int k = 0; k < 8; k++) {
            float a[8], b[8];
            *(float4*)&a[0] = *(const float4*)&As[k][trow * 8];
            *(float4*)&a[4] = *(const float4*)&As[k][trow * 8 + 4];
            *(float4*)&b[0] = *(const float4*)&Bs[k][tcol * 8];
            *(float4*)&b[4] = *(const float4*)&Bs[k][tcol * 8 + 4];
            #pragma unroll
            for (int i = 0; i < 8; i++)
                #pragma unroll
                for (int j = 0; j < 8; j++)
                    acc[i][j] += a[i] * b[j];
        }
        __syncthreads();
    }

    // epilogue
    float bv[8];
    #pragma unroll
    for (int j = 0; j < 8; j++) bv[j] = bias[n0 + tcol * 8 + j];

    #pragma unroll
    for (int i = 0; i < 8; i++) {
        const int row = m0 + trow * 8 + i;
        float* Crow = C + (size_t)row * N + n0 + tcol * 8;
        float out[8];
        #pragma unroll
        for (int j = 0; j < 8; j++) out[j] = acc[i][j] + bv[j];
        if (res) {
            const float* Rrow = res + (size_t)row * N + n0 + tcol * 8;
            float4 r0 = *(const float4*)&Rrow[0];
            float4 r1 = *(const float4*)&Rrow[4];
            out[0] += r0.x; out[1] += r0.y; out[2] += r0.z; out[3] += r0.w;
            out[4] += r1.x; out[5] += r1.y; out[6] += r1.z; out[7] += r1.w;
        }
        if (relu) {
            #pragma unroll
            for (int j = 0; j < 8; j++) out[j] = fmaxf(out[j], 0.f);
        }
        *(float4*)&Crow[0] = *(float4*)&out[0];
        *(float4*)&Crow[4] = *(float4*)&out[4];
    }
}

// ---------------------------------------------------------------------------
// Flash-attention (fp32, online softmax). qkv: [TOK, 768], out: [TOK, 256].
// One block per (64 queries, head). K/V streamed in 64-row tiles.
// ---------------------------------------------------------------------------
__global__ __launch_bounds__(256) void attn_kernel(
    const float* __restrict__ qkv, float* __restrict__ out)
{
    const int b  = blockIdx.y >> 3;
    const int h  = blockIdx.y & 7;
    const int q0 = blockIdx.x * 64;
    const int tid = threadIdx.x;

    __shared__ float Qs[64][33];
    __shared__ float Ks[64][33];
    __shared__ float Vs[64][33];
    __shared__ float Ps[64][65];
    __shared__ float m_s[64], l_s[64], sc_s[64];

    const size_t base = (size_t)b * NN;
    const float scale = 0.17677669529663687f;  // 1/sqrt(32)

    // load Q (pre-scaled)
    #pragma unroll
    for (int it = 0; it < 8; it++) {
        int idx = tid + it * 256;
        int r = idx >> 5, d = idx & 31;
        Qs[r][d] = qkv[(base + q0 + r) * 768 + h * 32 + d] * scale;
    }
    if (tid < 64) { m_s[tid] = -1e30f; l_s[tid] = 0.f; }

    // mapping A (score compute): 4x4 tile of 64x64 S
    const int tr = tid >> 4;   // rows tr*4..+3
    const int tc = tid & 15;   // cols tc*4..+3
    // mapping B (O accum): 2 rows x 4 dims of 64x32 O
    const int tidy = tid >> 3; // rows tidy*2, tidy*2+1
    const int tidx = tid & 7;  // dims tidx*4..+3

    float o0[4] = {0.f, 0.f, 0.f, 0.f};
    float o1[4] = {0.f, 0.f, 0.f, 0.f};
    __syncthreads();

    for (int kt = 0; kt < NN / 64; kt++) {
        const int k0 = kt * 64;
        #pragma unroll
        for (int it = 0; it < 8; it++) {
            int idx = tid + it * 256;
            int r = idx >> 5, d = idx & 31;
            size_t t = (base + k0 + r) * 768;
            Ks[r][d] = qkv[t + 256 + h * 32 + d];
            Vs[r][d] = qkv[t + 512 + h * 32 + d];
        }
        __syncthreads();

        // S = Q @ K^T (scaled)
        float s[4][4];
        #pragma unroll
        for (int i = 0; i < 4; i++)
            #pragma unroll
            for (int j = 0; j < 4; j++) s[i][j] = 0.f;

        for (int d = 0; d < 32; d++) {
            float a[4], bb[4];
            #pragma unroll
            for (int i = 0; i < 4; i++) a[i]  = Qs[tr * 4 + i][d];
            #pragma unroll
            for (int j = 0; j < 4; j++) bb[j] = Ks[tc * 4 + j][d];
            #pragma unroll
            for (int i = 0; i < 4; i++)
                #pragma unroll
                for (int j = 0; j < 4; j++)
                    s[i][j] += a[i] * bb[j];
        }

        // online softmax per row (16 threads share a row group of 4 rows)
        #pragma unroll
        for (int i = 0; i < 4; i++) {
            const int row = tr * 4 + i;
            float rmax = fmaxf(fmaxf(s[i][0], s[i][1]), fmaxf(s[i][2], s[i][3]));
            #pragma unroll
            for (int off = 1; off < 16; off <<= 1)
                rmax = fmaxf(rmax, __shfl_xor_sync(0xffffffffu, rmax, off));
            const float m_old = m_s[row];
            const float m_new = fmaxf(m_old, rmax);
            float lsum = 0.f;
            #pragma unroll
            for (int j = 0; j < 4; j++) {
                float p = __expf(s[i][j] - m_new);
                Ps[row][tc * 4 + j] = p;
                lsum += p;
            }
            #pragma unroll
            for (int off = 1; off < 16; off <<= 1)
                lsum += __shfl_xor_sync(0xffffffffu, lsum, off);
            if (tc == 0) {
                const float scl = __expf(m_old - m_new);
                sc_s[row] = scl;
                l_s[row]  = l_s[row] * scl + lsum;
                m_s[row]  = m_new;
            }
        }
        __syncthreads();

        // O = diag(scale)*O + P @ V
        const int r0 = tidy * 2, r1 = r0 + 1;
        const float sc0 = sc_s[r0], sc1 = sc_s[r1];
        #pragma unroll
        for (int dd = 0; dd < 4; dd++) { o0[dd] *= sc0; o1[dd] *= sc1; }
        for (int kk = 0; kk < 64; kk++) {
            const float p0 = Ps[r0][kk];
            const float p1 = Ps[r1][kk];
            #pragma unroll
            for (int dd = 0; dd < 4; dd++) {
                const float v = Vs[kk][tidx * 4 + dd];
                o0[dd] += p0 * v;
                o1[dd] += p1 * v;
            }
        }
        __syncthreads();
    }

    const int r0 = tidy * 2, r1 = r0 + 1;
    const float inv0 = 1.f / l_s[r0];
    const float inv1 = 1.f / l_s[r1];
    #pragma unroll
    for (int dd = 0; dd < 4; dd++) {
        out[(base + q0 + r0) * HH + h * 32 + tidx * 4 + dd] = o0[dd] * inv0;
        out[(base + q0 + r1) * HH + h * 32 + tidx * 4 + dd] = o1[dd] * inv1;
    }
}

// ---------------------------------------------------------------------------
// LayerNorm over last dim (256). Warp per row, 8 rows per block.
// ---------------------------------------------------------------------------
__global__ __launch_bounds__(256) void ln_kernel(
    const float* __restrict__ x, const float* __restrict__ gam,
    const float* __restrict__ bet, float* __restrict__ out)
{
    const int row  = blockIdx.x * 8 + (threadIdx.x >> 5);
    const int lane = threadIdx.x & 31;
    const float* xr = x + (size_t)row * HH;

    float v[8];
    float sum = 0.f;
    #pragma unroll
    for (int i = 0; i < 8; i++) { v[i] = xr[lane + i * 32]; sum += v[i]; }
    #pragma unroll
    for (int off = 16; off; off >>= 1) sum += __shfl_xor_sync(0xffffffffu, sum, off);
    const float mean = sum * (1.f / HH);

    float var = 0.f;
    #pragma unroll
    for (int i = 0; i < 8; i++) { float d = v[i] - mean; var += d * d; }
    #pragma unroll
    for (int off = 16; off; off >>= 1) var += __shfl_xor_sync(0xffffffffu, var, off);
    var *= (1.f / HH);
    const float inv = rsqrtf(var + 1e-5f);

    float* orow = out + (size_t)row * HH;
    #pragma unroll
    for (int i = 0; i < 8; i++) {
        const int c = lane + i * 32;
        orow[c] = (v[i] - mean) * inv * gam[c] + bet[c];
    }
}

// ---------------------------------------------------------------------------
// Output init: indices (as float) + zero the bw region
// ---------------------------------------------------------------------------
__global__ void init_out_kernel(const int* __restrict__ sel, float* __restrict__ out,
                                int out_size, int both)
{
    const int i = blockIdx.x * 256 + threadIdx.x;
    if (i >= out_size) return;
    if (both && i < BB * KK) out[i] = (float)sel[i];
    else out[i] = 0.f;
}

// ---------------------------------------------------------------------------
// Allocation: gather-mean -> ctx = mean@Wc+bc -> scores -> softmax*100 ->
// round -> fix-up -> scatter. One block per batch.
// ---------------------------------------------------------------------------
__global__ __launch_bounds__(256) void alloc_kernel(
    const float* __restrict__ enc, const int* __restrict__ sel,
    const float* __restrict__ Wc, const float* __restrict__ bc,
    float* __restrict__ bw)
{
    __shared__ float mean_s[HH];
    __shared__ float ctx_s[HH];
    __shared__ float sc_s[KK];
    __shared__ float red_s[256];
    __shared__ int   idx_s[KK];

    const int b = blockIdx.x, tid = threadIdx.x;

    idx_s[tid]       = sel[b * KK + tid];
    idx_s[tid + 256] = sel[b * KK + tid + 256];
    __syncthreads();

    // masked mean over gathered rows (thread = channel)
    float acc = 0.f; int cnt = 0;
    for (int k = 0; k < KK; k++) {
        const int idx = idx_s[k];
        if (idx < NN) { acc += enc[((size_t)b * NN + idx) * HH + tid]; cnt++; }
    }
    const float cntf = (float)(cnt > 0 ? cnt : 1);
    mean_s[tid] = acc / cntf;
    __syncthreads();

    // ctx = mean @ Wc + bc
    float c = bc[tid];
    for (int i = 0; i < HH; i++) c += mean_s[i] * Wc[i * HH + tid];
    ctx_s[tid] = c;
    __syncthreads();

    // scores[k] = ctx . enc[idx_k]  (warp per row, strided)
    const int wid = tid >> 5, lane = tid & 31;
    for (int k = wid; k < KK; k += 8) {
        const int idx = idx_s[k];
        float s = -1e30f;
        if (idx < NN) {
            const float* row = enc + ((size_t)b * NN + idx) * HH;
            float part = 0.f;
            #pragma unroll
            for (int i = 0; i < 8; i++) part += ctx_s[lane + i * 32] * row[lane + i * 32];
            #pragma unroll
            for (int off = 16; off; off >>= 1)
                part += __shfl_xor_sync(0xffffffffu, part, off);
            s = part;
        }
        if (lane == 0) sc_s[k] = s;
    }
    __syncthreads();

    // block max
    red_s[tid] = fmaxf(sc_s[tid], sc_s[tid + 256]);
    __syncthreads();
    for (int st = 128; st; st >>= 1) {
        if (tid < st) red_s[tid] = fmaxf(red_s[tid], red_s[tid + st]);
        __syncthreads();
    }
    const float m = red_s[0];
    __syncthreads();

    // exp + sum (invalid -> 0)
    const int i0 = idx_s[tid], i1 = idx_s[tid + 256];
    const float e0 = (i0 < NN) ? expf(sc_s[tid] - m)       : 0.f;
    const float e1 = (i1 < NN) ? expf(sc_s[tid + 256] - m) : 0.f;
    red_s[tid] = e0 + e1;
    __syncthreads();
    for (int st = 128; st; st >>= 1) {
        if (tid < st) red_s[tid] += red_s[tid + st];
        __syncthreads();
    }
    const float denom = red_s[0];
    __syncthreads();

    // rounded allocation (rintf == round-half-even == jnp.round)
    float a0 = rintf(e0 / denom * 100.f);
    float a1 = rintf(e1 / denom * 100.f);
    red_s[tid] = a0 + a1;
    __syncthreads();
    for (int st = 128; st; st >>= 1) {
        if (tid < st) red_s[tid] += red_s[tid + st];
        __syncthreads();
    }
    const float diff = 100.f - red_s[0];
    __syncthreads();

    if (tid == 0 && i0 < NN) a0 += diff;   // thread 0 owns k=0

    if (i0 < NN) bw[b * NN + i0] = a0;
    if (i1 < NN) bw[b * NN + i1] = a1;
}

// ---------------------------------------------------------------------------
// Launch
// ---------------------------------------------------------------------------
extern "C" void kernel_launch(void* const* d_in, const int* in_sizes, int n_in,
                              void* d_out, int out_size)
{
    const float* x     = (const float*)d_in[0];
    const int*   sel   = (const int*)  d_in[1];
    const float* W_in  = (const float*)d_in[2];
    const float* b_in  = (const float*)d_in[3];
    const float* Wqkv  = (const float*)d_in[4];
    const float* bqkv  = (const float*)d_in[5];
    const float* Wo    = (const float*)d_in[6];
    const float* bo    = (const float*)d_in[7];
    const float* ln1g  = (const float*)d_in[8];
    const float* ln1b  = (const float*)d_in[9];
    const float* W1    = (const float*)d_in[10];
    const float* b1    = (const float*)d_in[11];
    const float* W2    = (const float*)d_in[12];
    const float* b2    = (const float*)d_in[13];
    const float* ln2g  = (const float*)d_in[14];
    const float* ln2b  = (const float*)d_in[15];
    const float* Wc    = (const float*)d_in[16];
    const float* bc    = (const float*)d_in[17];

    float *h, *tmp, *qkvb, *attnb, *ffb;
    cudaGetSymbolAddress((void**)&h,     g_h);
    cudaGetSymbolAddress((void**)&tmp,   g_tmp);
    cudaGetSymbolAddress((void**)&qkvb,  g_qkv);
    cudaGetSymbolAddress((void**)&attnb, g_attn);
    cudaGetSymbolAddress((void**)&ffb,   g_ff);

    const dim3 blk(256);

    // h = x @ W_in + b_in
    sgemm_kernel<<<dim3(HH / 128, TOK / 128), blk>>>(
        x, W_in, b_in, nullptr, h, TOK, DIN, HH, 0);

    for (int l = 0; l < LL; l++) {
        // qkv = h @ Wqkv[l] + bqkv[l]
        sgemm_kernel<<<dim3(3 * HH / 128, TOK / 128), blk>>>(
            h, Wqkv + (size_t)l * HH * 3 * HH, bqkv + (size_t)l * 3 * HH,
            nullptr, qkvb, TOK, HH, 3 * HH, 0);

        // attention
        attn_kernel<<<dim3(NN / 64, BB * NHH), blk>>>(qkvb, attnb);

        // tmp = attn @ Wo[l] + bo[l] + h ; h = LN1(tmp)
        sgemm_kernel<<<dim3(HH / 128, TOK / 128), blk>>>(
            attnb, Wo + (size_t)l * HH * HH, bo + (size_t)l * HH,
            h, tmp, TOK, HH, HH, 0);
        ln_kernel<<<TOK / 8, blk>>>(tmp, ln1g + l * HH, ln1b + l * HH, h);

        // ff = relu(h @ W1[l] + b1[l])
        sgemm_kernel<<<dim3(FF / 128, TOK / 128), blk>>>(
            h, W1 + (size_t)l * HH * FF, b1 + (size_t)l * FF,
            nullptr, ffb, TOK, HH, FF, 1);

        // tmp = ff @ W2[l] + b2[l] + h ; h = LN2(tmp)
        sgemm_kernel<<<dim3(HH / 128, TOK / 128), blk>>>(
            ffb, W2 + (size_t)l * FF * HH, b2 + (size_t)l * HH,
            h, tmp, TOK, FF, HH, 0);
        ln_kernel<<<TOK / 8, blk>>>(tmp, ln2g + l * HH, ln2b + l * HH, h);
    }

    // output assembly
    float* outf = (float*)d_out;
    const int idx_elems = BB * KK;          // 8192
    const int bw_elems  = BB * NN;          // 16384
    const int both = (out_size >= idx_elems + bw_elems) ? 1 : 0;
    float* bw = both ? (outf + idx_elems) : outf;

    init_out_kernel<<<(out_size + 255) / 256, blk>>>(sel, outf, out_size, both);
    alloc_kernel<<<BB, blk>>>(h, sel, Wc, bc, bw);
}

// round 3
// speedup vs baseline: 1.0024x; 1.0024x over previous
#include <cuda_runtime.h>
#include <cstdint>

// ---------------------------------------------------------------------------
// Problem constants
// ---------------------------------------------------------------------------
#define BB   16
#define NN   1024
#define KK   512
#define DIN  64
#define HH   256
#define NHH  8
#define HD   32
#define FF   1024
#define LL   2
#define TOK  (BB * NN)   // 16384 tokens

// ---------------------------------------------------------------------------
// Device scratch (static globals: allocation-free rule)
// ---------------------------------------------------------------------------
__device__ float g_h   [TOK * HH];     // running hidden state
__device__ float g_tmp [TOK * HH];     // pre-LN buffer
__device__ float g_qkv [TOK * 3 * HH]; // qkv projections
__device__ float g_attn[TOK * HH];     // attention output
__device__ float g_ff  [TOK * FF];     // ffn hidden

// ---------------------------------------------------------------------------
// SGEMM: C[M,N] = A[M,K] @ W[K,N] + bias[N] (+ res[M,N]) (+ relu)
// 128x128 block tile, 8x8 per thread, BK=8. fp32 SIMT.
// Requires: M%128==0, N%128==0, K%8==0 (all shapes here satisfy this).
// ---------------------------------------------------------------------------
__global__ __launch_bounds__(256) void sgemm_kernel(
    const float* __restrict__ A, const float* __restrict__ W,
    const float* __restrict__ bias, const float* __restrict__ res,
    float* __restrict__ C, int M, int K, int N, int relu)
{
    __shared__ float As[8][128];
    __shared__ float Bs[8][128];

    const int tid  = threadIdx.x;
    const int m0   = blockIdx.y * 128;
    const int n0   = blockIdx.x * 128;
    const int trow = tid >> 4;        // 0..15 -> rows trow*8..+7
    const int tcol = tid & 15;        // 0..15 -> cols tcol*8..+7

    float acc[8][8];
    #pragma unroll
    for (int i = 0; i < 8; i++)
        #pragma unroll
        for (int j = 0; j < 8; j++) acc[i][j] = 0.f;

    // load assignments
    const int arow = tid >> 1;          // 0..127
    const int acol = (tid & 1) * 4;     // 0 or 4
    const int brow = tid >> 5;          // 0..7
    const int bcol = (tid & 31) * 4;    // 0..124

    const float* Aptr = A + (size_t)(m0 + arow) * K + acol;
    const float* Wptr = W + (size_t)brow * N + (n0 + bcol);

    for (int k0 = 0; k0 < K; k0 += 8) {
        float4 av = *(const float4*)(Aptr + k0);
        As[acol + 0][arow] = av.x;
        As[acol + 1][arow] = av.y;
        As[acol + 2][arow] = av.z;
        As[acol + 3][arow] = av.w;
        *(float4*)&Bs[brow][bcol] = *(const float4*)(Wptr + (size_t)k0 * N);
        __syncthreads();

        #pragma unroll
        for (int k = 0; k < 8; k++) {
            float a[8], b[8];
            *(float4*)&a[0] = *(const float4*)&As[k][trow * 8];
            *(float4*)&a[4] = *(const float4*)&As[k][trow * 8 + 4];
            *(float4*)&b[0] = *(const float4*)&Bs[k][tcol * 8];
            *(float4*)&b[4] = *(const float4*)&Bs[k][tcol * 8 + 4];
            #pragma unroll
            for (int i = 0; i < 8; i++)
                #pragma unroll
                for (int j = 0; j < 8; j++)
                    acc[i][j] += a[i] * b[j];
        }
        __syncthreads();
    }

    // epilogue
    float bv[8];
    #pragma unroll
    for (int j = 0; j < 8; j++) bv[j] = bias[n0 + tcol * 8 + j];

    #pragma unroll
    for (int i = 0; i < 8; i++) {
        const int row = m0 + trow * 8 + i;
        float* Crow = C + (size_t)row * N + n0 + tcol * 8;
        float out[8];
        #pragma unroll
        for (int j = 0; j < 8; j++) out[j] = acc[i][j] + bv[j];
        if (res) {
            const float* Rrow = res + (size_t)row * N + n0 + tcol * 8;
            float4 r0 = *(const float4*)&Rrow[0];
            float4 r1 = *(const float4*)&Rrow[4];
            out[0] += r0.x; out[1] += r0.y; out[2] += r0.z; out[3] += r0.w;
            out[4] += r1.x; out[5] += r1.y; out[6] += r1.z; out[7] += r1.w;
        }
        if (relu) {
            #pragma unroll
            for (int j = 0; j < 8; j++) out[j] = fmaxf(out[j], 0.f);
        }
        *(float4*)&Crow[0] = *(float4*)&out[0];
        *(float4*)&Crow[4] = *(float4*)&out[4];
    }
}

// ---------------------------------------------------------------------------
// Flash-attention (fp32, online softmax). qkv: [TOK, 768], out: [TOK, 256].
// One block per (64 queries, head). K/V streamed in 64-row tiles.
// ---------------------------------------------------------------------------
__global__ __launch_bounds__(256) void attn_kernel(
    const float* __restrict__ qkv, float* __restrict__ out)
{
    const int b  = blockIdx.y >> 3;
    const int h  = blockIdx.y & 7;
    const int q0 = blockIdx.x * 64;
    const int tid = threadIdx.x;

    __shared__ float Qs[64][33];
    __shared__ float Ks[64][33];
    __shared__ float Vs[64][33];
    __shared__ float Ps[64][65];
    __shared__ float m_s[64], l_s[64], sc_s[64];

    const size_t base = (size_t)b * NN;
    const float scale = 0.17677669529663687f;  // 1/sqrt(32)

    // load Q (pre-scaled)
    #pragma unroll
    for (int it = 0; it < 8; it++) {
        int idx = tid + it * 256;
        int r = idx >> 5, d = idx & 31;
        Qs[r][d] = qkv[(base + q0 + r) * 768 + h * 32 + d] * scale;
    }
    if (tid < 64) { m_s[tid] = -1e30f; l_s[tid] = 0.f; }

    // mapping A (score compute): 4x4 tile of 64x64 S
    const int tr = tid >> 4;   // rows tr*4..+3
    const int tc = tid & 15;   // cols tc*4..+3
    // mapping B (O accum): 2 rows x 4 dims of 64x32 O
    const int tidy = tid >> 3; // rows tidy*2, tidy*2+1
    const int tidx = tid & 7;  // dims tidx*4..+3

    float o0[4] = {0.f, 0.f, 0.f, 0.f};
    float o1[4] = {0.f, 0.f, 0.f, 0.f};
    __syncthreads();

    for (int kt = 0; kt < NN / 64; kt++) {
        const int k0 = kt * 64;
        #pragma unroll
        for (int it = 0; it < 8; it++) {
            int idx = tid + it * 256;
            int r = idx >> 5, d = idx & 31;
            size_t t = (base + k0 + r) * 768;
            Ks[r][d] = qkv[t + 256 + h * 32 + d];
            Vs[r][d] = qkv[t + 512 + h * 32 + d];
        }
        __syncthreads();

        // S = Q @ K^T (scaled)
        float s[4][4];
        #pragma unroll
        for (int i = 0; i < 4; i++)
            #pragma unroll
            for (int j = 0; j < 4; j++) s[i][j] = 0.f;

        for (int d = 0; d < 32; d++) {
            float a[4], bb[4];
            #pragma unroll
            for (int i = 0; i < 4; i++) a[i]  = Qs[tr * 4 + i][d];
            #pragma unroll
            for (int j = 0; j < 4; j++) bb[j] = Ks[tc * 4 + j][d];
            #pragma unroll
            for (int i = 0; i < 4; i++)
                #pragma unroll
                for (int j = 0; j < 4; j++)
                    s[i][j] += a[i] * bb[j];
        }

        // online softmax per row (16 threads share a row group of 4 rows)
        #pragma unroll
        for (int i = 0; i < 4; i++) {
            const int row = tr * 4 + i;
            float rmax = fmaxf(fmaxf(s[i][0], s[i][1]), fmaxf(s[i][2], s[i][3]));
            #pragma unroll
            for (int off = 1; off < 16; off <<= 1)
                rmax = fmaxf(rmax, __shfl_xor_sync(0xffffffffu, rmax, off));
            const float m_old = m_s[row];
            const float m_new = fmaxf(m_old, rmax);
            float lsum = 0.f;
            #pragma unroll
            for (int j = 0; j < 4; j++) {
                float p = __expf(s[i][j] - m_new);
                Ps[row][tc * 4 + j] = p;
                lsum += p;
            }
            #pragma unroll
            for (int off = 1; off < 16; off <<= 1)
                lsum += __shfl_xor_sync(0xffffffffu, lsum, off);
            if (tc == 0) {
                const float scl = __expf(m_old - m_new);
                sc_s[row] = scl;
                l_s[row]  = l_s[row] * scl + lsum;
                m_s[row]  = m_new;
            }
        }
        __syncthreads();

        // O = diag(scale)*O + P @ V
        const int r0 = tidy * 2, r1 = r0 + 1;
        const float sc0 = sc_s[r0], sc1 = sc_s[r1];
        #pragma unroll
        for (int dd = 0; dd < 4; dd++) { o0[dd] *= sc0; o1[dd] *= sc1; }
        for (int kk = 0; kk < 64; kk++) {
            const float p0 = Ps[r0][kk];
            const float p1 = Ps[r1][kk];
            #pragma unroll
            for (int dd = 0; dd < 4; dd++) {
                const float v = Vs[kk][tidx * 4 + dd];
                o0[dd] += p0 * v;
                o1[dd] += p1 * v;
            }
        }
        __syncthreads();
    }

    const int r0 = tidy * 2, r1 = r0 + 1;
    const float inv0 = 1.f / l_s[r0];
    const float inv1 = 1.f / l_s[r1];
    #pragma unroll
    for (int dd = 0; dd < 4; dd++) {
        out[(base + q0 + r0) * HH + h * 32 + tidx * 4 + dd] = o0[dd] * inv0;
        out[(base + q0 + r1) * HH + h * 32 + tidx * 4 + dd] = o1[dd] * inv1;
    }
}

// ---------------------------------------------------------------------------
// LayerNorm over last dim (256). Warp per row, 8 rows per block.
// ---------------------------------------------------------------------------
__global__ __launch_bounds__(256) void ln_kernel(
    const float* __restrict__ x, const float* __restrict__ gam,
    const float* __restrict__ bet, float* __restrict__ out)
{
    const int row  = blockIdx.x * 8 + (threadIdx.x >> 5);
    const int lane = threadIdx.x & 31;
    const float* xr = x + (size_t)row * HH;

    float v[8];
    float sum = 0.f;
    #pragma unroll
    for (int i = 0; i < 8; i++) { v[i] = xr[lane + i * 32]; sum += v[i]; }
    #pragma unroll
    for (int off = 16; off; off >>= 1) sum += __shfl_xor_sync(0xffffffffu, sum, off);
    const float mean = sum * (1.f / HH);

    float var = 0.f;
    #pragma unroll
    for (int i = 0; i < 8; i++) { float d = v[i] - mean; var += d * d; }
    #pragma unroll
    for (int off = 16; off; off >>= 1) var += __shfl_xor_sync(0xffffffffu, var, off);
    var *= (1.f / HH);
    const float inv = rsqrtf(var + 1e-5f);

    float* orow = out + (size_t)row * HH;
    #pragma unroll
    for (int i = 0; i < 8; i++) {
        const int c = lane + i * 32;
        orow[c] = (v[i] - mean) * inv * gam[c] + bet[c];
    }
}

// ---------------------------------------------------------------------------
// Output init: indices (as float) + zero the bw region
// ---------------------------------------------------------------------------
__global__ void init_out_kernel(const int* __restrict__ sel, float* __restrict__ out,
                                int out_size, int both)
{
    const int i = blockIdx.x * 256 + threadIdx.x;
    if (i >= out_size) return;
    if (both && i < BB * KK) out[i] = (float)sel[i];
    else out[i] = 0.f;
}

// ---------------------------------------------------------------------------
// Allocation: gather-mean -> ctx = mean@Wc+bc -> scores -> softmax*100 ->
// round -> fix-up -> scatter. One block per batch.
// ---------------------------------------------------------------------------
__global__ __launch_bounds__(256) void alloc_kernel(
    const float* __restrict__ enc, const int* __restrict__ sel,
    const float* __restrict__ Wc, const float* __restrict__ bc,
    float* __restrict__ bw)
{
    __shared__ float mean_s[HH];
    __shared__ float ctx_s[HH];
    __shared__ float sc_s[KK];
    __shared__ float red_s[256];
    __shared__ int   idx_s[KK];

    const int b = blockIdx.x, tid = threadIdx.x;

    idx_s[tid]       = sel[b * KK + tid];
    idx_s[tid + 256] = sel[b * KK + tid + 256];
    __syncthreads();

    // masked mean over gathered rows (thread = channel)
    float acc = 0.f; int cnt = 0;
    for (int k = 0; k < KK; k++) {
        const int idx = idx_s[k];
        if (idx < NN) { acc += enc[((size_t)b * NN + idx) * HH + tid]; cnt++; }
    }
    const float cntf = (float)(cnt > 0 ? cnt : 1);
    mean_s[tid] = acc / cntf;
    __syncthreads();

    // ctx = mean @ Wc + bc
    float c = bc[tid];
    for (int i = 0; i < HH; i++) c += mean_s[i] * Wc[i * HH + tid];
    ctx_s[tid] = c;
    __syncthreads();

    // scores[k] = ctx . enc[idx_k]  (warp per row, strided)
    const int wid = tid >> 5, lane = tid & 31;
    for (int k = wid; k < KK; k += 8) {
        const int idx = idx_s[k];
        float s = -1e30f;
        if (idx < NN) {
            const float* row = enc + ((size_t)b * NN + idx) * HH;
            float part = 0.f;
            #pragma unroll
            for (int i = 0; i < 8; i++) part += ctx_s[lane + i * 32] * row[lane + i * 32];
            #pragma unroll
            for (int off = 16; off; off >>= 1)
                part += __shfl_xor_sync(0xffffffffu, part, off);
            s = part;
        }
        if (lane == 0) sc_s[k] = s;
    }
    __syncthreads();

    // block max
    red_s[tid] = fmaxf(sc_s[tid], sc_s[tid + 256]);
    __syncthreads();
    for (int st = 128; st; st >>= 1) {
        if (tid < st) red_s[tid] = fmaxf(red_s[tid], red_s[tid + st]);
        __syncthreads();
    }
    const float m = red_s[0];
    __syncthreads();

    // exp + sum (invalid -> 0)
    const int i0 = idx_s[tid], i1 = idx_s[tid + 256];
    const float e0 = (i0 < NN) ? expf(sc_s[tid] - m)       : 0.f;
    const float e1 = (i1 < NN) ? expf(sc_s[tid + 256] - m) : 0.f;
    red_s[tid] = e0 + e1;
    __syncthreads();
    for (int st = 128; st; st >>= 1) {
        if (tid < st) red_s[tid] += red_s[tid + st];
        __syncthreads();
    }
    const float denom = red_s[0];
    __syncthreads();

    // rounded allocation (rintf == round-half-even == jnp.round)
    float a0 = rintf(e0 / denom * 100.f);
    float a1 = rintf(e1 / denom * 100.f);
    red_s[tid] = a0 + a1;
    __syncthreads();
    for (int st = 128; st; st >>= 1) {
        if (tid < st) red_s[tid] += red_s[tid + st];
        __syncthreads();
    }
    const float diff = 100.f - red_s[0];
    __syncthreads();

    if (tid == 0 && i0 < NN) a0 += diff;   // thread 0 owns k=0

    if (i0 < NN) bw[b * NN + i0] = a0;
    if (i1 < NN) bw[b * NN + i1] = a1;
}

// ---------------------------------------------------------------------------
// Launch
// ---------------------------------------------------------------------------
extern "C" void kernel_launch(void* const* d_in, const int* in_sizes, int n_in,
                              void* d_out, int out_size)
{
    const float* x     = (const float*)d_in[0];
    const int*   sel   = (const int*)  d_in[1];
    const float* W_in  = (const float*)d_in[2];
    const float* b_in  = (const float*)d_in[3];
    const float* Wqkv  = (const float*)d_in[4];
    const float* bqkv  = (const float*)d_in[5];
    const float* Wo    = (const float*)d_in[6];
    const float* bo    = (const float*)d_in[7];
    const float* ln1g  = (const float*)d_in[8];
    const float* ln1b  = (const float*)d_in[9];
    const float* W1    = (const float*)d_in[10];
    const float* b1    = (const float*)d_in[11];
    const float* W2    = (const float*)d_in[12];
    const float* b2    = (const float*)d_in[13];
    const float* ln2g  = (const float*)d_in[14];
    const float* ln2b  = (const float*)d_in[15];
    const float* Wc    = (const float*)d_in[16];
    const float* bc    = (const float*)d_in[17];

    float *h, *tmp, *qkvb, *attnb, *ffb;
    cudaGetSymbolAddress((void**)&h,     g_h);
    cudaGetSymbolAddress((void**)&tmp,   g_tmp);
    cudaGetSymbolAddress((void**)&qkvb,  g_qkv);
    cudaGetSymbolAddress((void**)&attnb, g_attn);
    cudaGetSymbolAddress((void**)&ffb,   g_ff);

    const dim3 blk(256);

    // h = x @ W_in + b_in
    sgemm_kernel<<<dim3(HH / 128, TOK / 128), blk>>>(
        x, W_in, b_in, nullptr, h, TOK, DIN, HH, 0);

    for (int l = 0; l < LL; l++) {
        // qkv = h @ Wqkv[l] + bqkv[l]
        sgemm_kernel<<<dim3(3 * HH / 128, TOK / 128), blk>>>(
            h, Wqkv + (size_t)l * HH * 3 * HH, bqkv + (size_t)l * 3 * HH,
            nullptr, qkvb, TOK, HH, 3 * HH, 0);

        // attention
        attn_kernel<<<dim3(NN / 64, BB * NHH), blk>>>(qkvb, attnb);

        // tmp = attn @ Wo[l] + bo[l] + h ; h = LN1(tmp)
        sgemm_kernel<<<dim3(HH / 128, TOK / 128), blk>>>(
            attnb, Wo + (size_t)l * HH * HH, bo + (size_t)l * HH,
            h, tmp, TOK, HH, HH, 0);
        ln_kernel<<<TOK / 8, blk>>>(tmp, ln1g + l * HH, ln1b + l * HH, h);

        // ff = relu(h @ W1[l] + b1[l])
        sgemm_kernel<<<dim3(FF / 128, TOK / 128), blk>>>(
            h, W1 + (size_t)l * HH * FF, b1 + (size_t)l * FF,
            nullptr, ffb, TOK, HH, FF, 1);

        // tmp = ff @ W2[l] + b2[l] + h ; h = LN2(tmp)
        sgemm_kernel<<<dim3(HH / 128, TOK / 128), blk>>>(
            ffb, W2 + (size_t)l * FF * HH, b2 + (size_t)l * HH,
            h, tmp, TOK, FF, HH, 0);
        ln_kernel<<<TOK / 8, blk>>>(tmp, ln2g + l * HH, ln2b + l * HH, h);
    }

    // output assembly
    float* outf = (float*)d_out;
    const int idx_elems = BB * KK;          // 8192
    const int bw_elems  = BB * NN;          // 16384
    const int both = (out_size >= idx_elems + bw_elems) ? 1 : 0;
    float* bw = both ? (outf + idx_elems) : outf;

    init_out_kernel<<<(out_size + 255) / 256, blk>>>(sel, outf, out_size, both);
    alloc_kernel<<<BB, blk>>>(h, sel, Wc, bc, bw);
}

// round 6
// speedup vs baseline: 3.0520x; 3.0447x over previous
#include <cuda_runtime.h>
#include <cuda_bf16.h>
#include <cstdint>

#define BB 16
#define NN 1024
#define KKc 512
#define DIN 64
#define HH 256
#define FF 1024
#define LL 2
#define TOK (BB*NN)

typedef __nv_bfloat16 bf16;

#define WOFF_IN 0
#define WOFF_QKV (WOFF_IN + DIN*HH)
#define WOFF_O (WOFF_QKV + LL*HH*3*HH)
#define WOFF_1 (WOFF_O + LL*HH*HH)
#define WOFF_2 (WOFF_1 + LL*HH*FF)
#define WTOT (WOFF_2 + LL*FF*HH)

__device__ __align__(16) float g_h[TOK*HH], g_tmp[TOK*HH];
__device__ __align__(16) bf16 g_xh[TOK*DIN], g_xl[TOK*DIN];
__device__ __align__(16) bf16 g_hbh[TOK*HH], g_hbl[TOK*HH];
__device__ __align__(16) bf16 g_qh[TOK*768], g_ql[TOK*768];
__device__ __align__(16) bf16 g_ah[TOK*HH], g_al[TOK*HH];
__device__ __align__(16) bf16 g_fh[TOK*FF], g_fl[TOK*FF];
__device__ __align__(16) bf16 g_wh[WTOT], g_wl[WTOT];

// ---------------- helpers ----------------
__device__ __forceinline__ uint32_t smem_u32(const void* p) {
    uint32_t a;
    asm("{ .reg .u64 t; cvta.to.shared.u64 t, %1; cvt.u32.u64 %0, t; }" : "=r"(a) : "l"(p));
    return a;
}
__device__ __forceinline__ void cp16(uint32_t d, const void* s) {
    asm volatile("cp.async.cg.shared.global [%0], [%1], 16;" :: "r"(d), "l"(s));
}
#define CPCOMMIT() asm volatile("cp.async.commit_group;" ::: "memory")
#define CPWAIT(n)  asm volatile("cp.async.wait_group %0;" :: "n"(n) : "memory")

__device__ __forceinline__ void ldm4(uint32_t* r, uint32_t a) {
    asm volatile("ldmatrix.sync.aligned.m8n8.x4.shared.b16 {%0,%1,%2,%3}, [%4];"
                 : "=r"(r[0]), "=r"(r[1]), "=r"(r[2]), "=r"(r[3]) : "r"(a));
}
__device__ __forceinline__ void ldm4t(uint32_t* r, uint32_t a) {
    asm volatile("ldmatrix.sync.aligned.m8n8.x4.trans.shared.b16 {%0,%1,%2,%3}, [%4];"
                 : "=r"(r[0]), "=r"(r[1]), "=r"(r[2]), "=r"(r[3]) : "r"(a));
}
__device__ __forceinline__ void mma_b16(float* c, const uint32_t* a, const uint32_t* b) {
    asm volatile("mma.sync.aligned.m16n8k16.row.col.f32.bf16.bf16.f32 "
                 "{%0,%1,%2,%3},{%4,%5,%6,%7},{%8,%9},{%0,%1,%2,%3};"
                 : "+f"(c[0]), "+f"(c[1]), "+f"(c[2]), "+f"(c[3])
                 : "r"(a[0]), "r"(a[1]), "r"(a[2]), "r"(a[3]), "r"(b[0]), "r"(b[1]));
}
__device__ __forceinline__ uint32_t bf2(float lo, float hi) {
    uint32_t r;
    asm("cvt.rn.bf16x2.f32 %0, %1, %2;" : "=r"(r) : "f"(hi), "f"(lo));
    return r;
}
__device__ __forceinline__ void split_pack(float a, float b, uint32_t& hi, uint32_t& lo) {
    float ah = __bfloat162float(__float2bfloat16(a));
    float bh = __bfloat162float(__float2bfloat16(b));
    hi = bf2(ah, bh); lo = bf2(a - ah, b - bh);
}

#define RS 40      // smem row stride (bf16 elems): 80B -> conflict-free ldmatrix
#define PLB 10240  // plane bytes: 128*RS*2

// ---------------- prep: weight transpose/split + x split ----------------
struct Seg { const float* s; bf16 *dh, *dl; int K, N, mode, ntiles; };
struct Segs { Seg seg[10]; };

__global__ void prep_kernel(Segs S) {
    Seg sg = S.seg[blockIdx.y];
    if ((int)blockIdx.x >= sg.ntiles) return;
    const int tx = threadIdx.x, ty = threadIdx.y;
    if (sg.mode == 1) {
        int off = blockIdx.x * 1024 + ty * 128 + tx * 4;
        float4 v = *(const float4*)(sg.s + off);
        float a[4] = {v.x, v.y, v.z, v.w};
        #pragma unroll
        for (int i = 0; i < 4; i++) {
            bf16 h = __float2bfloat16(a[i]);
            sg.dh[off + i] = h;
            sg.dl[off + i] = __float2bfloat16(a[i] - __bfloat162float(h));
        }
    } else {
        __shared__ float tile[32][33];
        int kt = blockIdx.x % (sg.K / 32), nt = blockIdx.x / (sg.K / 32);
        int k0 = kt * 32, n0 = nt * 32;
        #pragma unroll
        for (int i = 0; i < 4; i++)
            tile[ty * 4 + i][tx] = sg.s[(size_t)(k0 + ty * 4 + i) * sg.N + n0 + tx];
        __syncthreads();
        #pragma unroll
        for (int i = 0; i < 4; i++) {
            float v = tile[tx][ty * 4 + i];
            bf16 h = __float2bfloat16(v);
            size_t d = (size_t)(n0 + ty * 4 + i) * sg.K + k0 + tx;
            sg.dh[d] = h;
            sg.dl[d] = __float2bfloat16(v - __bfloat162float(h));
        }
    }
}

// ---------------- split-bf16 HMMA GEMM ----------------
// C[M,N] = A[M,K] @ B[N,K]^T + bias (+res)(+relu). grid(N/128, M/128), 256 thr.
__global__ __launch_bounds__(256) void gemm_mma(
    const bf16* __restrict__ Ah, const bf16* __restrict__ Al,
    const bf16* __restrict__ Bh, const bf16* __restrict__ Bl,
    const float* __restrict__ bias, const float* __restrict__ res,
    float* __restrict__ Cf, bf16* __restrict__ Cbh, bf16* __restrict__ Cbl,
    int K, int N, int relu)
{
    extern __shared__ __align__(16) bf16 smr[];
    const int tid = threadIdx.x, lane = tid & 31, wid = tid >> 5;
    const int m0 = blockIdx.y << 7, n0 = blockIdx.x << 7;
    const int wm = (wid & 3) << 5, wn = (wid >> 2) << 6;
    const uint32_t sb = smem_u32(smr);

    float acc[2][8][4];
    #pragma unroll
    for (int a = 0; a < 2; a++)
        #pragma unroll
        for (int b = 0; b < 8; b++)
            #pragma unroll
            for (int c = 0; c < 4; c++) acc[a][b][c] = 0.f;

    const int nst = K >> 5;

    {
        const int k0 = 0, buf = 0;
        #pragma unroll
        for (int i = 0; i < 2; i++) {
            int ch = (tid << 1) | i; int r = ch >> 2; int cc = (ch & 3) << 3;
            uint32_t so = (uint32_t)(r * RS + cc) << 1;
            size_t ga = (size_t)(m0 + r) * K + k0 + cc;
            size_t gb = (size_t)(n0 + r) * K + k0 + cc;
            cp16(sb + (0 * 2 + buf) * PLB + so, Ah + ga);
            cp16(sb + (1 * 2 + buf) * PLB + so, Al + ga);
            cp16(sb + (2 * 2 + buf) * PLB + so, Bh + gb);
            cp16(sb + (3 * 2 + buf) * PLB + so, Bl + gb);
        }
        CPCOMMIT();
    }

    for (int s = 0; s < nst; s++) {
        if (s + 1 < nst) {
            const int k0 = (s + 1) << 5, buf = (s + 1) & 1;
            #pragma unroll
            for (int i = 0; i < 2; i++) {
                int ch = (tid << 1) | i; int r = ch >> 2; int cc = (ch & 3) << 3;
                uint32_t so = (uint32_t)(r * RS + cc) << 1;
                size_t ga = (size_t)(m0 + r) * K + k0 + cc;
                size_t gb = (size_t)(n0 + r) * K + k0 + cc;
                cp16(sb + (0 * 2 + buf) * PLB + so, Ah + ga);
                cp16(sb + (1 * 2 + buf) * PLB + so, Al + ga);
                cp16(sb + (2 * 2 + buf) * PLB + so, Bh + gb);
                cp16(sb + (3 * 2 + buf) * PLB + so, Bl + gb);
            }
            CPCOMMIT();
            CPWAIT(1);
        } else {
            CPWAIT(0);
        }
        __syncthreads();

        const int buf = s & 1;
        const uint32_t pAh = sb + (0 * 2 + buf) * PLB, pAl = sb + (1 * 2 + buf) * PLB;
        const uint32_t pBh = sb + (2 * 2 + buf) * PLB, pBl = sb + (3 * 2 + buf) * PLB;
        #pragma unroll
        for (int ks = 0; ks < 2; ks++) {
            uint32_t ah[2][4], al[2][4];
            #pragma unroll
            for (int mt = 0; mt < 2; mt++) {
                uint32_t off = (uint32_t)((wm + mt * 16 + (lane & 15)) * RS
                                          + ks * 16 + ((lane >> 4) << 3)) << 1;
                ldm4(ah[mt], pAh + off); ldm4(al[mt], pAl + off);
            }
            #pragma unroll
            for (int nt2 = 0; nt2 < 4; nt2++) {
                uint32_t bh[4], bl[4];
                uint32_t off = (uint32_t)((wn + nt2 * 16 + (lane & 7) + ((lane >> 4) << 3)) * RS
                                          + ks * 16 + ((lane >> 3) & 1) * 8) << 1;
                ldm4(bh, pBh + off); ldm4(bl, pBl + off);
                #pragma unroll
                for (int mt = 0; mt < 2; mt++)
                    #pragma unroll
                    for (int t = 0; t < 2; t++) {
                        float* c = acc[mt][nt2 * 2 + t];
                        mma_b16(c, ah[mt], bh + 2 * t);
                        mma_b16(c, ah[mt], bl + 2 * t);
                        mma_b16(c, al[mt], bh + 2 * t);
                    }
            }
        }
        __syncthreads();
    }

    // epilogue
    #pragma unroll
    for (int mt = 0; mt < 2; mt++)
        #pragma unroll
        for (int nt = 0; nt < 8; nt++) {
            int r0 = m0 + wm + mt * 16 + (lane >> 2);
            int c  = n0 + wn + nt * 8 + ((lane & 3) << 1);
            float* a = acc[mt][nt];
            float b0 = bias[c], b1 = bias[c + 1];
            float v0 = a[0] + b0, v1 = a[1] + b1, v2 = a[2] + b0, v3 = a[3] + b1;
            if (res) {
                float2 q0 = *(const float2*)(res + (size_t)r0 * N + c);
                float2 q1 = *(const float2*)(res + (size_t)(r0 + 8) * N + c);
                v0 += q0.x; v1 += q0.y; v2 += q1.x; v3 += q1.y;
            }
            if (relu) {
                v0 = fmaxf(v0, 0.f); v1 = fmaxf(v1, 0.f);
                v2 = fmaxf(v2, 0.f); v3 = fmaxf(v3, 0.f);
            }
            if (Cf) {
                *(float2*)(Cf + (size_t)r0 * N + c)       = make_float2(v0, v1);
                *(float2*)(Cf + (size_t)(r0 + 8) * N + c) = make_float2(v2, v3);
            }
            if (Cbh) {
                uint32_t h0, l0, h1, l1;
                split_pack(v0, v1, h0, l0); split_pack(v2, v3, h1, l1);
                *(uint32_t*)(Cbh + (size_t)r0 * N + c) = h0;
                *(uint32_t*)(Cbl + (size_t)r0 * N + c) = l0;
                *(uint32_t*)(Cbh + (size_t)(r0 + 8) * N + c) = h1;
                *(uint32_t*)(Cbl + (size_t)(r0 + 8) * N + c) = l1;
            }
        }
}

// ---------------- fused HMMA flash attention ----------------
// grid (NN/128, BB*8), 256 thr. Each warp: 16 q rows. No-max softmax.
__global__ __launch_bounds__(256) void attn_mma(
    const bf16* __restrict__ qh, const bf16* __restrict__ ql,
    bf16* __restrict__ oh, bf16* __restrict__ ol)
{
    extern __shared__ __align__(16) bf16 smr[];
    const int tid = threadIdx.x, lane = tid & 31, wid = tid >> 5;
    const int bhn = blockIdx.y, b = bhn >> 3, h = bhn & 7;
    const int q0 = blockIdx.x << 7;
    const size_t base = (size_t)b * NN;
    const uint32_t sb = smem_u32(smr);
    const float SC = 0.17677669529663687f;

    // issue Q + stage 0
    #pragma unroll
    for (int i = 0; i < 4; i++) {
        int ch = tid * 4 + i; int p = ch >> 9; int r = (ch >> 2) & 127; int cc = (ch & 3) << 3;
        uint32_t so = (uint32_t)(r * RS + cc) << 1;
        const bf16* src = (p ? ql : qh) + (base + q0 + r) * 768 + h * 32 + cc;
        cp16(sb + p * PLB + so, src);
    }
    #pragma unroll
    for (int i = 0; i < 8; i++) {
        int ch = tid * 8 + i; int p = ch >> 9; int r = (ch >> 2) & 127; int cc = (ch & 3) << 3;
        uint32_t so = (uint32_t)(r * RS + cc) << 1;
        int fo = (p >> 1) ? 512 : 256;
        const bf16* src = ((p & 1) ? ql : qh) + (base + r) * 768 + fo + h * 32 + cc;
        cp16(sb + 2 * PLB + p * PLB + so, src);
    }
    CPCOMMIT();

    uint32_t qfh[2][4], qfl[2][4];
    float oacc[4][4];
    #pragma unroll
    for (int a = 0; a < 4; a++)
        #pragma unroll
        for (int c = 0; c < 4; c++) oacc[a][c] = 0.f;
    float rs0 = 0.f, rs1 = 0.f;

    for (int s = 0; s < 8; s++) {
        if (s < 7) {
            const int kv0 = (s + 1) << 7, buf = (s + 1) & 1;
            #pragma unroll
            for (int i = 0; i < 8; i++) {
                int ch = tid * 8 + i; int p = ch >> 9; int r = (ch >> 2) & 127; int cc = (ch & 3) << 3;
                uint32_t so = (uint32_t)(r * RS + cc) << 1;
                int fo = (p >> 1) ? 512 : 256;
                const bf16* src = ((p & 1) ? ql : qh) + (base + kv0 + r) * 768 + fo + h * 32 + cc;
                cp16(sb + 2 * PLB + (buf * 4 + p) * PLB + so, src);
            }
            CPCOMMIT();
            CPWAIT(1);
        } else {
            CPWAIT(0);
        }
        __syncthreads();

        if (s == 0) {
            #pragma unroll
            for (int ks = 0; ks < 2; ks++) {
                uint32_t off = (uint32_t)((wid * 16 + (lane & 15)) * RS
                                          + ks * 16 + ((lane >> 4) << 3)) << 1;
                ldm4(qfh[ks], sb + off); ldm4(qfl[ks], sb + PLB + off);
            }
        }

        const int buf = s & 1;
        const uint32_t kH = sb + 2 * PLB + (buf * 4 + 0) * PLB;
        const uint32_t kL = kH + PLB, vH = kH + 2 * PLB, vL = kH + 3 * PLB;

        #pragma unroll
        for (int kk = 0; kk < 8; kk++) {
            float s0[4] = {0.f, 0.f, 0.f, 0.f}, s1[4] = {0.f, 0.f, 0.f, 0.f};
            #pragma unroll
            for (int ks = 0; ks < 2; ks++) {
                uint32_t bh[4], bl[4];
                uint32_t off = (uint32_t)((kk * 16 + (lane & 7) + ((lane >> 4) << 3)) * RS
                                          + ks * 16 + ((lane >> 3) & 1) * 8) << 1;
                ldm4(bh, kH + off); ldm4(bl, kL + off);
                mma_b16(s0, qfh[ks], bh);     mma_b16(s0, qfh[ks], bl);
                mma_b16(s0, qfl[ks], bh);
                mma_b16(s1, qfh[ks], bh + 2); mma_b16(s1, qfh[ks], bl + 2);
                mma_b16(s1, qfl[ks], bh + 2);
            }
            float e00 = __expf(s0[0] * SC), e01 = __expf(s0[1] * SC);
            float e02 = __expf(s0[2] * SC), e03 = __expf(s0[3] * SC);
            float e10 = __expf(s1[0] * SC), e11 = __expf(s1[1] * SC);
            float e12 = __expf(s1[2] * SC), e13 = __expf(s1[3] * SC);
            rs0 += e00 + e01 + e10 + e11;
            rs1 += e02 + e03 + e12 + e13;
            uint32_t pah[4], pal[4];
            split_pack(e00, e01, pah[0], pal[0]);
            split_pack(e02, e03, pah[1], pal[1]);
            split_pack(e10, e11, pah[2], pal[2]);
            split_pack(e12, e13, pah[3], pal[3]);

            uint32_t va[4], vb[4], vc[4], vd[4];
            uint32_t ro = kk * 16 + (lane & 7) + (((lane >> 3) & 1) << 3);
            uint32_t ofa = (uint32_t)(ro * RS + ((lane >> 4) << 3)) << 1;
            uint32_t ofb = (uint32_t)(ro * RS + 16 + ((lane >> 4) << 3)) << 1;
            ldm4t(va, vH + ofa); ldm4t(vb, vH + ofb);
            ldm4t(vc, vL + ofa); ldm4t(vd, vL + ofb);
            mma_b16(oacc[0], pah, va);     mma_b16(oacc[0], pah, vc);     mma_b16(oacc[0], pal, va);
            mma_b16(oacc[1], pah, va + 2); mma_b16(oacc[1], pah, vc + 2); mma_b16(oacc[1], pal, va + 2);
            mma_b16(oacc[2], pah, vb);     mma_b16(oacc[2], pah, vd);     mma_b16(oacc[2], pal, vb);
            mma_b16(oacc[3], pah, vb + 2); mma_b16(oacc[3], pah, vd + 2); mma_b16(oacc[3], pal, vb + 2);
        }
        __syncthreads();
    }

    rs0 += __shfl_xor_sync(0xffffffffu, rs0, 1);
    rs0 += __shfl_xor_sync(0xffffffffu, rs0, 2);
    rs1 += __shfl_xor_sync(0xffffffffu, rs1, 1);
    rs1 += __shfl_xor_sync(0xffffffffu, rs1, 2);
    const float i0 = 1.f / rs0, i1 = 1.f / rs1;

    #pragma unroll
    for (int nt = 0; nt < 4; nt++) {
        int r0 = q0 + wid * 16 + (lane >> 2);
        int c  = h * 32 + nt * 8 + ((lane & 3) << 1);
        float v0 = oacc[nt][0] * i0, v1 = oacc[nt][1] * i0;
        float v2 = oacc[nt][2] * i1, v3 = oacc[nt][3] * i1;
        uint32_t h0, l0, h1, l1;
        split_pack(v0, v1, h0, l0); split_pack(v2, v3, h1, l1);
        *(uint32_t*)(oh + (base + r0) * HH + c) = h0;
        *(uint32_t*)(ol + (base + r0) * HH + c) = l0;
        *(uint32_t*)(oh + (base + r0 + 8) * HH + c) = h1;
        *(uint32_t*)(ol + (base + r0 + 8) * HH + c) = l1;
    }
}

// ---------------- LayerNorm: fp32 in -> fp32 + bf16 hi/lo ----------------
__global__ __launch_bounds__(256) void ln_kernel(
    const float* __restrict__ x, const float* __restrict__ gam,
    const float* __restrict__ bet, float* __restrict__ out,
    bf16* __restrict__ ohp, bf16* __restrict__ olp)
{
    const int row = blockIdx.x * 8 + (threadIdx.x >> 5);
    const int lane = threadIdx.x & 31;
    const float* xr = x + (size_t)row * HH;
    float v[8], sum = 0.f;
    #pragma unroll
    for (int i = 0; i < 8; i++) { v[i] = xr[lane + i * 32]; sum += v[i]; }
    #pragma unroll
    for (int o = 16; o; o >>= 1) sum += __shfl_xor_sync(0xffffffffu, sum, o);
    const float mean = sum * (1.f / HH);
    float var = 0.f;
    #pragma unroll
    for (int i = 0; i < 8; i++) { float d = v[i] - mean; var += d * d; }
    #pragma unroll
    for (int o = 16; o; o >>= 1) var += __shfl_xor_sync(0xffffffffu, var, o);
    const float inv = rsqrtf(var * (1.f / HH) + 1e-5f);
    #pragma unroll
    for (int i = 0; i < 8; i++) {
        const int c = lane + i * 32;
        float val = (v[i] - mean) * inv * gam[c] + bet[c];
        out[(size_t)row * HH + c] = val;
        bf16 hb = __float2bfloat16(val);
        ohp[(size_t)row * HH + c] = hb;
        olp[(size_t)row * HH + c] = __float2bfloat16(val - __bfloat162float(hb));
    }
}

// ---------------- output init + allocation ----------------
__global__ void init_out_kernel(const int* __restrict__ sel, float* __restrict__ out,
                                int out_size, int both)
{
    const int i = blockIdx.x * 256 + threadIdx.x;
    if (i >= out_size) return;
    if (both && i < BB * KKc) out[i] = (float)sel[i];
    else out[i] = 0.f;
}

__global__ __launch_bounds__(256) void alloc_kernel(
    const float* __restrict__ enc, const int* __restrict__ sel,
    const float* __restrict__ Wc, const float* __restrict__ bc,
    float* __restrict__ bw)
{
    __shared__ float mean_s[HH], ctx_s[HH], sc_s[KKc], red_s[256];
    __shared__ int idx_s[KKc];
    const int b = blockIdx.x, tid = threadIdx.x;
    idx_s[tid] = sel[b * KKc + tid];
    idx_s[tid + 256] = sel[b * KKc + tid + 256];
    __syncthreads();

    float acc = 0.f; int cnt = 0;
    for (int k = 0; k < KKc; k++) {
        const int idx = idx_s[k];
        if (idx < NN) { acc += enc[((size_t)b * NN + idx) * HH + tid]; cnt++; }
    }
    mean_s[tid] = acc / (float)(cnt > 0 ? cnt : 1);
    __syncthreads();

    float c = bc[tid];
    for (int i = 0; i < HH; i++) c += mean_s[i] * Wc[i * HH + tid];
    ctx_s[tid] = c;
    __syncthreads();

    const int wid = tid >> 5, lane = tid & 31;
    for (int k = wid; k < KKc; k += 8) {
        const int idx = idx_s[k];
        float s = -1e30f;
        if (idx < NN) {
            const float* row = enc + ((size_t)b * NN + idx) * HH;
            float part = 0.f;
            #pragma unroll
            for (int i = 0; i < 8; i++) part += ctx_s[lane + i * 32] * row[lane + i * 32];
            #pragma unroll
            for (int o = 16; o; o >>= 1) part += __shfl_xor_sync(0xffffffffu, part, o);
            s = part;
        }
        if (lane == 0) sc_s[k] = s;
    }
    __syncthreads();

    red_s[tid] = fmaxf(sc_s[tid], sc_s[tid + 256]);
    __syncthreads();
    for (int st = 128; st; st >>= 1) {
        if (tid < st) red_s[tid] = fmaxf(red_s[tid], red_s[tid + st]);
        __syncthreads();
    }
    const float m = red_s[0];
    __syncthreads();

    const int i0 = idx_s[tid], i1 = idx_s[tid + 256];
    const float e0 = (i0 < NN) ? expf(sc_s[tid] - m) : 0.f;
    const float e1 = (i1 < NN) ? expf(sc_s[tid + 256] - m) : 0.f;
    red_s[tid] = e0 + e1;
    __syncthreads();
    for (int st = 128; st; st >>= 1) {
        if (tid < st) red_s[tid] += red_s[tid + st];
        __syncthreads();
    }
    const float denom = red_s[0];
    __syncthreads();

    float a0 = rintf(e0 / denom * 100.f);
    float a1 = rintf(e1 / denom * 100.f);
    red_s[tid] = a0 + a1;
    __syncthreads();
    for (int st = 128; st; st >>= 1) {
        if (tid < st) red_s[tid] += red_s[tid + st];
        __syncthreads();
    }
    const float diff = 100.f - red_s[0];
    __syncthreads();

    if (tid == 0 && i0 < NN) a0 += diff;
    if (i0 < NN) bw[b * NN + i0] = a0;
    if (i1 < NN) bw[b * NN + i1] = a1;
}

// ---------------- launch ----------------
extern "C" void kernel_launch(void* const* d_in, const int* in_sizes, int n_in,
                              void* d_out, int out_size)
{
    const float* x    = (const float*)d_in[0];
    const int*   sel  = (const int*)  d_in[1];
    const float* W_in = (const float*)d_in[2];
    const float* b_in = (const float*)d_in[3];
    const float* Wqkv = (const float*)d_in[4];
    const float* bqkv = (const float*)d_in[5];
    const float* Wo   = (const float*)d_in[6];
    const float* bo   = (const float*)d_in[7];
    const float* ln1g = (const float*)d_in[8];
    const float* ln1b = (const float*)d_in[9];
    const float* W1   = (const float*)d_in[10];
    const float* b1   = (const float*)d_in[11];
    const float* W2   = (const float*)d_in[12];
    const float* b2   = (const float*)d_in[13];
    const float* ln2g = (const float*)d_in[14];
    const float* ln2b = (const float*)d_in[15];
    const float* Wc   = (const float*)d_in[16];
    const float* bc   = (const float*)d_in[17];

    float *h, *tmp;
    bf16 *xh, *xl, *hbh, *hbl, *qh, *ql, *ah, *al, *fh, *fl, *wh, *wl;
    cudaGetSymbolAddress((void**)&h,   g_h);   cudaGetSymbolAddress((void**)&tmp, g_tmp);
    cudaGetSymbolAddress((void**)&xh,  g_xh);  cudaGetSymbolAddress((void**)&xl,  g_xl);
    cudaGetSymbolAddress((void**)&hbh, g_hbh); cudaGetSymbolAddress((void**)&hbl, g_hbl);
    cudaGetSymbolAddress((void**)&qh,  g_qh);  cudaGetSymbolAddress((void**)&ql,  g_ql);
    cudaGetSymbolAddress((void**)&ah,  g_ah);  cudaGetSymbolAddress((void**)&al,  g_al);
    cudaGetSymbolAddress((void**)&fh,  g_fh);  cudaGetSymbolAddress((void**)&fl,  g_fl);
    cudaGetSymbolAddress((void**)&wh,  g_wh);  cudaGetSymbolAddress((void**)&wl,  g_wl);

    const int GSM = 8 * PLB;            // 81920
    const int ASM_ = 10 * PLB;          // 102400
    cudaFuncSetAttribute(gemm_mma, cudaFuncAttributeMaxDynamicSharedMemorySize, GSM);
    cudaFuncSetAttribute(attn_mma, cudaFuncAttributeMaxDynamicSharedMemorySize, ASM_);

    Segs S;
    S.seg[0] = { x, xh, xl, 0, 0, 1, (TOK * DIN) / 1024 };
    S.seg[1] = { W_in, wh + WOFF_IN, wl + WOFF_IN, DIN, HH, 0, (DIN/32)*(HH/32) };
    for (int l = 0; l < LL; l++) {
        S.seg[2+l] = { Wqkv + (size_t)l*HH*3*HH, wh + WOFF_QKV + l*HH*3*HH,
                       wl + WOFF_QKV + l*HH*3*HH, HH, 3*HH, 0, (HH/32)*(3*HH/32) };
        S.seg[4+l] = { Wo + (size_t)l*HH*HH, wh + WOFF_O + l*HH*HH,
                       wl + WOFF_O + l*HH*HH, HH, HH, 0, (HH/32)*(HH/32) };
        S.seg[6+l] = { W1 + (size_t)l*HH*FF, wh + WOFF_1 + l*HH*FF,
                       wl + WOFF_1 + l*HH*FF, HH, FF, 0, (HH/32)*(FF/32) };
        S.seg[8+l] = { W2 + (size_t)l*FF*HH, wh + WOFF_2 + l*FF*HH,
                       wl + WOFF_2 + l*FF*HH, FF, HH, 0, (FF/32)*(HH/32) };
    }
    prep_kernel<<<dim3(1024, 10), dim3(32, 8)>>>(S);

    gemm_mma<<<dim3(HH/128, TOK/128), 256, GSM>>>(
        xh, xl, wh + WOFF_IN, wl + WOFF_IN, b_in, nullptr, h, hbh, hbl, DIN, HH, 0);

    for (int l = 0; l < LL; l++) {
        gemm_mma<<<dim3(3*HH/128, TOK/128), 256, GSM>>>(
            hbh, hbl, wh + WOFF_QKV + l*HH*3*HH, wl + WOFF_QKV + l*HH*3*HH,
            bqkv + l*3*HH, nullptr, nullptr, qh, ql, HH, 3*HH, 0);
        attn_mma<<<dim3(NN/128, BB*8), 256, ASM_>>>(qh, ql, ah, al);
        gemm_mma<<<dim3(HH/128, TOK/128), 256, GSM>>>(
            ah, al, wh + WOFF_O + l*HH*HH, wl + WOFF_O + l*HH*HH,
            bo + l*HH, h, tmp, nullptr, nullptr, HH, HH, 0);
        ln_kernel<<<TOK/8, 256>>>(tmp, ln1g + l*HH, ln1b + l*HH, h, hbh, hbl);
        gemm_mma<<<dim3(FF/128, TOK/128), 256, GSM>>>(
            hbh, hbl, wh + WOFF_1 + l*HH*FF, wl + WOFF_1 + l*HH*FF,
            b1 + l*FF, nullptr, nullptr, fh, fl, HH, FF, 1);
        gemm_mma<<<dim3(HH/128, TOK/128), 256, GSM>>>(
            fh, fl, wh + WOFF_2 + l*FF*HH, wl + WOFF_2 + l*FF*HH,
            b2 + l*HH, h, tmp, nullptr, nullptr, FF, HH, 0);
        ln_kernel<<<TOK/8, 256>>>(tmp, ln2g + l*HH, ln2b + l*HH, h, hbh, hbl);
    }

    float* outf = (float*)d_out;
    const int idx_elems = BB * KKc, bw_elems = BB * NN;
    const int both = (out_size >= idx_elems + bw_elems) ? 1 : 0;
    float* bw = both ? (outf + idx_elems) : outf;
    init_out_kernel<<<(out_size + 255) / 256, 256>>>(sel, outf, out_size, both);
    alloc_kernel<<<BB, 256>>>(h, sel, Wc, bc, bw);
}

// round 7
// speedup vs baseline: 3.1002x; 1.0158x over previous
#include <cuda_runtime.h>
#include <cuda_bf16.h>
#include <cstdint>

#define BB 16
#define NN 1024
#define KKc 512
#define DIN 64
#define HH 256
#define FF 1024
#define LL 2
#define TOK (BB*NN)

typedef __nv_bfloat16 bf16;

#define WOFF_IN 0
#define WOFF_QKV (WOFF_IN + DIN*HH)
#define WOFF_O (WOFF_QKV + LL*HH*3*HH)
#define WOFF_1 (WOFF_O + LL*HH*HH)
#define WOFF_2 (WOFF_1 + LL*HH*FF)
#define WTOT (WOFF_2 + LL*FF*HH)

__device__ __align__(16) float g_h[TOK*HH], g_tmp[TOK*HH];
__device__ __align__(16) bf16 g_xh[TOK*DIN], g_xl[TOK*DIN];
__device__ __align__(16) bf16 g_hbh[TOK*HH], g_hbl[TOK*HH];
__device__ __align__(16) bf16 g_qh[TOK*768], g_ql[TOK*768];
__device__ __align__(16) bf16 g_ah[TOK*HH], g_al[TOK*HH];
__device__ __align__(16) bf16 g_fh[TOK*FF], g_fl[TOK*FF];
__device__ __align__(16) bf16 g_wh[WTOT], g_wl[WTOT];

// ---------------- helpers ----------------
__device__ __forceinline__ uint32_t smem_u32(const void* p) {
    uint32_t a;
    asm("{ .reg .u64 t; cvta.to.shared.u64 t, %1; cvt.u32.u64 %0, t; }" : "=r"(a) : "l"(p));
    return a;
}
__device__ __forceinline__ void cp16(uint32_t d, const void* s) {
    asm volatile("cp.async.cg.shared.global [%0], [%1], 16;" :: "r"(d), "l"(s));
}
#define CPCOMMIT() asm volatile("cp.async.commit_group;" ::: "memory")
#define CPWAIT(n)  asm volatile("cp.async.wait_group %0;" :: "n"(n) : "memory")

__device__ __forceinline__ void ldm4(uint32_t* r, uint32_t a) {
    asm volatile("ldmatrix.sync.aligned.m8n8.x4.shared.b16 {%0,%1,%2,%3}, [%4];"
                 : "=r"(r[0]), "=r"(r[1]), "=r"(r[2]), "=r"(r[3]) : "r"(a));
}
__device__ __forceinline__ void ldm4t(uint32_t* r, uint32_t a) {
    asm volatile("ldmatrix.sync.aligned.m8n8.x4.trans.shared.b16 {%0,%1,%2,%3}, [%4];"
                 : "=r"(r[0]), "=r"(r[1]), "=r"(r[2]), "=r"(r[3]) : "r"(a));
}
__device__ __forceinline__ void mma_b16(float* c, const uint32_t* a, const uint32_t* b) {
    asm volatile("mma.sync.aligned.m16n8k16.row.col.f32.bf16.bf16.f32 "
                 "{%0,%1,%2,%3},{%4,%5,%6,%7},{%8,%9},{%0,%1,%2,%3};"
                 : "+f"(c[0]), "+f"(c[1]), "+f"(c[2]), "+f"(c[3])
                 : "r"(a[0]), "r"(a[1]), "r"(a[2]), "r"(a[3]), "r"(b[0]), "r"(b[1]));
}
__device__ __forceinline__ uint32_t bf2(float lo, float hi) {
    uint32_t r;
    asm("cvt.rn.bf16x2.f32 %0, %1, %2;" : "=r"(r) : "f"(hi), "f"(lo));
    return r;
}
__device__ __forceinline__ void split_pack(float a, float b, uint32_t& hi, uint32_t& lo) {
    float ah = __bfloat162float(__float2bfloat16(a));
    float bh = __bfloat162float(__float2bfloat16(b));
    hi = bf2(ah, bh); lo = bf2(a - ah, b - bh);
}

#define RS 40        // smem row stride (bf16): 80B, conflict-free ldmatrix
#define PLA 20480    // 256-row plane bytes
#define PLB 10240    // 128-row plane bytes
#define PLV 5120     // 64-row plane bytes

// ---------------- prep: weight transpose/split + x split ----------------
struct Seg { const float* s; bf16 *dh, *dl; int K, N, mode, ntiles; };
struct Segs { Seg seg[10]; };

__global__ void prep_kernel(Segs S) {
    Seg sg = S.seg[blockIdx.y];
    if ((int)blockIdx.x >= sg.ntiles) return;
    const int tx = threadIdx.x, ty = threadIdx.y;
    if (sg.mode == 1) {
        int off = blockIdx.x * 1024 + ty * 128 + tx * 4;
        float4 v = *(const float4*)(sg.s + off);
        float a[4] = {v.x, v.y, v.z, v.w};
        #pragma unroll
        for (int i = 0; i < 4; i++) {
            bf16 h = __float2bfloat16(a[i]);
            sg.dh[off + i] = h;
            sg.dl[off + i] = __float2bfloat16(a[i] - __bfloat162float(h));
        }
    } else {
        __shared__ float tile[32][33];
        int kt = blockIdx.x % (sg.K / 32), nt = blockIdx.x / (sg.K / 32);
        int k0 = kt * 32, n0 = nt * 32;
        #pragma unroll
        for (int i = 0; i < 4; i++)
            tile[ty * 4 + i][tx] = sg.s[(size_t)(k0 + ty * 4 + i) * sg.N + n0 + tx];
        __syncthreads();
        #pragma unroll
        for (int i = 0; i < 4; i++) {
            float v = tile[tx][ty * 4 + i];
            bf16 h = __float2bfloat16(v);
            size_t d = (size_t)(n0 + ty * 4 + i) * sg.K + k0 + tx;
            sg.dh[d] = h;
            sg.dl[d] = __float2bfloat16(v - __bfloat162float(h));
        }
    }
}

// ---------------- split-bf16 HMMA GEMM, 256x128 block, 64x64 warp ----------
// C[M,N] = A[M,K] @ B[N,K]^T + bias (+res)(+relu). grid(N/128, M/256), 256 thr.
// smem: Ah 2st@0, Al@2*PLA, Bh@4*PLA, Bl@4*PLA+2*PLB  (total 122880)
__global__ __launch_bounds__(256) void gemm_mma(
    const bf16* __restrict__ Ah, const bf16* __restrict__ Al,
    const bf16* __restrict__ Bh, const bf16* __restrict__ Bl,
    const float* __restrict__ bias, const float* __restrict__ res,
    float* __restrict__ Cf, bf16* __restrict__ Cbh, bf16* __restrict__ Cbl,
    int K, int N, int relu)
{
    extern __shared__ __align__(16) bf16 smr[];
    const int tid = threadIdx.x, lane = tid & 31, wid = tid >> 5;
    const int m0 = blockIdx.y << 8, n0 = blockIdx.x << 7;
    const int wm = (wid & 3) << 6, wn = (wid >> 2) << 6;
    const uint32_t sb = smem_u32(smr);
    const uint32_t sbA = sb, sbAl = sb + 2 * PLA;
    const uint32_t sbB = sb + 4 * PLA, sbBl = sb + 4 * PLA + 2 * PLB;

    float acc[4][8][4];
    #pragma unroll
    for (int a = 0; a < 4; a++)
        #pragma unroll
        for (int b = 0; b < 8; b++)
            #pragma unroll
            for (int c = 0; c < 4; c++) acc[a][b][c] = 0.f;

    const int nst = K >> 5;

    #pragma unroll 1
    for (int sp = 0; sp <= nst; sp++) {
        if (sp < nst) {           // issue stage sp
            const int k0 = sp << 5, buf = sp & 1;
            #pragma unroll
            for (int i = 0; i < 8; i++) {   // A: 2048 chunks
                int idx = tid + (i << 8);
                int pl = idx >> 10, rest = idx & 1023;
                int r = rest >> 2, c8 = (rest & 3) << 3;
                uint32_t so = (uint32_t)(r * RS + c8) << 1;
                const bf16* src = (pl ? Al : Ah) + (size_t)(m0 + r) * K + k0 + c8;
                cp16((pl ? sbAl : sbA) + buf * PLA + so, src);
            }
            #pragma unroll
            for (int i = 0; i < 4; i++) {   // B: 1024 chunks
                int idx = tid + (i << 8);
                int pl = idx >> 9, rest = idx & 511;
                int r = rest >> 2, c8 = (rest & 3) << 3;
                uint32_t so = (uint32_t)(r * RS + c8) << 1;
                const bf16* src = (pl ? Bl : Bh) + (size_t)(n0 + r) * K + k0 + c8;
                cp16((pl ? sbBl : sbB) + buf * PLB + so, src);
            }
            CPCOMMIT();
        }
        if (sp == 0) continue;
        const int s = sp - 1;     // compute stage s
        if (sp < nst) { CPWAIT(1); } else { CPWAIT(0); }
        __syncthreads();

        const int buf = s & 1;
        const uint32_t pAh = sbA + buf * PLA, pAl = sbAl + buf * PLA;
        const uint32_t pBh = sbB + buf * PLB, pBl = sbBl + buf * PLB;
        #pragma unroll
        for (int ks = 0; ks < 2; ks++) {
            uint32_t ah[4][4], al[4][4];
            #pragma unroll
            for (int mt = 0; mt < 4; mt++) {
                uint32_t off = (uint32_t)((wm + mt * 16 + (lane & 15)) * RS
                                          + ks * 16 + ((lane >> 4) << 3)) << 1;
                ldm4(ah[mt], pAh + off); ldm4(al[mt], pAl + off);
            }
            #pragma unroll
            for (int nt = 0; nt < 4; nt++) {
                uint32_t bh[4], bl[4];
                uint32_t off = (uint32_t)((wn + nt * 16 + (lane & 7) + ((lane >> 4) << 3)) * RS
                                          + ks * 16 + ((lane >> 3) & 1) * 8) << 1;
                ldm4(bh, pBh + off); ldm4(bl, pBl + off);
                #pragma unroll
                for (int mt = 0; mt < 4; mt++)
                    #pragma unroll
                    for (int t = 0; t < 2; t++) {
                        float* c = acc[mt][nt * 2 + t];
                        mma_b16(c, ah[mt], bh + 2 * t);
                        mma_b16(c, ah[mt], bl + 2 * t);
                        mma_b16(c, al[mt], bh + 2 * t);
                    }
            }
        }
        __syncthreads();
    }

    // epilogue
    #pragma unroll
    for (int mt = 0; mt < 4; mt++)
        #pragma unroll
        for (int nt = 0; nt < 8; nt++) {
            int r0 = m0 + wm + mt * 16 + (lane >> 2);
            int c  = n0 + wn + nt * 8 + ((lane & 3) << 1);
            float* a = acc[mt][nt];
            float b0 = bias[c], b1 = bias[c + 1];
            float v0 = a[0] + b0, v1 = a[1] + b1, v2 = a[2] + b0, v3 = a[3] + b1;
            if (res) {
                float2 q0 = *(const float2*)(res + (size_t)r0 * N + c);
                float2 q1 = *(const float2*)(res + (size_t)(r0 + 8) * N + c);
                v0 += q0.x; v1 += q0.y; v2 += q1.x; v3 += q1.y;
            }
            if (relu) {
                v0 = fmaxf(v0, 0.f); v1 = fmaxf(v1, 0.f);
                v2 = fmaxf(v2, 0.f); v3 = fmaxf(v3, 0.f);
            }
            if (Cf) {
                *(float2*)(Cf + (size_t)r0 * N + c)       = make_float2(v0, v1);
                *(float2*)(Cf + (size_t)(r0 + 8) * N + c) = make_float2(v2, v3);
            }
            if (Cbh) {
                uint32_t h0, l0, h1, l1;
                split_pack(v0, v1, h0, l0); split_pack(v2, v3, h1, l1);
                *(uint32_t*)(Cbh + (size_t)r0 * N + c) = h0;
                *(uint32_t*)(Cbl + (size_t)r0 * N + c) = l0;
                *(uint32_t*)(Cbh + (size_t)(r0 + 8) * N + c) = h1;
                *(uint32_t*)(Cbl + (size_t)(r0 + 8) * N + c) = l1;
            }
        }
}

// ---------------- fused HMMA flash attention, 256-q block, 32-q warp --------
// grid (NN/256, BB*8), 256 thr. 64-k tiles per stage (16 stages). No-max softmax.
// smem: Qh@0, Ql@PLA; stages @2*PLA + (buf*4+p)*PLV, p={Kh,Kl,Vh,Vl} (81920 B)
__global__ __launch_bounds__(256) void attn_mma(
    const bf16* __restrict__ qh, const bf16* __restrict__ ql,
    bf16* __restrict__ oh, bf16* __restrict__ ol)
{
    extern __shared__ __align__(16) bf16 smr[];
    const int tid = threadIdx.x, lane = tid & 31, wid = tid >> 5;
    const int bhn = blockIdx.y, b = bhn >> 3, h = bhn & 7;
    const int q0 = blockIdx.x << 8;
    const size_t base = (size_t)b * NN;
    const uint32_t sb = smem_u32(smr);
    const uint32_t sbKV = sb + 2 * PLA;
    const float SC = 0.17677669529663687f;

    // issue Q + stage 0
    #pragma unroll
    for (int i = 0; i < 8; i++) {          // Q: 2048 chunks
        int idx = tid + (i << 8);
        int pl = idx >> 10, rest = idx & 1023;
        int r = rest >> 2, c8 = (rest & 3) << 3;
        uint32_t so = (uint32_t)(r * RS + c8) << 1;
        const bf16* src = (pl ? ql : qh) + (base + q0 + r) * 768 + h * 32 + c8;
        cp16(sb + pl * PLA + so, src);
    }
    #pragma unroll
    for (int i = 0; i < 4; i++) {          // KV stage 0: 1024 chunks
        int idx = tid + (i << 8);
        int pl = idx >> 8, rest = idx & 255;
        int r = rest >> 2, c8 = (rest & 3) << 3;
        uint32_t so = (uint32_t)(r * RS + c8) << 1;
        int fo = (pl >> 1) ? 512 : 256;
        const bf16* src = ((pl & 1) ? ql : qh) + (base + r) * 768 + fo + h * 32 + c8;
        cp16(sbKV + pl * PLV + so, src);
    }
    CPCOMMIT();

    uint32_t qfh[2][2][4], qfl[2][2][4];
    float oacc[2][4][4];
    #pragma unroll
    for (int m = 0; m < 2; m++)
        #pragma unroll
        for (int a = 0; a < 4; a++)
            #pragma unroll
            for (int c = 0; c < 4; c++) oacc[m][a][c] = 0.f;
    float rs[2][2] = {{0.f, 0.f}, {0.f, 0.f}};

    for (int s = 0; s < 16; s++) {
        if (s < 15) {
            const int kv0 = (s + 1) << 6, buf = (s + 1) & 1;
            #pragma unroll
            for (int i = 0; i < 4; i++) {
                int idx = tid + (i << 8);
                int pl = idx >> 8, rest = idx & 255;
                int r = rest >> 2, c8 = (rest & 3) << 3;
                uint32_t so = (uint32_t)(r * RS + c8) << 1;
                int fo = (pl >> 1) ? 512 : 256;
                const bf16* src = ((pl & 1) ? ql : qh) + (base + kv0 + r) * 768 + fo + h * 32 + c8;
                cp16(sbKV + (buf * 4 + pl) * PLV + so, src);
            }
            CPCOMMIT();
            CPWAIT(1);
        } else {
            CPWAIT(0);
        }
        __syncthreads();

        if (s == 0) {
            #pragma unroll
            for (int mt = 0; mt < 2; mt++)
                #pragma unroll
                for (int ks = 0; ks < 2; ks++) {
                    uint32_t off = (uint32_t)((wid * 32 + mt * 16 + (lane & 15)) * RS
                                              + ks * 16 + ((lane >> 4) << 3)) << 1;
                    ldm4(qfh[mt][ks], sb + off);
                    ldm4(qfl[mt][ks], sb + PLA + off);
                }
        }

        const int buf = s & 1;
        const uint32_t kH = sbKV + (buf * 4 + 0) * PLV;
        const uint32_t kL = kH + PLV, vH = kH + 2 * PLV, vL = kH + 3 * PLV;

        #pragma unroll
        for (int kk = 0; kk < 4; kk++) {
            float sv[2][2][4];
            #pragma unroll
            for (int m = 0; m < 2; m++)
                #pragma unroll
                for (int t = 0; t < 2; t++)
                    #pragma unroll
                    for (int c = 0; c < 4; c++) sv[m][t][c] = 0.f;
            #pragma unroll
            for (int ks = 0; ks < 2; ks++) {
                uint32_t bh[4], bl[4];
                uint32_t off = (uint32_t)((kk * 16 + (lane & 7) + ((lane >> 4) << 3)) * RS
                                          + ks * 16 + ((lane >> 3) & 1) * 8) << 1;
                ldm4(bh, kH + off); ldm4(bl, kL + off);
                #pragma unroll
                for (int mt = 0; mt < 2; mt++)
                    #pragma unroll
                    for (int t = 0; t < 2; t++) {
                        float* c = sv[mt][t];
                        mma_b16(c, qfh[mt][ks], bh + 2 * t);
                        mma_b16(c, qfh[mt][ks], bl + 2 * t);
                        mma_b16(c, qfl[mt][ks], bh + 2 * t);
                    }
            }
            // exp + split P + V frags + PV
            uint32_t va[4], vb[4], vc[4], vd[4];
            {
                uint32_t ro = kk * 16 + (lane & 7) + (((lane >> 3) & 1) << 3);
                uint32_t ofa = (uint32_t)(ro * RS + ((lane >> 4) << 3)) << 1;
                uint32_t ofb = (uint32_t)(ro * RS + 16 + ((lane >> 4) << 3)) << 1;
                ldm4t(va, vH + ofa); ldm4t(vb, vH + ofb);
                ldm4t(vc, vL + ofa); ldm4t(vd, vL + ofb);
            }
            #pragma unroll
            for (int mt = 0; mt < 2; mt++) {
                float e00 = __expf(sv[mt][0][0] * SC), e01 = __expf(sv[mt][0][1] * SC);
                float e02 = __expf(sv[mt][0][2] * SC), e03 = __expf(sv[mt][0][3] * SC);
                float e10 = __expf(sv[mt][1][0] * SC), e11 = __expf(sv[mt][1][1] * SC);
                float e12 = __expf(sv[mt][1][2] * SC), e13 = __expf(sv[mt][1][3] * SC);
                rs[mt][0] += e00 + e01 + e10 + e11;
                rs[mt][1] += e02 + e03 + e12 + e13;
                uint32_t pah[4], pal[4];
                split_pack(e00, e01, pah[0], pal[0]);
                split_pack(e02, e03, pah[1], pal[1]);
                split_pack(e10, e11, pah[2], pal[2]);
                split_pack(e12, e13, pah[3], pal[3]);
                float* o = (float*)oacc[mt];
                mma_b16(o + 0,  pah, va);     mma_b16(o + 0,  pah, vc);     mma_b16(o + 0,  pal, va);
                mma_b16(o + 4,  pah, va + 2); mma_b16(o + 4,  pah, vc + 2); mma_b16(o + 4,  pal, va + 2);
                mma_b16(o + 8,  pah, vb);     mma_b16(o + 8,  pah, vd);     mma_b16(o + 8,  pal, vb);
                mma_b16(o + 12, pah, vb + 2); mma_b16(o + 12, pah, vd + 2); mma_b16(o + 12, pal, vb + 2);
            }
        }
        __syncthreads();
    }

    #pragma unroll
    for (int mt = 0; mt < 2; mt++) {
        float r0 = rs[mt][0], r1 = rs[mt][1];
        r0 += __shfl_xor_sync(0xffffffffu, r0, 1);
        r0 += __shfl_xor_sync(0xffffffffu, r0, 2);
        r1 += __shfl_xor_sync(0xffffffffu, r1, 1);
        r1 += __shfl_xor_sync(0xffffffffu, r1, 2);
        const float i0 = 1.f / r0, i1 = 1.f / r1;
        #pragma unroll
        for (int nt = 0; nt < 4; nt++) {
            int row = q0 + wid * 32 + mt * 16 + (lane >> 2);
            int c   = h * 32 + nt * 8 + ((lane & 3) << 1);
            float v0 = oacc[mt][nt][0] * i0, v1 = oacc[mt][nt][1] * i0;
            float v2 = oacc[mt][nt][2] * i1, v3 = oacc[mt][nt][3] * i1;
            uint32_t h0, l0, h1, l1;
            split_pack(v0, v1, h0, l0); split_pack(v2, v3, h1, l1);
            *(uint32_t*)(oh + (base + row) * HH + c) = h0;
            *(uint32_t*)(ol + (base + row) * HH + c) = l0;
            *(uint32_t*)(oh + (base + row + 8) * HH + c) = h1;
            *(uint32_t*)(ol + (base + row + 8) * HH + c) = l1;
        }
    }
}

// ---------------- LayerNorm: fp32 in -> fp32 + bf16 hi/lo ----------------
__global__ __launch_bounds__(256) void ln_kernel(
    const float* __restrict__ x, const float* __restrict__ gam,
    const float* __restrict__ bet, float* __restrict__ out,
    bf16* __restrict__ ohp, bf16* __restrict__ olp)
{
    const int row = blockIdx.x * 8 + (threadIdx.x >> 5);
    const int lane = threadIdx.x & 31;
    const float* xr = x + (size_t)row * HH;
    float v[8], sum = 0.f;
    #pragma unroll
    for (int i = 0; i < 8; i++) { v[i] = xr[lane + i * 32]; sum += v[i]; }
    #pragma unroll
    for (int o = 16; o; o >>= 1) sum += __shfl_xor_sync(0xffffffffu, sum, o);
    const float mean = sum * (1.f / HH);
    float var = 0.f;
    #pragma unroll
    for (int i = 0; i < 8; i++) { float d = v[i] - mean; var += d * d; }
    #pragma unroll
    for (int o = 16; o; o >>= 1) var += __shfl_xor_sync(0xffffffffu, var, o);
    const float inv = rsqrtf(var * (1.f / HH) + 1e-5f);
    #pragma unroll
    for (int i = 0; i < 8; i++) {
        const int c = lane + i * 32;
        float val = (v[i] - mean) * inv * gam[c] + bet[c];
        out[(size_t)row * HH + c] = val;
        bf16 hb = __float2bfloat16(val);
        ohp[(size_t)row * HH + c] = hb;
        olp[(size_t)row * HH + c] = __float2bfloat16(val - __bfloat162float(hb));
    }
}

// ---------------- output init + allocation ----------------
__global__ void init_out_kernel(const int* __restrict__ sel, float* __restrict__ out,
                                int out_size, int both)
{
    const int i = blockIdx.x * 256 + threadIdx.x;
    if (i >= out_size) return;
    if (both && i < BB * KKc) out[i] = (float)sel[i];
    else out[i] = 0.f;
}

__global__ __launch_bounds__(256) void alloc_kernel(
    const float* __restrict__ enc, const int* __restrict__ sel,
    const float* __restrict__ Wc, const float* __restrict__ bc,
    float* __restrict__ bw)
{
    __shared__ float mean_s[HH], ctx_s[HH], sc_s[KKc], red_s[256];
    __shared__ int idx_s[KKc];
    const int b = blockIdx.x, tid = threadIdx.x;
    idx_s[tid] = sel[b * KKc + tid];
    idx_s[tid + 256] = sel[b * KKc + tid + 256];
    __syncthreads();

    float acc = 0.f; int cnt = 0;
    for (int k = 0; k < KKc; k++) {
        const int idx = idx_s[k];
        if (idx < NN) { acc += enc[((size_t)b * NN + idx) * HH + tid]; cnt++; }
    }
    mean_s[tid] = acc / (float)(cnt > 0 ? cnt : 1);
    __syncthreads();

    float c = bc[tid];
    for (int i = 0; i < HH; i++) c += mean_s[i] * Wc[i * HH + tid];
    ctx_s[tid] = c;
    __syncthreads();

    const int wid = tid >> 5, lane = tid & 31;
    for (int k = wid; k < KKc; k += 8) {
        const int idx = idx_s[k];
        float s = -1e30f;
        if (idx < NN) {
            const float* row = enc + ((size_t)b * NN + idx) * HH;
            float part = 0.f;
            #pragma unroll
            for (int i = 0; i < 8; i++) part += ctx_s[lane + i * 32] * row[lane + i * 32];
            #pragma unroll
            for (int o = 16; o; o >>= 1) part += __shfl_xor_sync(0xffffffffu, part, o);
            s = part;
        }
        if (lane == 0) sc_s[k] = s;
    }
    __syncthreads();

    red_s[tid] = fmaxf(sc_s[tid], sc_s[tid + 256]);
    __syncthreads();
    for (int st = 128; st; st >>= 1) {
        if (tid < st) red_s[tid] = fmaxf(red_s[tid], red_s[tid + st]);
        __syncthreads();
    }
    const float m = red_s[0];
    __syncthreads();

    const int i0 = idx_s[tid], i1 = idx_s[tid + 256];
    const float e0 = (i0 < NN) ? expf(sc_s[tid] - m) : 0.f;
    const float e1 = (i1 < NN) ? expf(sc_s[tid + 256] - m) : 0.f;
    red_s[tid] = e0 + e1;
    __syncthreads();
    for (int st = 128; st; st >>= 1) {
        if (tid < st) red_s[tid] += red_s[tid + st];
        __syncthreads();
    }
    const float denom = red_s[0];
    __syncthreads();

    float a0 = rintf(e0 / denom * 100.f);
    float a1 = rintf(e1 / denom * 100.f);
    red_s[tid] = a0 + a1;
    __syncthreads();
    for (int st = 128; st; st >>= 1) {
        if (tid < st) red_s[tid] += red_s[tid + st];
        __syncthreads();
    }
    const float diff = 100.f - red_s[0];
    __syncthreads();

    if (tid == 0 && i0 < NN) a0 += diff;
    if (i0 < NN) bw[b * NN + i0] = a0;
    if (i1 < NN) bw[b * NN + i1] = a1;
}

// ---------------- launch ----------------
extern "C" void kernel_launch(void* const* d_in, const int* in_sizes, int n_in,
                              void* d_out, int out_size)
{
    const float* x    = (const float*)d_in[0];
    const int*   sel  = (const int*)  d_in[1];
    const float* W_in = (const float*)d_in[2];
    const float* b_in = (const float*)d_in[3];
    const float* Wqkv = (const float*)d_in[4];
    const float* bqkv = (const float*)d_in[5];
    const float* Wo   = (const float*)d_in[6];
    const float* bo   = (const float*)d_in[7];
    const float* ln1g = (const float*)d_in[8];
    const float* ln1b = (const float*)d_in[9];
    const float* W1   = (const float*)d_in[10];
    const float* b1   = (const float*)d_in[11];
    const float* W2   = (const float*)d_in[12];
    const float* b2   = (const float*)d_in[13];
    const float* ln2g = (const float*)d_in[14];
    const float* ln2b = (const float*)d_in[15];
    const float* Wc   = (const float*)d_in[16];
    const float* bc   = (const float*)d_in[17];

    float *h, *tmp;
    bf16 *xh, *xl, *hbh, *hbl, *qh, *ql, *ah, *al, *fh, *fl, *wh, *wl;
    cudaGetSymbolAddress((void**)&h,   g_h);   cudaGetSymbolAddress((void**)&tmp, g_tmp);
    cudaGetSymbolAddress((void**)&xh,  g_xh);  cudaGetSymbolAddress((void**)&xl,  g_xl);
    cudaGetSymbolAddress((void**)&hbh, g_hbh); cudaGetSymbolAddress((void**)&hbl, g_hbl);
    cudaGetSymbolAddress((void**)&qh,  g_qh);  cudaGetSymbolAddress((void**)&ql,  g_ql);
    cudaGetSymbolAddress((void**)&ah,  g_ah);  cudaGetSymbolAddress((void**)&al,  g_al);
    cudaGetSymbolAddress((void**)&fh,  g_fh);  cudaGetSymbolAddress((void**)&fl,  g_fl);
    cudaGetSymbolAddress((void**)&wh,  g_wh);  cudaGetSymbolAddress((void**)&wl,  g_wl);

    const int GSM = 4 * PLA + 4 * PLB;   // 122880
    const int ASM_ = 2 * PLA + 8 * PLV;  // 81920
    cudaFuncSetAttribute(gemm_mma, cudaFuncAttributeMaxDynamicSharedMemorySize, GSM);
    cudaFuncSetAttribute(attn_mma, cudaFuncAttributeMaxDynamicSharedMemorySize, ASM_);

    Segs S;
    S.seg[0] = { x, xh, xl, 0, 0, 1, (TOK * DIN) / 1024 };
    S.seg[1] = { W_in, wh + WOFF_IN, wl + WOFF_IN, DIN, HH, 0, (DIN/32)*(HH/32) };
    for (int l = 0; l < LL; l++) {
        S.seg[2+l] = { Wqkv + (size_t)l*HH*3*HH, wh + WOFF_QKV + l*HH*3*HH,
                       wl + WOFF_QKV + l*HH*3*HH, HH, 3*HH, 0, (HH/32)*(3*HH/32) };
        S.seg[4+l] = { Wo + (size_t)l*HH*HH, wh + WOFF_O + l*HH*HH,
                       wl + WOFF_O + l*HH*HH, HH, HH, 0, (HH/32)*(HH/32) };
        S.seg[6+l] = { W1 + (size_t)l*HH*FF, wh + WOFF_1 + l*HH*FF,
                       wl + WOFF_1 + l*HH*FF, HH, FF, 0, (HH/32)*(FF/32) };
        S.seg[8+l] = { W2 + (size_t)l*FF*HH, wh + WOFF_2 + l*FF*HH,
                       wl + WOFF_2 + l*FF*HH, FF, HH, 0, (FF/32)*(HH/32) };
    }
    prep_kernel<<<dim3(1024, 10), dim3(32, 8)>>>(S);

    gemm_mma<<<dim3(HH/128, TOK/256), 256, GSM>>>(
        xh, xl, wh + WOFF_IN, wl + WOFF_IN, b_in, nullptr, h, hbh, hbl, DIN, HH, 0);

    for (int l = 0; l < LL; l++) {
        gemm_mma<<<dim3(3*HH/128, TOK/256), 256, GSM>>>(
            hbh, hbl, wh + WOFF_QKV + l*HH*3*HH, wl + WOFF_QKV + l*HH*3*HH,
            bqkv + l*3*HH, nullptr, nullptr, qh, ql, HH, 3*HH, 0);
        attn_mma<<<dim3(NN/256, BB*8), 256, ASM_>>>(qh, ql, ah, al);
        gemm_mma<<<dim3(HH/128, TOK/256), 256, GSM>>>(
            ah, al, wh + WOFF_O + l*HH*HH, wl + WOFF_O + l*HH*HH,
            bo + l*HH, h, tmp, nullptr, nullptr, HH, HH, 0);
        ln_kernel<<<TOK/8, 256>>>(tmp, ln1g + l*HH, ln1b + l*HH, h, hbh, hbl);
        gemm_mma<<<dim3(FF/128, TOK/256), 256, GSM>>>(
            hbh, hbl, wh + WOFF_1 + l*HH*FF, wl + WOFF_1 + l*HH*FF,
            b1 + l*FF, nullptr, nullptr, fh, fl, HH, FF, 1);
        gemm_mma<<<dim3(HH/128, TOK/256), 256, GSM>>>(
            fh, fl, wh + WOFF_2 + l*FF*HH, wl + WOFF_2 + l*FF*HH,
            b2 + l*HH, h, tmp, nullptr, nullptr, FF, HH, 0);
        ln_kernel<<<TOK/8, 256>>>(tmp, ln2g + l*HH, ln2b + l*HH, h, hbh, hbl);
    }

    float* outf = (float*)d_out;
    const int idx_elems = BB * KKc, bw_elems = BB * NN;
    const int both = (out_size >= idx_elems + bw_elems) ? 1 : 0;
    float* bw = both ? (outf + idx_elems) : outf;
    init_out_kernel<<<(out_size + 255) / 256, 256>>>(sel, outf, out_size, both);
    alloc_kernel<<<BB, 256>>>(h, sel, Wc, bc, bw);
}

// round 8
// speedup vs baseline: 3.3422x; 1.0781x over previous
#include <cuda_runtime.h>
#include <cuda_bf16.h>
#include <cstdint>

#define BB 16
#define NN 1024
#define KKc 512
#define DIN 64
#define HH 256
#define FF 1024
#define LL 2
#define TOK (BB*NN)

typedef __nv_bfloat16 bf16;

#define WOFF_IN 0
#define WOFF_QKV (WOFF_IN + DIN*HH)
#define WOFF_O (WOFF_QKV + LL*HH*3*HH)
#define WOFF_1 (WOFF_O + LL*HH*HH)
#define WOFF_2 (WOFF_1 + LL*HH*FF)
#define WTOT (WOFF_2 + LL*FF*HH)

__device__ __align__(16) float g_h[TOK*HH], g_tmp[TOK*HH];
__device__ __align__(16) bf16 g_xh[TOK*DIN], g_xl[TOK*DIN];
__device__ __align__(16) bf16 g_hbh[TOK*HH], g_hbl[TOK*HH];
__device__ __align__(16) bf16 g_qh[TOK*768], g_ql[TOK*768];
__device__ __align__(16) bf16 g_ah[TOK*HH], g_al[TOK*HH];
__device__ __align__(16) bf16 g_fh[TOK*FF], g_fl[TOK*FF];
__device__ __align__(16) bf16 g_wh[WTOT], g_wl[WTOT];

// ---------------- helpers ----------------
__device__ __forceinline__ uint32_t smem_u32(const void* p) {
    uint32_t a;
    asm("{ .reg .u64 t; cvta.to.shared.u64 t, %1; cvt.u32.u64 %0, t; }" : "=r"(a) : "l"(p));
    return a;
}
__device__ __forceinline__ void cp16(uint32_t d, const void* s) {
    asm volatile("cp.async.cg.shared.global [%0], [%1], 16;" :: "r"(d), "l"(s));
}
#define CPCOMMIT() asm volatile("cp.async.commit_group;" ::: "memory")
#define CPWAIT(n)  asm volatile("cp.async.wait_group %0;" :: "n"(n) : "memory")

__device__ __forceinline__ void ldm4(uint32_t* r, uint32_t a) {
    asm volatile("ldmatrix.sync.aligned.m8n8.x4.shared.b16 {%0,%1,%2,%3}, [%4];"
                 : "=r"(r[0]), "=r"(r[1]), "=r"(r[2]), "=r"(r[3]) : "r"(a));
}
__device__ __forceinline__ void ldm4t(uint32_t* r, uint32_t a) {
    asm volatile("ldmatrix.sync.aligned.m8n8.x4.trans.shared.b16 {%0,%1,%2,%3}, [%4];"
                 : "=r"(r[0]), "=r"(r[1]), "=r"(r[2]), "=r"(r[3]) : "r"(a));
}
__device__ __forceinline__ void mma_b16(float* c, const uint32_t* a, const uint32_t* b) {
    asm volatile("mma.sync.aligned.m16n8k16.row.col.f32.bf16.bf16.f32 "
                 "{%0,%1,%2,%3},{%4,%5,%6,%7},{%8,%9},{%0,%1,%2,%3};"
                 : "+f"(c[0]), "+f"(c[1]), "+f"(c[2]), "+f"(c[3])
                 : "r"(a[0]), "r"(a[1]), "r"(a[2]), "r"(a[3]), "r"(b[0]), "r"(b[1]));
}
__device__ __forceinline__ uint32_t bf2(float lo, float hi) {
    uint32_t r;
    asm("cvt.rn.bf16x2.f32 %0, %1, %2;" : "=r"(r) : "f"(hi), "f"(lo));
    return r;
}
__device__ __forceinline__ void split_pack(float a, float b, uint32_t& hi, uint32_t& lo) {
    float ah = __bfloat162float(__float2bfloat16(a));
    float bh = __bfloat162float(__float2bfloat16(b));
    hi = bf2(ah, bh); lo = bf2(a - ah, b - bh);
}

#define RS 40        // smem row stride (bf16): 80B, conflict-free ldmatrix
#define PLB 10240    // 128-row plane bytes (128*RS*2)

// ---------------- prep: weight transpose/split + x split ----------------
struct Seg { const float* s; bf16 *dh, *dl; int K, N, mode, ntiles; };
struct Segs { Seg seg[10]; };

__global__ void prep_kernel(Segs S) {
    Seg sg = S.seg[blockIdx.y];
    if ((int)blockIdx.x >= sg.ntiles) return;
    const int tx = threadIdx.x, ty = threadIdx.y;
    if (sg.mode == 1) {
        int off = blockIdx.x * 1024 + ty * 128 + tx * 4;
        float4 v = *(const float4*)(sg.s + off);
        float a[4] = {v.x, v.y, v.z, v.w};
        #pragma unroll
        for (int i = 0; i < 4; i++) {
            bf16 h = __float2bfloat16(a[i]);
            sg.dh[off + i] = h;
            sg.dl[off + i] = __float2bfloat16(a[i] - __bfloat162float(h));
        }
    } else {
        __shared__ float tile[32][33];
        int kt = blockIdx.x % (sg.K / 32), nt = blockIdx.x / (sg.K / 32);
        int k0 = kt * 32, n0 = nt * 32;
        #pragma unroll
        for (int i = 0; i < 4; i++)
            tile[ty * 4 + i][tx] = sg.s[(size_t)(k0 + ty * 4 + i) * sg.N + n0 + tx];
        __syncthreads();
        #pragma unroll
        for (int i = 0; i < 4; i++) {
            float v = tile[tx][ty * 4 + i];
            bf16 h = __float2bfloat16(v);
            size_t d = (size_t)(n0 + ty * 4 + i) * sg.K + k0 + tx;
            sg.dh[d] = h;
            sg.dl[d] = __float2bfloat16(v - __bfloat162float(h));
        }
    }
}

// ---------------- split-bf16 HMMA GEMM, 128x128 block, 64x64 warp, 128 thr --
// C[M,N] = A[M,K] @ B[N,K]^T + bias (+res)(+relu). grid(N/128, M/128).
// smem planes @ (p*2+buf)*PLB, p={Ah,Al,Bh,Bl}. total 81920 B -> 2 CTA/SM.
__global__ __launch_bounds__(128) void gemm_mma(
    const bf16* __restrict__ Ah, const bf16* __restrict__ Al,
    const bf16* __restrict__ Bh, const bf16* __restrict__ Bl,
    const float* __restrict__ bias, const float* __restrict__ res,
    float* __restrict__ Cf, bf16* __restrict__ Cbh, bf16* __restrict__ Cbl,
    int K, int N, int relu)
{
    extern __shared__ __align__(16) bf16 smr[];
    const int tid = threadIdx.x, lane = tid & 31, wid = tid >> 5;
    const int m0 = blockIdx.y << 7, n0 = blockIdx.x << 7;
    const int wm = (wid & 1) << 6, wn = (wid >> 1) << 6;
    const uint32_t sb = smem_u32(smr);
    const uint32_t sbA = sb, sbAl = sb + 2 * PLB;
    const uint32_t sbB = sb + 4 * PLB, sbBl = sb + 6 * PLB;

    float acc[4][8][4];
    #pragma unroll
    for (int a = 0; a < 4; a++)
        #pragma unroll
        for (int b = 0; b < 8; b++)
            #pragma unroll
            for (int c = 0; c < 4; c++) acc[a][b][c] = 0.f;

    const int nst = K >> 5;

    #pragma unroll 1
    for (int sp = 0; sp <= nst; sp++) {
        if (sp < nst) {           // issue stage sp
            const int k0 = sp << 5, buf = sp & 1;
            #pragma unroll
            for (int i = 0; i < 8; i++) {   // A: 1024 chunks (hi+lo)
                int idx = tid + (i << 7);
                int pl = idx >> 9, rest = idx & 511;
                int r = rest >> 2, c8 = (rest & 3) << 3;
                uint32_t so = (uint32_t)(r * RS + c8) << 1;
                const bf16* src = (pl ? Al : Ah) + (size_t)(m0 + r) * K + k0 + c8;
                cp16((pl ? sbAl : sbA) + buf * PLB + so, src);
            }
            #pragma unroll
            for (int i = 0; i < 8; i++) {   // B: 1024 chunks (hi+lo)
                int idx = tid + (i << 7);
                int pl = idx >> 9, rest = idx & 511;
                int r = rest >> 2, c8 = (rest & 3) << 3;
                uint32_t so = (uint32_t)(r * RS + c8) << 1;
                const bf16* src = (pl ? Bl : Bh) + (size_t)(n0 + r) * K + k0 + c8;
                cp16((pl ? sbBl : sbB) + buf * PLB + so, src);
            }
            CPCOMMIT();
        }
        if (sp == 0) continue;
        const int s = sp - 1;     // compute stage s
        if (sp < nst) { CPWAIT(1); } else { CPWAIT(0); }
        __syncthreads();

        const int buf = s & 1;
        const uint32_t pAh = sbA + buf * PLB, pAl = sbAl + buf * PLB;
        const uint32_t pBh = sbB + buf * PLB, pBl = sbBl + buf * PLB;
        #pragma unroll
        for (int ks = 0; ks < 2; ks++) {
            uint32_t ah[4][4], al[4][4];
            #pragma unroll
            for (int mt = 0; mt < 4; mt++) {
                uint32_t off = (uint32_t)((wm + mt * 16 + (lane & 15)) * RS
                                          + ks * 16 + ((lane >> 4) << 3)) << 1;
                ldm4(ah[mt], pAh + off); ldm4(al[mt], pAl + off);
            }
            #pragma unroll
            for (int nt = 0; nt < 4; nt++) {
                uint32_t bh[4], bl[4];
                uint32_t off = (uint32_t)((wn + nt * 16 + (lane & 7) + ((lane >> 4) << 3)) * RS
                                          + ks * 16 + ((lane >> 3) & 1) * 8) << 1;
                ldm4(bh, pBh + off); ldm4(bl, pBl + off);
                #pragma unroll
                for (int mt = 0; mt < 4; mt++)
                    #pragma unroll
                    for (int t = 0; t < 2; t++) {
                        float* c = acc[mt][nt * 2 + t];
                        mma_b16(c, ah[mt], bh + 2 * t);
                        mma_b16(c, ah[mt], bl + 2 * t);
                        mma_b16(c, al[mt], bh + 2 * t);
                    }
            }
        }
        __syncthreads();
    }

    // epilogue
    #pragma unroll
    for (int mt = 0; mt < 4; mt++)
        #pragma unroll
        for (int nt = 0; nt < 8; nt++) {
            int r0 = m0 + wm + mt * 16 + (lane >> 2);
            int c  = n0 + wn + nt * 8 + ((lane & 3) << 1);
            float* a = acc[mt][nt];
            float b0 = bias[c], b1 = bias[c + 1];
            float v0 = a[0] + b0, v1 = a[1] + b1, v2 = a[2] + b0, v3 = a[3] + b1;
            if (res) {
                float2 q0 = *(const float2*)(res + (size_t)r0 * N + c);
                float2 q1 = *(const float2*)(res + (size_t)(r0 + 8) * N + c);
                v0 += q0.x; v1 += q0.y; v2 += q1.x; v3 += q1.y;
            }
            if (relu) {
                v0 = fmaxf(v0, 0.f); v1 = fmaxf(v1, 0.f);
                v2 = fmaxf(v2, 0.f); v3 = fmaxf(v3, 0.f);
            }
            if (Cf) {
                *(float2*)(Cf + (size_t)r0 * N + c)       = make_float2(v0, v1);
                *(float2*)(Cf + (size_t)(r0 + 8) * N + c) = make_float2(v2, v3);
            }
            if (Cbh) {
                uint32_t h0, l0, h1, l1;
                split_pack(v0, v1, h0, l0); split_pack(v2, v3, h1, l1);
                *(uint32_t*)(Cbh + (size_t)r0 * N + c) = h0;
                *(uint32_t*)(Cbl + (size_t)r0 * N + c) = l0;
                *(uint32_t*)(Cbh + (size_t)(r0 + 8) * N + c) = h1;
                *(uint32_t*)(Cbl + (size_t)(r0 + 8) * N + c) = l1;
            }
        }
}

// ---------------- fused HMMA flash attention ----------------
// grid (NN/128, BB*8), 128 thr, 4 warps x 32 q-rows. 128-key stages (8).
// smem: Qh@0, Ql@PLB; KV stages @(2 + buf*4 + p)*PLB, p={Kh,Kl,Vh,Vl}.
// total 102400 B -> 2 CTA/SM.
__global__ __launch_bounds__(128) void attn_mma(
    const bf16* __restrict__ qh, const bf16* __restrict__ ql,
    bf16* __restrict__ oh, bf16* __restrict__ ol)
{
    extern __shared__ __align__(16) bf16 smr[];
    const int tid = threadIdx.x, lane = tid & 31, wid = tid >> 5;
    const int bhn = blockIdx.y, b = bhn >> 3, h = bhn & 7;
    const int q0 = blockIdx.x << 7;
    const size_t base = (size_t)b * NN;
    const uint32_t sb = smem_u32(smr);
    const uint32_t sbKV = sb + 2 * PLB;
    const float SC = 0.17677669529663687f;

    // issue Q (1024 chunks) + stage 0 (2048 chunks)
    #pragma unroll
    for (int i = 0; i < 8; i++) {
        int idx = tid + (i << 7);
        int pl = idx >> 9, rest = idx & 511;
        int r = rest >> 2, c8 = (rest & 3) << 3;
        uint32_t so = (uint32_t)(r * RS + c8) << 1;
        const bf16* src = (pl ? ql : qh) + (base + q0 + r) * 768 + h * 32 + c8;
        cp16(sb + pl * PLB + so, src);
    }
    #pragma unroll
    for (int i = 0; i < 16; i++) {
        int idx = tid + (i << 7);
        int pl = idx >> 9, rest = idx & 511;
        int r = rest >> 2, c8 = (rest & 3) << 3;
        uint32_t so = (uint32_t)(r * RS + c8) << 1;
        int fo = (pl >> 1) ? 512 : 256;
        const bf16* src = ((pl & 1) ? ql : qh) + (base + r) * 768 + fo + h * 32 + c8;
        cp16(sbKV + pl * PLB + so, src);
    }
    CPCOMMIT();

    uint32_t qfh[2][2][4], qfl[2][2][4];
    float oacc[2][4][4];
    #pragma unroll
    for (int m = 0; m < 2; m++)
        #pragma unroll
        for (int a = 0; a < 4; a++)
            #pragma unroll
            for (int c = 0; c < 4; c++) oacc[m][a][c] = 0.f;
    float rs[2][2] = {{0.f, 0.f}, {0.f, 0.f}};

    for (int s = 0; s < 8; s++) {
        if (s < 7) {
            const int kv0 = (s + 1) << 7, buf = (s + 1) & 1;
            #pragma unroll
            for (int i = 0; i < 16; i++) {
                int idx = tid + (i << 7);
                int pl = idx >> 9, rest = idx & 511;
                int r = rest >> 2, c8 = (rest & 3) << 3;
                uint32_t so = (uint32_t)(r * RS + c8) << 1;
                int fo = (pl >> 1) ? 512 : 256;
                const bf16* src = ((pl & 1) ? ql : qh) + (base + kv0 + r) * 768 + fo + h * 32 + c8;
                cp16(sbKV + (buf * 4 + pl) * PLB + so, src);
            }
            CPCOMMIT();
            CPWAIT(1);
        } else {
            CPWAIT(0);
        }
        __syncthreads();

        if (s == 0) {
            #pragma unroll
            for (int mt = 0; mt < 2; mt++)
                #pragma unroll
                for (int ks = 0; ks < 2; ks++) {
                    uint32_t off = (uint32_t)((wid * 32 + mt * 16 + (lane & 15)) * RS
                                              + ks * 16 + ((lane >> 4) << 3)) << 1;
                    ldm4(qfh[mt][ks], sb + off);
                    ldm4(qfl[mt][ks], sb + PLB + off);
                }
        }

        const int buf = s & 1;
        const uint32_t kH = sbKV + (buf * 4 + 0) * PLB;
        const uint32_t kL = kH + PLB, vH = kH + 2 * PLB, vL = kH + 3 * PLB;

        #pragma unroll
        for (int kk = 0; kk < 8; kk++) {
            float sv[2][2][4];
            #pragma unroll
            for (int m = 0; m < 2; m++)
                #pragma unroll
                for (int t = 0; t < 2; t++)
                    #pragma unroll
                    for (int c = 0; c < 4; c++) sv[m][t][c] = 0.f;
            #pragma unroll
            for (int ks = 0; ks < 2; ks++) {
                uint32_t bh[4], bl[4];
                uint32_t off = (uint32_t)((kk * 16 + (lane & 7) + ((lane >> 4) << 3)) * RS
                                          + ks * 16 + ((lane >> 3) & 1) * 8) << 1;
                ldm4(bh, kH + off); ldm4(bl, kL + off);
                #pragma unroll
                for (int mt = 0; mt < 2; mt++)
                    #pragma unroll
                    for (int t = 0; t < 2; t++) {
                        float* c = sv[mt][t];
                        mma_b16(c, qfh[mt][ks], bh + 2 * t);
                        mma_b16(c, qfh[mt][ks], bl + 2 * t);
                        mma_b16(c, qfl[mt][ks], bh + 2 * t);
                    }
            }
            // exp + split P + V frags + PV
            uint32_t va[4], vb[4], vc[4], vd[4];
            {
                uint32_t ro = kk * 16 + (lane & 7) + (((lane >> 3) & 1) << 3);
                uint32_t ofa = (uint32_t)(ro * RS + ((lane >> 4) << 3)) << 1;
                uint32_t ofb = (uint32_t)(ro * RS + 16 + ((lane >> 4) << 3)) << 1;
                ldm4t(va, vH + ofa); ldm4t(vb, vH + ofb);
                ldm4t(vc, vL + ofa); ldm4t(vd, vL + ofb);
            }
            #pragma unroll
            for (int mt = 0; mt < 2; mt++) {
                float e00 = __expf(sv[mt][0][0] * SC), e01 = __expf(sv[mt][0][1] * SC);
                float e02 = __expf(sv[mt][0][2] * SC), e03 = __expf(sv[mt][0][3] * SC);
                float e10 = __expf(sv[mt][1][0] * SC), e11 = __expf(sv[mt][1][1] * SC);
                float e12 = __expf(sv[mt][1][2] * SC), e13 = __expf(sv[mt][1][3] * SC);
                rs[mt][0] += e00 + e01 + e10 + e11;
                rs[mt][1] += e02 + e03 + e12 + e13;
                uint32_t pah[4], pal[4];
                split_pack(e00, e01, pah[0], pal[0]);
                split_pack(e02, e03, pah[1], pal[1]);
                split_pack(e10, e11, pah[2], pal[2]);
                split_pack(e12, e13, pah[3], pal[3]);
                float* o = (float*)oacc[mt];
                mma_b16(o + 0,  pah, va);     mma_b16(o + 0,  pah, vc);     mma_b16(o + 0,  pal, va);
                mma_b16(o + 4,  pah, va + 2); mma_b16(o + 4,  pah, vc + 2); mma_b16(o + 4,  pal, va + 2);
                mma_b16(o + 8,  pah, vb);     mma_b16(o + 8,  pah, vd);     mma_b16(o + 8,  pal, vb);
                mma_b16(o + 12, pah, vb + 2); mma_b16(o + 12, pah, vd + 2); mma_b16(o + 12, pal, vb + 2);
            }
        }
        __syncthreads();
    }

    #pragma unroll
    for (int mt = 0; mt < 2; mt++) {
        float r0 = rs[mt][0], r1 = rs[mt][1];
        r0 += __shfl_xor_sync(0xffffffffu, r0, 1);
        r0 += __shfl_xor_sync(0xffffffffu, r0, 2);
        r1 += __shfl_xor_sync(0xffffffffu, r1, 1);
        r1 += __shfl_xor_sync(0xffffffffu, r1, 2);
        const float i0 = 1.f / r0, i1 = 1.f / r1;
        #pragma unroll
        for (int nt = 0; nt < 4; nt++) {
            int row = q0 + wid * 32 + mt * 16 + (lane >> 2);
            int c   = h * 32 + nt * 8 + ((lane & 3) << 1);
            float v0 = oacc[mt][nt][0] * i0, v1 = oacc[mt][nt][1] * i0;
            float v2 = oacc[mt][nt][2] * i1, v3 = oacc[mt][nt][3] * i1;
            uint32_t h0, l0, h1, l1;
            split_pack(v0, v1, h0, l0); split_pack(v2, v3, h1, l1);
            *(uint32_t*)(oh + (base + row) * HH + c) = h0;
            *(uint32_t*)(ol + (base + row) * HH + c) = l0;
            *(uint32_t*)(oh + (base + row + 8) * HH + c) = h1;
            *(uint32_t*)(ol + (base + row + 8) * HH + c) = l1;
        }
    }
}

// ---------------- LayerNorm: fp32 in -> fp32 + bf16 hi/lo ----------------
__global__ __launch_bounds__(256) void ln_kernel(
    const float* __restrict__ x, const float* __restrict__ gam,
    const float* __restrict__ bet, float* __restrict__ out,
    bf16* __restrict__ ohp, bf16* __restrict__ olp)
{
    const int row = blockIdx.x * 8 + (threadIdx.x >> 5);
    const int lane = threadIdx.x & 31;
    const float* xr = x + (size_t)row * HH;
    float v[8], sum = 0.f;
    #pragma unroll
    for (int i = 0; i < 8; i++) { v[i] = xr[lane + i * 32]; sum += v[i]; }
    #pragma unroll
    for (int o = 16; o; o >>= 1) sum += __shfl_xor_sync(0xffffffffu, sum, o);
    const float mean = sum * (1.f / HH);
    float var = 0.f;
    #pragma unroll
    for (int i = 0; i < 8; i++) { float d = v[i] - mean; var += d * d; }
    #pragma unroll
    for (int o = 16; o; o >>= 1) var += __shfl_xor_sync(0xffffffffu, var, o);
    const float inv = rsqrtf(var * (1.f / HH) + 1e-5f);
    #pragma unroll
    for (int i = 0; i < 8; i++) {
        const int c = lane + i * 32;
        float val = (v[i] - mean) * inv * gam[c] + bet[c];
        out[(size_t)row * HH + c] = val;
        bf16 hb = __float2bfloat16(val);
        ohp[(size_t)row * HH + c] = hb;
        olp[(size_t)row * HH + c] = __float2bfloat16(val - __bfloat162float(hb));
    }
}

// ---------------- output init + allocation ----------------
__global__ void init_out_kernel(const int* __restrict__ sel, float* __restrict__ out,
                                int out_size, int both)
{
    const int i = blockIdx.x * 256 + threadIdx.x;
    if (i >= out_size) return;
    if (both && i < BB * KKc) out[i] = (float)sel[i];
    else out[i] = 0.f;
}

__global__ __launch_bounds__(256) void alloc_kernel(
    const float* __restrict__ enc, const int* __restrict__ sel,
    const float* __restrict__ Wc, const float* __restrict__ bc,
    float* __restrict__ bw)
{
    __shared__ float mean_s[HH], ctx_s[HH], sc_s[KKc], red_s[256];
    __shared__ int idx_s[KKc];
    const int b = blockIdx.x, tid = threadIdx.x;
    idx_s[tid] = sel[b * KKc + tid];
    idx_s[tid + 256] = sel[b * KKc + tid + 256];
    __syncthreads();

    float acc = 0.f; int cnt = 0;
    for (int k = 0; k < KKc; k++) {
        const int idx = idx_s[k];
        if (idx < NN) { acc += enc[((size_t)b * NN + idx) * HH + tid]; cnt++; }
    }
    mean_s[tid] = acc / (float)(cnt > 0 ? cnt : 1);
    __syncthreads();

    float c = bc[tid];
    for (int i = 0; i < HH; i++) c += mean_s[i] * Wc[i * HH + tid];
    ctx_s[tid] = c;
    __syncthreads();

    const int wid = tid >> 5, lane = tid & 31;
    for (int k = wid; k < KKc; k += 8) {
        const int idx = idx_s[k];
        float s = -1e30f;
        if (idx < NN) {
            const float* row = enc + ((size_t)b * NN + idx) * HH;
            float part = 0.f;
            #pragma unroll
            for (int i = 0; i < 8; i++) part += ctx_s[lane + i * 32] * row[lane + i * 32];
            #pragma unroll
            for (int o = 16; o; o >>= 1) part += __shfl_xor_sync(0xffffffffu, part, o);
            s = part;
        }
        if (lane == 0) sc_s[k] = s;
    }
    __syncthreads();

    red_s[tid] = fmaxf(sc_s[tid], sc_s[tid + 256]);
    __syncthreads();
    for (int st = 128; st; st >>= 1) {
        if (tid < st) red_s[tid] = fmaxf(red_s[tid], red_s[tid + st]);
        __syncthreads();
    }
    const float m = red_s[0];
    __syncthreads();

    const int i0 = idx_s[tid], i1 = idx_s[tid + 256];
    const float e0 = (i0 < NN) ? expf(sc_s[tid] - m) : 0.f;
    const float e1 = (i1 < NN) ? expf(sc_s[tid + 256] - m) : 0.f;
    red_s[tid] = e0 + e1;
    __syncthreads();
    for (int st = 128; st; st >>= 1) {
        if (tid < st) red_s[tid] += red_s[tid + st];
        __syncthreads();
    }
    const float denom = red_s[0];
    __syncthreads();

    float a0 = rintf(e0 / denom * 100.f);
    float a1 = rintf(e1 / denom * 100.f);
    red_s[tid] = a0 + a1;
    __syncthreads();
    for (int st = 128; st; st >>= 1) {
        if (tid < st) red_s[tid] += red_s[tid + st];
        __syncthreads();
    }
    const float diff = 100.f - red_s[0];
    __syncthreads();

    if (tid == 0 && i0 < NN) a0 += diff;
    if (i0 < NN) bw[b * NN + i0] = a0;
    if (i1 < NN) bw[b * NN + i1] = a1;
}

// ---------------- launch ----------------
extern "C" void kernel_launch(void* const* d_in, const int* in_sizes, int n_in,
                              void* d_out, int out_size)
{
    const float* x    = (const float*)d_in[0];
    const int*   sel  = (const int*)  d_in[1];
    const float* W_in = (const float*)d_in[2];
    const float* b_in = (const float*)d_in[3];
    const float* Wqkv = (const float*)d_in[4];
    const float* bqkv = (const float*)d_in[5];
    const float* Wo   = (const float*)d_in[6];
    const float* bo   = (const float*)d_in[7];
    const float* ln1g = (const float*)d_in[8];
    const float* ln1b = (const float*)d_in[9];
    const float* W1   = (const float*)d_in[10];
    const float* b1   = (const float*)d_in[11];
    const float* W2   = (const float*)d_in[12];
    const float* b2   = (const float*)d_in[13];
    const float* ln2g = (const float*)d_in[14];
    const float* ln2b = (const float*)d_in[15];
    const float* Wc   = (const float*)d_in[16];
    const float* bc   = (const float*)d_in[17];

    float *h, *tmp;
    bf16 *xh, *xl, *hbh, *hbl, *qh, *ql, *ah, *al, *fh, *fl, *wh, *wl;
    cudaGetSymbolAddress((void**)&h,   g_h);   cudaGetSymbolAddress((void**)&tmp, g_tmp);
    cudaGetSymbolAddress((void**)&xh,  g_xh);  cudaGetSymbolAddress((void**)&xl,  g_xl);
    cudaGetSymbolAddress((void**)&hbh, g_hbh); cudaGetSymbolAddress((void**)&hbl, g_hbl);
    cudaGetSymbolAddress((void**)&qh,  g_qh);  cudaGetSymbolAddress((void**)&ql,  g_ql);
    cudaGetSymbolAddress((void**)&ah,  g_ah);  cudaGetSymbolAddress((void**)&al,  g_al);
    cudaGetSymbolAddress((void**)&fh,  g_fh);  cudaGetSymbolAddress((void**)&fl,  g_fl);
    cudaGetSymbolAddress((void**)&wh,  g_wh);  cudaGetSymbolAddress((void**)&wl,  g_wl);

    const int GSM = 8 * PLB;     // 81920
    const int ASM_ = 10 * PLB;   // 102400
    cudaFuncSetAttribute(gemm_mma, cudaFuncAttributeMaxDynamicSharedMemorySize, GSM);
    cudaFuncSetAttribute(attn_mma, cudaFuncAttributeMaxDynamicSharedMemorySize, ASM_);

    Segs S;
    S.seg[0] = { x, xh, xl, 0, 0, 1, (TOK * DIN) / 1024 };
    S.seg[1] = { W_in, wh + WOFF_IN, wl + WOFF_IN, DIN, HH, 0, (DIN/32)*(HH/32) };
    for (int l = 0; l < LL; l++) {
        S.seg[2+l] = { Wqkv + (size_t)l*HH*3*HH, wh + WOFF_QKV + l*HH*3*HH,
                       wl + WOFF_QKV + l*HH*3*HH, HH, 3*HH, 0, (HH/32)*(3*HH/32) };
        S.seg[4+l] = { Wo + (size_t)l*HH*HH, wh + WOFF_O + l*HH*HH,
                       wl + WOFF_O + l*HH*HH, HH, HH, 0, (HH/32)*(HH/32) };
        S.seg[6+l] = { W1 + (size_t)l*HH*FF, wh + WOFF_1 + l*HH*FF,
                       wl + WOFF_1 + l*HH*FF, HH, FF, 0, (HH/32)*(FF/32) };
        S.seg[8+l] = { W2 + (size_t)l*FF*HH, wh + WOFF_2 + l*FF*HH,
                       wl + WOFF_2 + l*FF*HH, FF, HH, 0, (FF/32)*(HH/32) };
    }
    prep_kernel<<<dim3(1024, 10), dim3(32, 8)>>>(S);

    gemm_mma<<<dim3(HH/128, TOK/128), 128, GSM>>>(
        xh, xl, wh + WOFF_IN, wl + WOFF_IN, b_in, nullptr, h, hbh, hbl, DIN, HH, 0);

    for (int l = 0; l < LL; l++) {
        gemm_mma<<<dim3(3*HH/128, TOK/128), 128, GSM>>>(
            hbh, hbl, wh + WOFF_QKV + l*HH*3*HH, wl + WOFF_QKV + l*HH*3*HH,
            bqkv + l*3*HH, nullptr, nullptr, qh, ql, HH, 3*HH, 0);
        attn_mma<<<dim3(NN/128, BB*8), 128, ASM_>>>(qh, ql, ah, al);
        gemm_mma<<<dim3(HH/128, TOK/128), 128, GSM>>>(
            ah, al, wh + WOFF_O + l*HH*HH, wl + WOFF_O + l*HH*HH,
            bo + l*HH, h, tmp, nullptr, nullptr, HH, HH, 0);
        ln_kernel<<<TOK/8, 256>>>(tmp, ln1g + l*HH, ln1b + l*HH, h, hbh, hbl);
        gemm_mma<<<dim3(FF/128, TOK/128), 128, GSM>>>(
            hbh, hbl, wh + WOFF_1 + l*HH*FF, wl + WOFF_1 + l*HH*FF,
            b1 + l*FF, nullptr, nullptr, fh, fl, HH, FF, 1);
        gemm_mma<<<dim3(HH/128, TOK/128), 128, GSM>>>(
            fh, fl, wh + WOFF_2 + l*FF*HH, wl + WOFF_2 + l*FF*HH,
            b2 + l*HH, h, tmp, nullptr, nullptr, FF, HH, 0);
        ln_kernel<<<TOK/8, 256>>>(tmp, ln2g + l*HH, ln2b + l*HH, h, hbh, hbl);
    }

    float* outf = (float*)d_out;
    const int idx_elems = BB * KKc, bw_elems = BB * NN;
    const int both = (out_size >= idx_elems + bw_elems) ? 1 : 0;
    float* bw = both ? (outf + idx_elems) : outf;
    init_out_kernel<<<(out_size + 255) / 256, 256>>>(sel, outf, out_size, both);
    alloc_kernel<<<BB, 256>>>(h, sel, Wc, bc, bw);
}

// round 9
// speedup vs baseline: 3.4022x; 1.0180x over previous
#include <cuda_runtime.h>
#include <cuda_bf16.h>
#include <cstdint>

#define BB 16
#define NN 1024
#define KKc 512
#define DIN 64
#define HH 256
#define FF 1024
#define LL 2
#define TOK (BB*NN)

typedef __nv_bfloat16 bf16;

#define WOFF_IN 0
#define WOFF_QKV (WOFF_IN + DIN*HH)
#define WOFF_O (WOFF_QKV + LL*HH*3*HH)
#define WOFF_1 (WOFF_O + LL*HH*HH)
#define WOFF_2 (WOFF_1 + LL*HH*FF)
#define WTOT (WOFF_2 + LL*FF*HH)

__device__ __align__(16) float g_h[TOK*HH], g_tmp[TOK*HH];
__device__ __align__(16) bf16 g_xh[TOK*DIN], g_xl[TOK*DIN];
__device__ __align__(16) bf16 g_hbh[TOK*HH], g_hbl[TOK*HH];
__device__ __align__(16) bf16 g_qh[TOK*768], g_ql[TOK*768];
__device__ __align__(16) bf16 g_ah[TOK*HH], g_al[TOK*HH];
__device__ __align__(16) bf16 g_fh[TOK*FF], g_fl[TOK*FF];
__device__ __align__(16) bf16 g_wh[WTOT], g_wl[WTOT];

// ---------------- helpers ----------------
__device__ __forceinline__ uint32_t smem_u32(const void* p) {
    uint32_t a;
    asm("{ .reg .u64 t; cvta.to.shared.u64 t, %1; cvt.u32.u64 %0, t; }" : "=r"(a) : "l"(p));
    return a;
}
__device__ __forceinline__ void cp16(uint32_t d, const void* s) {
    asm volatile("cp.async.cg.shared.global [%0], [%1], 16;" :: "r"(d), "l"(s));
}
#define CPCOMMIT() asm volatile("cp.async.commit_group;" ::: "memory")
#define CPWAIT(n)  asm volatile("cp.async.wait_group %0;" :: "n"(n) : "memory")

__device__ __forceinline__ void ldm4(uint32_t* r, uint32_t a) {
    asm volatile("ldmatrix.sync.aligned.m8n8.x4.shared.b16 {%0,%1,%2,%3}, [%4];"
                 : "=r"(r[0]), "=r"(r[1]), "=r"(r[2]), "=r"(r[3]) : "r"(a));
}
__device__ __forceinline__ void ldm4t(uint32_t* r, uint32_t a) {
    asm volatile("ldmatrix.sync.aligned.m8n8.x4.trans.shared.b16 {%0,%1,%2,%3}, [%4];"
                 : "=r"(r[0]), "=r"(r[1]), "=r"(r[2]), "=r"(r[3]) : "r"(a));
}
__device__ __forceinline__ void mma_b16(float* c, const uint32_t* a, const uint32_t* b) {
    asm volatile("mma.sync.aligned.m16n8k16.row.col.f32.bf16.bf16.f32 "
                 "{%0,%1,%2,%3},{%4,%5,%6,%7},{%8,%9},{%0,%1,%2,%3};"
                 : "+f"(c[0]), "+f"(c[1]), "+f"(c[2]), "+f"(c[3])
                 : "r"(a[0]), "r"(a[1]), "r"(a[2]), "r"(a[3]), "r"(b[0]), "r"(b[1]));
}
__device__ __forceinline__ uint32_t bf2(float lo, float hi) {
    uint32_t r;
    asm("cvt.rn.bf16x2.f32 %0, %1, %2;" : "=r"(r) : "f"(hi), "f"(lo));
    return r;
}
__device__ __forceinline__ void split_pack(float a, float b, uint32_t& hi, uint32_t& lo) {
    float ah = __bfloat162float(__float2bfloat16(a));
    float bh = __bfloat162float(__float2bfloat16(b));
    hi = bf2(ah, bh); lo = bf2(a - ah, b - bh);
}

#define RS 40        // smem row stride (bf16): 80B, conflict-free ldmatrix
#define PLB 10240    // 128-row plane bytes (128*RS*2)
#define PLV 5120     // 64-row plane bytes (64*RS*2)

// ---------------- prep: weight transpose/split + x split ----------------
struct Seg { const float* s; bf16 *dh, *dl; int K, N, mode, ntiles; };
struct Segs { Seg seg[10]; };

__global__ void prep_kernel(Segs S) {
    Seg sg = S.seg[blockIdx.y];
    if ((int)blockIdx.x >= sg.ntiles) return;
    const int tx = threadIdx.x, ty = threadIdx.y;
    if (sg.mode == 1) {
        int off = blockIdx.x * 1024 + ty * 128 + tx * 4;
        float4 v = *(const float4*)(sg.s + off);
        float a[4] = {v.x, v.y, v.z, v.w};
        #pragma unroll
        for (int i = 0; i < 4; i++) {
            bf16 h = __float2bfloat16(a[i]);
            sg.dh[off + i] = h;
            sg.dl[off + i] = __float2bfloat16(a[i] - __bfloat162float(h));
        }
    } else {
        __shared__ float tile[32][33];
        int kt = blockIdx.x % (sg.K / 32), nt = blockIdx.x / (sg.K / 32);
        int k0 = kt * 32, n0 = nt * 32;
        #pragma unroll
        for (int i = 0; i < 4; i++)
            tile[ty * 4 + i][tx] = sg.s[(size_t)(k0 + ty * 4 + i) * sg.N + n0 + tx];
        __syncthreads();
        #pragma unroll
        for (int i = 0; i < 4; i++) {
            float v = tile[tx][ty * 4 + i];
            bf16 h = __float2bfloat16(v);
            size_t d = (size_t)(n0 + ty * 4 + i) * sg.K + k0 + tx;
            sg.dh[d] = h;
            sg.dl[d] = __float2bfloat16(v - __bfloat162float(h));
        }
    }
}

// ---------------- split-bf16 HMMA GEMM, 128x128 block, 64x64 warp, 128 thr --
// (round-8 proven config) smem planes @ (p*2+buf)*PLB, p={Ah,Al,Bh,Bl}. 80KB.
__global__ __launch_bounds__(128) void gemm_mma(
    const bf16* __restrict__ Ah, const bf16* __restrict__ Al,
    const bf16* __restrict__ Bh, const bf16* __restrict__ Bl,
    const float* __restrict__ bias, const float* __restrict__ res,
    float* __restrict__ Cf, bf16* __restrict__ Cbh, bf16* __restrict__ Cbl,
    int K, int N, int relu)
{
    extern __shared__ __align__(16) bf16 smr[];
    const int tid = threadIdx.x, lane = tid & 31, wid = tid >> 5;
    const int m0 = blockIdx.y << 7, n0 = blockIdx.x << 7;
    const int wm = (wid & 1) << 6, wn = (wid >> 1) << 6;
    const uint32_t sb = smem_u32(smr);
    const uint32_t sbA = sb, sbAl = sb + 2 * PLB;
    const uint32_t sbB = sb + 4 * PLB, sbBl = sb + 6 * PLB;

    float acc[4][8][4];
    #pragma unroll
    for (int a = 0; a < 4; a++)
        #pragma unroll
        for (int b = 0; b < 8; b++)
            #pragma unroll
            for (int c = 0; c < 4; c++) acc[a][b][c] = 0.f;

    const int nst = K >> 5;

    #pragma unroll 1
    for (int sp = 0; sp <= nst; sp++) {
        if (sp < nst) {
            const int k0 = sp << 5, buf = sp & 1;
            #pragma unroll
            for (int i = 0; i < 8; i++) {
                int idx = tid + (i << 7);
                int pl = idx >> 9, rest = idx & 511;
                int r = rest >> 2, c8 = (rest & 3) << 3;
                uint32_t so = (uint32_t)(r * RS + c8) << 1;
                const bf16* src = (pl ? Al : Ah) + (size_t)(m0 + r) * K + k0 + c8;
                cp16((pl ? sbAl : sbA) + buf * PLB + so, src);
            }
            #pragma unroll
            for (int i = 0; i < 8; i++) {
                int idx = tid + (i << 7);
                int pl = idx >> 9, rest = idx & 511;
                int r = rest >> 2, c8 = (rest & 3) << 3;
                uint32_t so = (uint32_t)(r * RS + c8) << 1;
                const bf16* src = (pl ? Bl : Bh) + (size_t)(n0 + r) * K + k0 + c8;
                cp16((pl ? sbBl : sbB) + buf * PLB + so, src);
            }
            CPCOMMIT();
        }
        if (sp == 0) continue;
        const int s = sp - 1;
        if (sp < nst) { CPWAIT(1); } else { CPWAIT(0); }
        __syncthreads();

        const int buf = s & 1;
        const uint32_t pAh = sbA + buf * PLB, pAl = sbAl + buf * PLB;
        const uint32_t pBh = sbB + buf * PLB, pBl = sbBl + buf * PLB;
        #pragma unroll
        for (int ks = 0; ks < 2; ks++) {
            uint32_t ah[4][4], al[4][4];
            #pragma unroll
            for (int mt = 0; mt < 4; mt++) {
                uint32_t off = (uint32_t)((wm + mt * 16 + (lane & 15)) * RS
                                          + ks * 16 + ((lane >> 4) << 3)) << 1;
                ldm4(ah[mt], pAh + off); ldm4(al[mt], pAl + off);
            }
            #pragma unroll
            for (int nt = 0; nt < 4; nt++) {
                uint32_t bh[4], bl[4];
                uint32_t off = (uint32_t)((wn + nt * 16 + (lane & 7) + ((lane >> 4) << 3)) * RS
                                          + ks * 16 + ((lane >> 3) & 1) * 8) << 1;
                ldm4(bh, pBh + off); ldm4(bl, pBl + off);
                #pragma unroll
                for (int mt = 0; mt < 4; mt++)
                    #pragma unroll
                    for (int t = 0; t < 2; t++) {
                        float* c = acc[mt][nt * 2 + t];
                        mma_b16(c, ah[mt], bh + 2 * t);
                        mma_b16(c, ah[mt], bl + 2 * t);
                        mma_b16(c, al[mt], bh + 2 * t);
                    }
            }
        }
        __syncthreads();
    }

    #pragma unroll
    for (int mt = 0; mt < 4; mt++)
        #pragma unroll
        for (int nt = 0; nt < 8; nt++) {
            int r0 = m0 + wm + mt * 16 + (lane >> 2);
            int c  = n0 + wn + nt * 8 + ((lane & 3) << 1);
            float* a = acc[mt][nt];
            float b0 = bias[c], b1 = bias[c + 1];
            float v0 = a[0] + b0, v1 = a[1] + b1, v2 = a[2] + b0, v3 = a[3] + b1;
            if (res) {
                float2 q0 = *(const float2*)(res + (size_t)r0 * N + c);
                float2 q1 = *(const float2*)(res + (size_t)(r0 + 8) * N + c);
                v0 += q0.x; v1 += q0.y; v2 += q1.x; v3 += q1.y;
            }
            if (relu) {
                v0 = fmaxf(v0, 0.f); v1 = fmaxf(v1, 0.f);
                v2 = fmaxf(v2, 0.f); v3 = fmaxf(v3, 0.f);
            }
            if (Cf) {
                *(float2*)(Cf + (size_t)r0 * N + c)       = make_float2(v0, v1);
                *(float2*)(Cf + (size_t)(r0 + 8) * N + c) = make_float2(v2, v3);
            }
            if (Cbh) {
                uint32_t h0, l0, h1, l1;
                split_pack(v0, v1, h0, l0); split_pack(v2, v3, h1, l1);
                *(uint32_t*)(Cbh + (size_t)r0 * N + c) = h0;
                *(uint32_t*)(Cbl + (size_t)r0 * N + c) = l0;
                *(uint32_t*)(Cbh + (size_t)(r0 + 8) * N + c) = h1;
                *(uint32_t*)(Cbl + (size_t)(r0 + 8) * N + c) = l1;
            }
        }
}

// ---------------- fused HMMA flash attention ----------------
// grid (NN/128, BB*8), 128 thr, 4 warps x 32 q-rows. 64-key stages (16).
// smem: Qh@0, Ql@PLB; KV stages @ sbKV + (buf*4+p)*PLV, p={Kh,Kl,Vh,Vl}.
// total 61440 B, 136 regs -> 3 CTAs/SM (12 warps).
__global__ __launch_bounds__(128) void attn_mma(
    const bf16* __restrict__ qh, const bf16* __restrict__ ql,
    bf16* __restrict__ oh, bf16* __restrict__ ol)
{
    extern __shared__ __align__(16) bf16 smr[];
    const int tid = threadIdx.x, lane = tid & 31, wid = tid >> 5;
    const int bhn = blockIdx.y, b = bhn >> 3, h = bhn & 7;
    const int q0 = blockIdx.x << 7;
    const size_t base = (size_t)b * NN;
    const uint32_t sb = smem_u32(smr);
    const uint32_t sbKV = sb + 2 * PLB;
    const float SC = 0.17677669529663687f;

    // issue Q (1024 chunks) + KV stage 0 (1024 chunks of 64 keys)
    #pragma unroll
    for (int i = 0; i < 8; i++) {
        int idx = tid + (i << 7);
        int pl = idx >> 9, rest = idx & 511;
        int r = rest >> 2, c8 = (rest & 3) << 3;
        uint32_t so = (uint32_t)(r * RS + c8) << 1;
        const bf16* src = (pl ? ql : qh) + (base + q0 + r) * 768 + h * 32 + c8;
        cp16(sb + pl * PLB + so, src);
    }
    #pragma unroll
    for (int i = 0; i < 8; i++) {
        int idx = tid + (i << 7);          // 0..1023
        int pl = idx >> 8, rest = idx & 255;
        int r = rest >> 2, c8 = (rest & 3) << 3;
        uint32_t so = (uint32_t)(r * RS + c8) << 1;
        int fo = (pl >> 1) ? 512 : 256;
        const bf16* src = ((pl & 1) ? ql : qh) + (base + r) * 768 + fo + h * 32 + c8;
        cp16(sbKV + pl * PLV + so, src);
    }
    CPCOMMIT();

    uint32_t qfh[2][2][4], qfl[2][2][4];
    float oacc[2][4][4];
    #pragma unroll
    for (int m = 0; m < 2; m++)
        #pragma unroll
        for (int a = 0; a < 4; a++)
            #pragma unroll
            for (int c = 0; c < 4; c++) oacc[m][a][c] = 0.f;
    float rs[2][2] = {{0.f, 0.f}, {0.f, 0.f}};

    for (int s = 0; s < 16; s++) {
        if (s < 15) {
            const int kv0 = (s + 1) << 6, buf = (s + 1) & 1;
            #pragma unroll
            for (int i = 0; i < 8; i++) {
                int idx = tid + (i << 7);
                int pl = idx >> 8, rest = idx & 255;
                int r = rest >> 2, c8 = (rest & 3) << 3;
                uint32_t so = (uint32_t)(r * RS + c8) << 1;
                int fo = (pl >> 1) ? 512 : 256;
                const bf16* src = ((pl & 1) ? ql : qh) + (base + kv0 + r) * 768 + fo + h * 32 + c8;
                cp16(sbKV + (buf * 4 + pl) * PLV + so, src);
            }
            CPCOMMIT();
            CPWAIT(1);
        } else {
            CPWAIT(0);
        }
        __syncthreads();

        if (s == 0) {
            #pragma unroll
            for (int mt = 0; mt < 2; mt++)
                #pragma unroll
                for (int ks = 0; ks < 2; ks++) {
                    uint32_t off = (uint32_t)((wid * 32 + mt * 16 + (lane & 15)) * RS
                                              + ks * 16 + ((lane >> 4) << 3)) << 1;
                    ldm4(qfh[mt][ks], sb + off);
                    ldm4(qfl[mt][ks], sb + PLB + off);
                }
        }

        const int buf = s & 1;
        const uint32_t kH = sbKV + (buf * 4 + 0) * PLV;
        const uint32_t kL = kH + PLV, vH = kH + 2 * PLV, vL = kH + 3 * PLV;

        #pragma unroll
        for (int kk = 0; kk < 4; kk++) {
            float sv[2][2][4];
            #pragma unroll
            for (int m = 0; m < 2; m++)
                #pragma unroll
                for (int t = 0; t < 2; t++)
                    #pragma unroll
                    for (int c = 0; c < 4; c++) sv[m][t][c] = 0.f;
            #pragma unroll
            for (int ks = 0; ks < 2; ks++) {
                uint32_t bh[4], bl[4];
                uint32_t off = (uint32_t)((kk * 16 + (lane & 7) + ((lane >> 4) << 3)) * RS
                                          + ks * 16 + ((lane >> 3) & 1) * 8) << 1;
                ldm4(bh, kH + off); ldm4(bl, kL + off);
                #pragma unroll
                for (int mt = 0; mt < 2; mt++)
                    #pragma unroll
                    for (int t = 0; t < 2; t++) {
                        float* c = sv[mt][t];
                        mma_b16(c, qfh[mt][ks], bh + 2 * t);
                        mma_b16(c, qfh[mt][ks], bl + 2 * t);
                        mma_b16(c, qfl[mt][ks], bh + 2 * t);
                    }
            }
            uint32_t va[4], vb[4], vc[4], vd[4];
            {
                uint32_t ro = kk * 16 + (lane & 7) + (((lane >> 3) & 1) << 3);
                uint32_t ofa = (uint32_t)(ro * RS + ((lane >> 4) << 3)) << 1;
                uint32_t ofb = (uint32_t)(ro * RS + 16 + ((lane >> 4) << 3)) << 1;
                ldm4t(va, vH + ofa); ldm4t(vb, vH + ofb);
                ldm4t(vc, vL + ofa); ldm4t(vd, vL + ofb);
            }
            #pragma unroll
            for (int mt = 0; mt < 2; mt++) {
                float e00 = __expf(sv[mt][0][0] * SC), e01 = __expf(sv[mt][0][1] * SC);
                float e02 = __expf(sv[mt][0][2] * SC), e03 = __expf(sv[mt][0][3] * SC);
                float e10 = __expf(sv[mt][1][0] * SC), e11 = __expf(sv[mt][1][1] * SC);
                float e12 = __expf(sv[mt][1][2] * SC), e13 = __expf(sv[mt][1][3] * SC);
                rs[mt][0] += e00 + e01 + e10 + e11;
                rs[mt][1] += e02 + e03 + e12 + e13;
                uint32_t pah[4], pal[4];
                split_pack(e00, e01, pah[0], pal[0]);
                split_pack(e02, e03, pah[1], pal[1]);
                split_pack(e10, e11, pah[2], pal[2]);
                split_pack(e12, e13, pah[3], pal[3]);
                float* o = (float*)oacc[mt];
                mma_b16(o + 0,  pah, va);     mma_b16(o + 0,  pah, vc);     mma_b16(o + 0,  pal, va);
                mma_b16(o + 4,  pah, va + 2); mma_b16(o + 4,  pah, vc + 2); mma_b16(o + 4,  pal, va + 2);
                mma_b16(o + 8,  pah, vb);     mma_b16(o + 8,  pah, vd);     mma_b16(o + 8,  pal, vb);
                mma_b16(o + 12, pah, vb + 2); mma_b16(o + 12, pah, vd + 2); mma_b16(o + 12, pal, vb + 2);
            }
        }
        __syncthreads();
    }

    #pragma unroll
    for (int mt = 0; mt < 2; mt++) {
        float r0 = rs[mt][0], r1 = rs[mt][1];
        r0 += __shfl_xor_sync(0xffffffffu, r0, 1);
        r0 += __shfl_xor_sync(0xffffffffu, r0, 2);
        r1 += __shfl_xor_sync(0xffffffffu, r1, 1);
        r1 += __shfl_xor_sync(0xffffffffu, r1, 2);
        const float i0 = 1.f / r0, i1 = 1.f / r1;
        #pragma unroll
        for (int nt = 0; nt < 4; nt++) {
            int row = q0 + wid * 32 + mt * 16 + (lane >> 2);
            int c   = h * 32 + nt * 8 + ((lane & 3) << 1);
            float v0 = oacc[mt][nt][0] * i0, v1 = oacc[mt][nt][1] * i0;
            float v2 = oacc[mt][nt][2] * i1, v3 = oacc[mt][nt][3] * i1;
            uint32_t h0, l0, h1, l1;
            split_pack(v0, v1, h0, l0); split_pack(v2, v3, h1, l1);
            *(uint32_t*)(oh + (base + row) * HH + c) = h0;
            *(uint32_t*)(ol + (base + row) * HH + c) = l0;
            *(uint32_t*)(oh + (base + row + 8) * HH + c) = h1;
            *(uint32_t*)(ol + (base + row + 8) * HH + c) = l1;
        }
    }
}

// ---------------- LayerNorm: fp32 in -> fp32 + bf16 hi/lo ----------------
__global__ __launch_bounds__(256) void ln_kernel(
    const float* __restrict__ x, const float* __restrict__ gam,
    const float* __restrict__ bet, float* __restrict__ out,
    bf16* __restrict__ ohp, bf16* __restrict__ olp)
{
    const int row = blockIdx.x * 8 + (threadIdx.x >> 5);
    const int lane = threadIdx.x & 31;
    const float* xr = x + (size_t)row * HH;
    float v[8], sum = 0.f;
    #pragma unroll
    for (int i = 0; i < 8; i++) { v[i] = xr[lane + i * 32]; sum += v[i]; }
    #pragma unroll
    for (int o = 16; o; o >>= 1) sum += __shfl_xor_sync(0xffffffffu, sum, o);
    const float mean = sum * (1.f / HH);
    float var = 0.f;
    #pragma unroll
    for (int i = 0; i < 8; i++) { float d = v[i] - mean; var += d * d; }
    #pragma unroll
    for (int o = 16; o; o >>= 1) var += __shfl_xor_sync(0xffffffffu, var, o);
    const float inv = rsqrtf(var * (1.f / HH) + 1e-5f);
    #pragma unroll
    for (int i = 0; i < 8; i++) {
        const int c = lane + i * 32;
        float val = (v[i] - mean) * inv * gam[c] + bet[c];
        out[(size_t)row * HH + c] = val;
        bf16 hb = __float2bfloat16(val);
        ohp[(size_t)row * HH + c] = hb;
        olp[(size_t)row * HH + c] = __float2bfloat16(val - __bfloat162float(hb));
    }
}

// ---------------- output init + allocation ----------------
__global__ void init_out_kernel(const int* __restrict__ sel, float* __restrict__ out,
                                int out_size, int both)
{
    const int i = blockIdx.x * 256 + threadIdx.x;
    if (i >= out_size) return;
    if (both && i < BB * KKc) out[i] = (float)sel[i];
    else out[i] = 0.f;
}

__global__ __launch_bounds__(256) void alloc_kernel(
    const float* __restrict__ enc, const int* __restrict__ sel,
    const float* __restrict__ Wc, const float* __restrict__ bc,
    float* __restrict__ bw)
{
    __shared__ float mean_s[HH], ctx_s[HH], sc_s[KKc], red_s[256];
    __shared__ int idx_s[KKc];
    const int b = blockIdx.x, tid = threadIdx.x;
    idx_s[tid] = sel[b * KKc + tid];
    idx_s[tid + 256] = sel[b * KKc + tid + 256];
    __syncthreads();

    float acc = 0.f; int cnt = 0;
    #pragma unroll 4
    for (int k = 0; k < KKc; k++) {
        const int idx = idx_s[k];
        if (idx < NN) { acc += enc[((size_t)b * NN + idx) * HH + tid]; cnt++; }
    }
    mean_s[tid] = acc / (float)(cnt > 0 ? cnt : 1);
    __syncthreads();

    float c = bc[tid];
    #pragma unroll 4
    for (int i = 0; i < HH; i++) c += mean_s[i] * Wc[i * HH + tid];
    ctx_s[tid] = c;
    __syncthreads();

    const int wid = tid >> 5, lane = tid & 31;
    for (int k = wid; k < KKc; k += 8) {
        const int idx = idx_s[k];
        float s = -1e30f;
        if (idx < NN) {
            const float* row = enc + ((size_t)b * NN + idx) * HH;
            float part = 0.f;
            #pragma unroll
            for (int i = 0; i < 8; i++) part += ctx_s[lane + i * 32] * row[lane + i * 32];
            #pragma unroll
            for (int o = 16; o; o >>= 1) part += __shfl_xor_sync(0xffffffffu, part, o);
            s = part;
        }
        if (lane == 0) sc_s[k] = s;
    }
    __syncthreads();

    red_s[tid] = fmaxf(sc_s[tid], sc_s[tid + 256]);
    __syncthreads();
    for (int st = 128; st; st >>= 1) {
        if (tid < st) red_s[tid] = fmaxf(red_s[tid], red_s[tid + st]);
        __syncthreads();
    }
    const float m = red_s[0];
    __syncthreads();

    const int i0 = idx_s[tid], i1 = idx_s[tid + 256];
    const float e0 = (i0 < NN) ? expf(sc_s[tid] - m) : 0.f;
    const float e1 = (i1 < NN) ? expf(sc_s[tid + 256] - m) : 0.f;
    red_s[tid] = e0 + e1;
    __syncthreads();
    for (int st = 128; st; st >>= 1) {
        if (tid < st) red_s[tid] += red_s[tid + st];
        __syncthreads();
    }
    const float denom = red_s[0];
    __syncthreads();

    float a0 = rintf(e0 / denom * 100.f);
    float a1 = rintf(e1 / denom * 100.f);
    red_s[tid] = a0 + a1;
    __syncthreads();
    for (int st = 128; st; st >>= 1) {
        if (tid < st) red_s[tid] += red_s[tid + st];
        __syncthreads();
    }
    const float diff = 100.f - red_s[0];
    __syncthreads();

    if (tid == 0 && i0 < NN) a0 += diff;
    if (i0 < NN) bw[b * NN + i0] = a0;
    if (i1 < NN) bw[b * NN + i1] = a1;
}

// ---------------- launch ----------------
extern "C" void kernel_launch(void* const* d_in, const int* in_sizes, int n_in,
                              void* d_out, int out_size)
{
    const float* x    = (const float*)d_in[0];
    const int*   sel  = (const int*)  d_in[1];
    const float* W_in = (const float*)d_in[2];
    const float* b_in = (const float*)d_in[3];
    const float* Wqkv = (const float*)d_in[4];
    const float* bqkv = (const float*)d_in[5];
    const float* Wo   = (const float*)d_in[6];
    const float* bo   = (const float*)d_in[7];
    const float* ln1g = (const float*)d_in[8];
    const float* ln1b = (const float*)d_in[9];
    const float* W1   = (const float*)d_in[10];
    const float* b1   = (const float*)d_in[11];
    const float* W2   = (const float*)d_in[12];
    const float* b2   = (const float*)d_in[13];
    const float* ln2g = (const float*)d_in[14];
    const float* ln2b = (const float*)d_in[15];
    const float* Wc   = (const float*)d_in[16];
    const float* bc   = (const float*)d_in[17];

    float *h, *tmp;
    bf16 *xh, *xl, *hbh, *hbl, *qh, *ql, *ah, *al, *fh, *fl, *wh, *wl;
    cudaGetSymbolAddress((void**)&h,   g_h);   cudaGetSymbolAddress((void**)&tmp, g_tmp);
    cudaGetSymbolAddress((void**)&xh,  g_xh);  cudaGetSymbolAddress((void**)&xl,  g_xl);
    cudaGetSymbolAddress((void**)&hbh, g_hbh); cudaGetSymbolAddress((void**)&hbl, g_hbl);
    cudaGetSymbolAddress((void**)&qh,  g_qh);  cudaGetSymbolAddress((void**)&ql,  g_ql);
    cudaGetSymbolAddress((void**)&ah,  g_ah);  cudaGetSymbolAddress((void**)&al,  g_al);
    cudaGetSymbolAddress((void**)&fh,  g_fh);  cudaGetSymbolAddress((void**)&fl,  g_fl);
    cudaGetSymbolAddress((void**)&wh,  g_wh);  cudaGetSymbolAddress((void**)&wl,  g_wl);

    const int GSM = 8 * PLB;              // 81920
    const int ASM_ = 2 * PLB + 8 * PLV;   // 61440 -> 3 CTAs/SM
    cudaFuncSetAttribute(gemm_mma, cudaFuncAttributeMaxDynamicSharedMemorySize, GSM);
    cudaFuncSetAttribute(attn_mma, cudaFuncAttributeMaxDynamicSharedMemorySize, ASM_);

    Segs S;
    S.seg[0] = { x, xh, xl, 0, 0, 1, (TOK * DIN) / 1024 };
    S.seg[1] = { W_in, wh + WOFF_IN, wl + WOFF_IN, DIN, HH, 0, (DIN/32)*(HH/32) };
    for (int l = 0; l < LL; l++) {
        S.seg[2+l] = { Wqkv + (size_t)l*HH*3*HH, wh + WOFF_QKV + l*HH*3*HH,
                       wl + WOFF_QKV + l*HH*3*HH, HH, 3*HH, 0, (HH/32)*(3*HH/32) };
        S.seg[4+l] = { Wo + (size_t)l*HH*HH, wh + WOFF_O + l*HH*HH,
                       wl + WOFF_O + l*HH*HH, HH, HH, 0, (HH/32)*(HH/32) };
        S.seg[6+l] = { W1 + (size_t)l*HH*FF, wh + WOFF_1 + l*HH*FF,
                       wl + WOFF_1 + l*HH*FF, HH, FF, 0, (HH/32)*(FF/32) };
        S.seg[8+l] = { W2 + (size_t)l*FF*HH, wh + WOFF_2 + l*FF*HH,
                       wl + WOFF_2 + l*FF*HH, FF, HH, 0, (FF/32)*(HH/32) };
    }
    prep_kernel<<<dim3(1024, 10), dim3(32, 8)>>>(S);

    gemm_mma<<<dim3(HH/128, TOK/128), 128, GSM>>>(
        xh, xl, wh + WOFF_IN, wl + WOFF_IN, b_in, nullptr, h, hbh, hbl, DIN, HH, 0);

    for (int l = 0; l < LL; l++) {
        gemm_mma<<<dim3(3*HH/128, TOK/128), 128, GSM>>>(
            hbh, hbl, wh + WOFF_QKV + l*HH*3*HH, wl + WOFF_QKV + l*HH*3*HH,
            bqkv + l*3*HH, nullptr, nullptr, qh, ql, HH, 3*HH, 0);
        attn_mma<<<dim3(NN/128, BB*8), 128, ASM_>>>(qh, ql, ah, al);
        gemm_mma<<<dim3(HH/128, TOK/128), 128, GSM>>>(
            ah, al, wh + WOFF_O + l*HH*HH, wl + WOFF_O + l*HH*HH,
            bo + l*HH, h, tmp, nullptr, nullptr, HH, HH, 0);
        ln_kernel<<<TOK/8, 256>>>(tmp, ln1g + l*HH, ln1b + l*HH, h, hbh, hbl);
        gemm_mma<<<dim3(FF/128, TOK/128), 128, GSM>>>(
            hbh, hbl, wh + WOFF_1 + l*HH*FF, wl + WOFF_1 + l*HH*FF,
            b1 + l*FF, nullptr, nullptr, fh, fl, HH, FF, 1);
        gemm_mma<<<dim3(HH/128, TOK/128), 128, GSM>>>(
            fh, fl, wh + WOFF_2 + l*FF*HH, wl + WOFF_2 + l*FF*HH,
            b2 + l*HH, h, tmp, nullptr, nullptr, FF, HH, 0);
        ln_kernel<<<TOK/8, 256>>>(tmp, ln2g + l*HH, ln2b + l*HH, h, hbh, hbl);
    }

    float* outf = (float*)d_out;
    const int idx_elems = BB * KKc, bw_elems = BB * NN;
    const int both = (out_size >= idx_elems + bw_elems) ? 1 : 0;
    float* bw = both ? (outf + idx_elems) : outf;
    init_out_kernel<<<(out_size + 255) / 256, 256>>>(sel, outf, out_size, both);
    alloc_kernel<<<BB, 256>>>(h, sel, Wc, bc, bw);
}

// round 10
// speedup vs baseline: 3.4606x; 1.0172x over previous
#include <cuda_runtime.h>
#include <cuda_bf16.h>
#include <cstdint>

#define BB 16
#define NN 1024
#define KKc 512
#define DIN 64
#define HH 256
#define FF 1024
#define LL 2
#define TOK (BB*NN)

typedef __nv_bfloat16 bf16;

#define WOFF_IN 0
#define WOFF_QKV (WOFF_IN + DIN*HH)
#define WOFF_O (WOFF_QKV + LL*HH*3*HH)
#define WOFF_1 (WOFF_O + LL*HH*HH)
#define WOFF_2 (WOFF_1 + LL*HH*FF)
#define WTOT (WOFF_2 + LL*FF*HH)

__device__ __align__(16) float g_h[TOK*HH], g_tmp[TOK*HH];
__device__ __align__(16) bf16 g_xh[TOK*DIN], g_xl[TOK*DIN];
__device__ __align__(16) bf16 g_hbh[TOK*HH], g_hbl[TOK*HH];
__device__ __align__(16) bf16 g_qh[TOK*768], g_ql[TOK*768];
__device__ __align__(16) bf16 g_ah[TOK*HH], g_al[TOK*HH];
__device__ __align__(16) bf16 g_fh[TOK*FF], g_fl[TOK*FF];
__device__ __align__(16) bf16 g_wh[WTOT], g_wl[WTOT];

// ---------------- helpers ----------------
__device__ __forceinline__ uint32_t smem_u32(const void* p) {
    uint32_t a;
    asm("{ .reg .u64 t; cvta.to.shared.u64 t, %1; cvt.u32.u64 %0, t; }" : "=r"(a) : "l"(p));
    return a;
}
__device__ __forceinline__ void cp16(uint32_t d, const void* s) {
    asm volatile("cp.async.cg.shared.global [%0], [%1], 16;" :: "r"(d), "l"(s));
}
#define CPCOMMIT() asm volatile("cp.async.commit_group;" ::: "memory")
#define CPWAIT(n)  asm volatile("cp.async.wait_group %0;" :: "n"(n) : "memory")

__device__ __forceinline__ void ldm4(uint32_t* r, uint32_t a) {
    asm volatile("ldmatrix.sync.aligned.m8n8.x4.shared.b16 {%0,%1,%2,%3}, [%4];"
                 : "=r"(r[0]), "=r"(r[1]), "=r"(r[2]), "=r"(r[3]) : "r"(a));
}
__device__ __forceinline__ void ldm4t(uint32_t* r, uint32_t a) {
    asm volatile("ldmatrix.sync.aligned.m8n8.x4.trans.shared.b16 {%0,%1,%2,%3}, [%4];"
                 : "=r"(r[0]), "=r"(r[1]), "=r"(r[2]), "=r"(r[3]) : "r"(a));
}
__device__ __forceinline__ void mma_b16(float* c, const uint32_t* a, const uint32_t* b) {
    asm volatile("mma.sync.aligned.m16n8k16.row.col.f32.bf16.bf16.f32 "
                 "{%0,%1,%2,%3},{%4,%5,%6,%7},{%8,%9},{%0,%1,%2,%3};"
                 : "+f"(c[0]), "+f"(c[1]), "+f"(c[2]), "+f"(c[3])
                 : "r"(a[0]), "r"(a[1]), "r"(a[2]), "r"(a[3]), "r"(b[0]), "r"(b[1]));
}
__device__ __forceinline__ uint32_t bf2(float lo, float hi) {
    uint32_t r;
    asm("cvt.rn.bf16x2.f32 %0, %1, %2;" : "=r"(r) : "f"(hi), "f"(lo));
    return r;
}
__device__ __forceinline__ void split_pack(float a, float b, uint32_t& hi, uint32_t& lo) {
    float ah = __bfloat162float(__float2bfloat16(a));
    float bh = __bfloat162float(__float2bfloat16(b));
    hi = bf2(ah, bh); lo = bf2(a - ah, b - bh);
}

#define RS 40        // smem row stride (bf16): 80B, conflict-free ldmatrix
#define PLB 10240    // 128-row plane bytes (128*RS*2)
#define PLV 5120     // 64-row plane bytes (64*RS*2)

// ---------------- prep: weight transpose/split + x split ----------------
struct Seg { const float* s; bf16 *dh, *dl; int K, N, mode, ntiles; };
struct Segs { Seg seg[10]; };

__global__ void prep_kernel(Segs S) {
    Seg sg = S.seg[blockIdx.y];
    if ((int)blockIdx.x >= sg.ntiles) return;
    const int tx = threadIdx.x, ty = threadIdx.y;
    if (sg.mode == 1) {
        int off = blockIdx.x * 1024 + ty * 128 + tx * 4;
        float4 v = *(const float4*)(sg.s + off);
        float a[4] = {v.x, v.y, v.z, v.w};
        #pragma unroll
        for (int i = 0; i < 4; i++) {
            bf16 h = __float2bfloat16(a[i]);
            sg.dh[off + i] = h;
            sg.dl[off + i] = __float2bfloat16(a[i] - __bfloat162float(h));
        }
    } else {
        __shared__ float tile[32][33];
        int kt = blockIdx.x % (sg.K / 32), nt = blockIdx.x / (sg.K / 32);
        int k0 = kt * 32, n0 = nt * 32;
        #pragma unroll
        for (int i = 0; i < 4; i++)
            tile[ty * 4 + i][tx] = sg.s[(size_t)(k0 + ty * 4 + i) * sg.N + n0 + tx];
        __syncthreads();
        #pragma unroll
        for (int i = 0; i < 4; i++) {
            float v = tile[tx][ty * 4 + i];
            bf16 h = __float2bfloat16(v);
            size_t d = (size_t)(n0 + ty * 4 + i) * sg.K + k0 + tx;
            sg.dh[d] = h;
            sg.dl[d] = __float2bfloat16(v - __bfloat162float(h));
        }
    }
}

// ---------------- split-bf16 HMMA GEMM, 128x128 block, 64x64 warp, 128 thr --
// (round-8 proven config) smem planes @ (p*2+buf)*PLB, p={Ah,Al,Bh,Bl}. 80KB.
__global__ __launch_bounds__(128) void gemm_mma(
    const bf16* __restrict__ Ah, const bf16* __restrict__ Al,
    const bf16* __restrict__ Bh, const bf16* __restrict__ Bl,
    const float* __restrict__ bias, const float* __restrict__ res,
    float* __restrict__ Cf, bf16* __restrict__ Cbh, bf16* __restrict__ Cbl,
    int K, int N, int relu)
{
    extern __shared__ __align__(16) bf16 smr[];
    const int tid = threadIdx.x, lane = tid & 31, wid = tid >> 5;
    const int m0 = blockIdx.y << 7, n0 = blockIdx.x << 7;
    const int wm = (wid & 1) << 6, wn = (wid >> 1) << 6;
    const uint32_t sb = smem_u32(smr);
    const uint32_t sbA = sb, sbAl = sb + 2 * PLB;
    const uint32_t sbB = sb + 4 * PLB, sbBl = sb + 6 * PLB;

    float acc[4][8][4];
    #pragma unroll
    for (int a = 0; a < 4; a++)
        #pragma unroll
        for (int b = 0; b < 8; b++)
            #pragma unroll
            for (int c = 0; c < 4; c++) acc[a][b][c] = 0.f;

    const int nst = K >> 5;

    #pragma unroll 1
    for (int sp = 0; sp <= nst; sp++) {
        if (sp < nst) {
            const int k0 = sp << 5, buf = sp & 1;
            #pragma unroll
            for (int i = 0; i < 8; i++) {
                int idx = tid + (i << 7);
                int pl = idx >> 9, rest = idx & 511;
                int r = rest >> 2, c8 = (rest & 3) << 3;
                uint32_t so = (uint32_t)(r * RS + c8) << 1;
                const bf16* src = (pl ? Al : Ah) + (size_t)(m0 + r) * K + k0 + c8;
                cp16((pl ? sbAl : sbA) + buf * PLB + so, src);
            }
            #pragma unroll
            for (int i = 0; i < 8; i++) {
                int idx = tid + (i << 7);
                int pl = idx >> 9, rest = idx & 511;
                int r = rest >> 2, c8 = (rest & 3) << 3;
                uint32_t so = (uint32_t)(r * RS + c8) << 1;
                const bf16* src = (pl ? Bl : Bh) + (size_t)(n0 + r) * K + k0 + c8;
                cp16((pl ? sbBl : sbB) + buf * PLB + so, src);
            }
            CPCOMMIT();
        }
        if (sp == 0) continue;
        const int s = sp - 1;
        if (sp < nst) { CPWAIT(1); } else { CPWAIT(0); }
        __syncthreads();

        const int buf = s & 1;
        const uint32_t pAh = sbA + buf * PLB, pAl = sbAl + buf * PLB;
        const uint32_t pBh = sbB + buf * PLB, pBl = sbBl + buf * PLB;
        #pragma unroll
        for (int ks = 0; ks < 2; ks++) {
            uint32_t ah[4][4], al[4][4];
            #pragma unroll
            for (int mt = 0; mt < 4; mt++) {
                uint32_t off = (uint32_t)((wm + mt * 16 + (lane & 15)) * RS
                                          + ks * 16 + ((lane >> 4) << 3)) << 1;
                ldm4(ah[mt], pAh + off); ldm4(al[mt], pAl + off);
            }
            #pragma unroll
            for (int nt = 0; nt < 4; nt++) {
                uint32_t bh[4], bl[4];
                uint32_t off = (uint32_t)((wn + nt * 16 + (lane & 7) + ((lane >> 4) << 3)) * RS
                                          + ks * 16 + ((lane >> 3) & 1) * 8) << 1;
                ldm4(bh, pBh + off); ldm4(bl, pBl + off);
                #pragma unroll
                for (int mt = 0; mt < 4; mt++)
                    #pragma unroll
                    for (int t = 0; t < 2; t++) {
                        float* c = acc[mt][nt * 2 + t];
                        mma_b16(c, ah[mt], bh + 2 * t);
                        mma_b16(c, ah[mt], bl + 2 * t);
                        mma_b16(c, al[mt], bh + 2 * t);
                    }
            }
        }
        __syncthreads();
    }

    #pragma unroll
    for (int mt = 0; mt < 4; mt++)
        #pragma unroll
        for (int nt = 0; nt < 8; nt++) {
            int r0 = m0 + wm + mt * 16 + (lane >> 2);
            int c  = n0 + wn + nt * 8 + ((lane & 3) << 1);
            float* a = acc[mt][nt];
            float b0 = bias[c], b1 = bias[c + 1];
            float v0 = a[0] + b0, v1 = a[1] + b1, v2 = a[2] + b0, v3 = a[3] + b1;
            if (res) {
                float2 q0 = *(const float2*)(res + (size_t)r0 * N + c);
                float2 q1 = *(const float2*)(res + (size_t)(r0 + 8) * N + c);
                v0 += q0.x; v1 += q0.y; v2 += q1.x; v3 += q1.y;
            }
            if (relu) {
                v0 = fmaxf(v0, 0.f); v1 = fmaxf(v1, 0.f);
                v2 = fmaxf(v2, 0.f); v3 = fmaxf(v3, 0.f);
            }
            if (Cf) {
                *(float2*)(Cf + (size_t)r0 * N + c)       = make_float2(v0, v1);
                *(float2*)(Cf + (size_t)(r0 + 8) * N + c) = make_float2(v2, v3);
            }
            if (Cbh) {
                uint32_t h0, l0, h1, l1;
                split_pack(v0, v1, h0, l0); split_pack(v2, v3, h1, l1);
                *(uint32_t*)(Cbh + (size_t)r0 * N + c) = h0;
                *(uint32_t*)(Cbl + (size_t)r0 * N + c) = l0;
                *(uint32_t*)(Cbh + (size_t)(r0 + 8) * N + c) = h1;
                *(uint32_t*)(Cbl + (size_t)(r0 + 8) * N + c) = l1;
            }
        }
}

// ---------------- fused HMMA flash attention ----------------
// grid (NN/128, BB*8), 128 thr, 4 warps x 32 q-rows. 64-key stages (16).
// smem layout (40960 B total -> 4 CTAs/SM with reg cap 128):
//   [0, 4*PLV)        : Q planes during prologue; KV buf1 during mainloop
//   [4*PLV, 8*PLV)    : KV buf0
// Q is consumed into registers before buf1 overwrites it.
__global__ __launch_bounds__(128, 4) void attn_mma(
    const bf16* __restrict__ qh, const bf16* __restrict__ ql,
    bf16* __restrict__ oh, bf16* __restrict__ ol)
{
    extern __shared__ __align__(16) bf16 smr[];
    const int tid = threadIdx.x, lane = tid & 31, wid = tid >> 5;
    const int bhn = blockIdx.y, b = bhn >> 3, h = bhn & 7;
    const int q0 = blockIdx.x << 7;
    const size_t base = (size_t)b * NN;
    const uint32_t sb = smem_u32(smr);
    const float SC = 0.17677669529663687f;
    // KV buffer base for buf: buf0 @ sb+4*PLV, buf1 @ sb+0
    // Q planes: Qh @ sb, Ql @ sb + 2*PLV (2*PLV = 10240 = PLB, rows 0..127 ok
    // since Q tile is 128 rows x 32 cols => 128*RS*2 = 10240 bytes = 2*PLV)

    // issue Q (1024 chunks) into [0, 2*PLB=4*PLV) and KV stage 0 into buf0
    #pragma unroll
    for (int i = 0; i < 8; i++) {
        int idx = tid + (i << 7);
        int pl = idx >> 9, rest = idx & 511;
        int r = rest >> 2, c8 = (rest & 3) << 3;
        uint32_t so = (uint32_t)(r * RS + c8) << 1;
        const bf16* src = (pl ? ql : qh) + (base + q0 + r) * 768 + h * 32 + c8;
        cp16(sb + pl * (2 * PLV) + so, src);
    }
    #pragma unroll
    for (int i = 0; i < 8; i++) {
        int idx = tid + (i << 7);          // 0..1023
        int pl = idx >> 8, rest = idx & 255;
        int r = rest >> 2, c8 = (rest & 3) << 3;
        uint32_t so = (uint32_t)(r * RS + c8) << 1;
        int fo = (pl >> 1) ? 512 : 256;
        const bf16* src = ((pl & 1) ? ql : qh) + (base + r) * 768 + fo + h * 32 + c8;
        cp16(sb + 4 * PLV + pl * PLV + so, src);
    }
    CPCOMMIT();

    uint32_t qfh[2][2][4], qfl[2][2][4];
    float oacc[2][4][4];
    #pragma unroll
    for (int m = 0; m < 2; m++)
        #pragma unroll
        for (int a = 0; a < 4; a++)
            #pragma unroll
            for (int c = 0; c < 4; c++) oacc[m][a][c] = 0.f;
    float rs[2][2] = {{0.f, 0.f}, {0.f, 0.f}};

    // consume Q into registers, then free its smem for KV buf1
    CPWAIT(0);
    __syncthreads();
    #pragma unroll
    for (int mt = 0; mt < 2; mt++)
        #pragma unroll
        for (int ks = 0; ks < 2; ks++) {
            uint32_t off = (uint32_t)((wid * 32 + mt * 16 + (lane & 15)) * RS
                                      + ks * 16 + ((lane >> 4) << 3)) << 1;
            ldm4(qfh[mt][ks], sb + off);
            ldm4(qfl[mt][ks], sb + 2 * PLV + off);
        }
    __syncthreads();   // all Q frag reads done before buf1 overwrites

    for (int s = 0; s < 16; s++) {
        if (s < 15) {
            const int kv0 = (s + 1) << 6;
            const uint32_t dstb = ((s + 1) & 1) ? sb : sb + 4 * PLV;
            #pragma unroll
            for (int i = 0; i < 8; i++) {
                int idx = tid + (i << 7);
                int pl = idx >> 8, rest = idx & 255;
                int r = rest >> 2, c8 = (rest & 3) << 3;
                uint32_t so = (uint32_t)(r * RS + c8) << 1;
                int fo = (pl >> 1) ? 512 : 256;
                const bf16* src = ((pl & 1) ? ql : qh) + (base + kv0 + r) * 768 + fo + h * 32 + c8;
                cp16(dstb + pl * PLV + so, src);
            }
            CPCOMMIT();
            CPWAIT(1);
        } else {
            CPWAIT(0);
        }
        __syncthreads();

        const uint32_t kH = (s & 1) ? sb : sb + 4 * PLV;
        const uint32_t kL = kH + PLV, vH = kH + 2 * PLV, vL = kH + 3 * PLV;

        #pragma unroll
        for (int kk = 0; kk < 4; kk++) {
            float sv[2][2][4];
            #pragma unroll
            for (int m = 0; m < 2; m++)
                #pragma unroll
                for (int t = 0; t < 2; t++)
                    #pragma unroll
                    for (int c = 0; c < 4; c++) sv[m][t][c] = 0.f;
            #pragma unroll
            for (int ks = 0; ks < 2; ks++) {
                uint32_t bh[4], bl[4];
                uint32_t off = (uint32_t)((kk * 16 + (lane & 7) + ((lane >> 4) << 3)) * RS
                                          + ks * 16 + ((lane >> 3) & 1) * 8) << 1;
                ldm4(bh, kH + off); ldm4(bl, kL + off);
                #pragma unroll
                for (int mt = 0; mt < 2; mt++)
                    #pragma unroll
                    for (int t = 0; t < 2; t++) {
                        float* c = sv[mt][t];
                        mma_b16(c, qfh[mt][ks], bh + 2 * t);
                        mma_b16(c, qfh[mt][ks], bl + 2 * t);
                        mma_b16(c, qfl[mt][ks], bh + 2 * t);
                    }
            }
            uint32_t va[4], vb[4], vc[4], vd[4];
            {
                uint32_t ro = kk * 16 + (lane & 7) + (((lane >> 3) & 1) << 3);
                uint32_t ofa = (uint32_t)(ro * RS + ((lane >> 4) << 3)) << 1;
                uint32_t ofb = (uint32_t)(ro * RS + 16 + ((lane >> 4) << 3)) << 1;
                ldm4t(va, vH + ofa); ldm4t(vb, vH + ofb);
                ldm4t(vc, vL + ofa); ldm4t(vd, vL + ofb);
            }
            #pragma unroll
            for (int mt = 0; mt < 2; mt++) {
                float e00 = __expf(sv[mt][0][0] * SC), e01 = __expf(sv[mt][0][1] * SC);
                float e02 = __expf(sv[mt][0][2] * SC), e03 = __expf(sv[mt][0][3] * SC);
                float e10 = __expf(sv[mt][1][0] * SC), e11 = __expf(sv[mt][1][1] * SC);
                float e12 = __expf(sv[mt][1][2] * SC), e13 = __expf(sv[mt][1][3] * SC);
                rs[mt][0] += e00 + e01 + e10 + e11;
                rs[mt][1] += e02 + e03 + e12 + e13;
                uint32_t pah[4], pal[4];
                split_pack(e00, e01, pah[0], pal[0]);
                split_pack(e02, e03, pah[1], pal[1]);
                split_pack(e10, e11, pah[2], pal[2]);
                split_pack(e12, e13, pah[3], pal[3]);
                float* o = (float*)oacc[mt];
                mma_b16(o + 0,  pah, va);     mma_b16(o + 0,  pah, vc);     mma_b16(o + 0,  pal, va);
                mma_b16(o + 4,  pah, va + 2); mma_b16(o + 4,  pah, vc + 2); mma_b16(o + 4,  pal, va + 2);
                mma_b16(o + 8,  pah, vb);     mma_b16(o + 8,  pah, vd);     mma_b16(o + 8,  pal, vb);
                mma_b16(o + 12, pah, vb + 2); mma_b16(o + 12, pah, vd + 2); mma_b16(o + 12, pal, vb + 2);
            }
        }
        __syncthreads();
    }

    #pragma unroll
    for (int mt = 0; mt < 2; mt++) {
        float r0 = rs[mt][0], r1 = rs[mt][1];
        r0 += __shfl_xor_sync(0xffffffffu, r0, 1);
        r0 += __shfl_xor_sync(0xffffffffu, r0, 2);
        r1 += __shfl_xor_sync(0xffffffffu, r1, 1);
        r1 += __shfl_xor_sync(0xffffffffu, r1, 2);
        const float i0 = 1.f / r0, i1 = 1.f / r1;
        #pragma unroll
        for (int nt = 0; nt < 4; nt++) {
            int row = q0 + wid * 32 + mt * 16 + (lane >> 2);
            int c   = h * 32 + nt * 8 + ((lane & 3) << 1);
            float v0 = oacc[mt][nt][0] * i0, v1 = oacc[mt][nt][1] * i0;
            float v2 = oacc[mt][nt][2] * i1, v3 = oacc[mt][nt][3] * i1;
            uint32_t h0, l0, h1, l1;
            split_pack(v0, v1, h0, l0); split_pack(v2, v3, h1, l1);
            *(uint32_t*)(oh + (base + row) * HH + c) = h0;
            *(uint32_t*)(ol + (base + row) * HH + c) = l0;
            *(uint32_t*)(oh + (base + row + 8) * HH + c) = h1;
            *(uint32_t*)(ol + (base + row + 8) * HH + c) = l1;
        }
    }
}

// ---------------- LayerNorm: fp32 in -> fp32 + bf16 hi/lo ----------------
__global__ __launch_bounds__(256) void ln_kernel(
    const float* __restrict__ x, const float* __restrict__ gam,
    const float* __restrict__ bet, float* __restrict__ out,
    bf16* __restrict__ ohp, bf16* __restrict__ olp)
{
    const int row = blockIdx.x * 8 + (threadIdx.x >> 5);
    const int lane = threadIdx.x & 31;
    const float* xr = x + (size_t)row * HH;
    float v[8], sum = 0.f;
    #pragma unroll
    for (int i = 0; i < 8; i++) { v[i] = xr[lane + i * 32]; sum += v[i]; }
    #pragma unroll
    for (int o = 16; o; o >>= 1) sum += __shfl_xor_sync(0xffffffffu, sum, o);
    const float mean = sum * (1.f / HH);
    float var = 0.f;
    #pragma unroll
    for (int i = 0; i < 8; i++) { float d = v[i] - mean; var += d * d; }
    #pragma unroll
    for (int o = 16; o; o >>= 1) var += __shfl_xor_sync(0xffffffffu, var, o);
    const float inv = rsqrtf(var * (1.f / HH) + 1e-5f);
    #pragma unroll
    for (int i = 0; i < 8; i++) {
        const int c = lane + i * 32;
        float val = (v[i] - mean) * inv * gam[c] + bet[c];
        out[(size_t)row * HH + c] = val;
        bf16 hb = __float2bfloat16(val);
        ohp[(size_t)row * HH + c] = hb;
        olp[(size_t)row * HH + c] = __float2bfloat16(val - __bfloat162float(hb));
    }
}

// ---------------- output init + allocation ----------------
__global__ void init_out_kernel(const int* __restrict__ sel, float* __restrict__ out,
                                int out_size, int both)
{
    const int i = blockIdx.x * 256 + threadIdx.x;
    if (i >= out_size) return;
    if (both && i < BB * KKc) out[i] = (float)sel[i];
    else out[i] = 0.f;
}

__global__ __launch_bounds__(256) void alloc_kernel(
    const float* __restrict__ enc, const int* __restrict__ sel,
    const float* __restrict__ Wc, const float* __restrict__ bc,
    float* __restrict__ bw)
{
    __shared__ float mean_s[HH], ctx_s[HH], sc_s[KKc], red_s[256];
    __shared__ int idx_s[KKc];
    const int b = blockIdx.x, tid = threadIdx.x;
    idx_s[tid] = sel[b * KKc + tid];
    idx_s[tid + 256] = sel[b * KKc + tid + 256];
    __syncthreads();

    float acc = 0.f; int cnt = 0;
    #pragma unroll 4
    for (int k = 0; k < KKc; k++) {
        const int idx = idx_s[k];
        if (idx < NN) { acc += enc[((size_t)b * NN + idx) * HH + tid]; cnt++; }
    }
    mean_s[tid] = acc / (float)(cnt > 0 ? cnt : 1);
    __syncthreads();

    float c = bc[tid];
    #pragma unroll 4
    for (int i = 0; i < HH; i++) c += mean_s[i] * Wc[i * HH + tid];
    ctx_s[tid] = c;
    __syncthreads();

    const int wid = tid >> 5, lane = tid & 31;
    for (int k = wid; k < KKc; k += 8) {
        const int idx = idx_s[k];
        float s = -1e30f;
        if (idx < NN) {
            const float* row = enc + ((size_t)b * NN + idx) * HH;
            float part = 0.f;
            #pragma unroll
            for (int i = 0; i < 8; i++) part += ctx_s[lane + i * 32] * row[lane + i * 32];
            #pragma unroll
            for (int o = 16; o; o >>= 1) part += __shfl_xor_sync(0xffffffffu, part, o);
            s = part;
        }
        if (lane == 0) sc_s[k] = s;
    }
    __syncthreads();

    red_s[tid] = fmaxf(sc_s[tid], sc_s[tid + 256]);
    __syncthreads();
    for (int st = 128; st; st >>= 1) {
        if (tid < st) red_s[tid] = fmaxf(red_s[tid], red_s[tid + st]);
        __syncthreads();
    }
    const float m = red_s[0];
    __syncthreads();

    const int i0 = idx_s[tid], i1 = idx_s[tid + 256];
    const float e0 = (i0 < NN) ? expf(sc_s[tid] - m) : 0.f;
    const float e1 = (i1 < NN) ? expf(sc_s[tid + 256] - m) : 0.f;
    red_s[tid] = e0 + e1;
    __syncthreads();
    for (int st = 128; st; st >>= 1) {
        if (tid < st) red_s[tid] += red_s[tid + st];
        __syncthreads();
    }
    const float denom = red_s[0];
    __syncthreads();

    float a0 = rintf(e0 / denom * 100.f);
    float a1 = rintf(e1 / denom * 100.f);
    red_s[tid] = a0 + a1;
    __syncthreads();
    for (int st = 128; st; st >>= 1) {
        if (tid < st) red_s[tid] += red_s[tid + st];
        __syncthreads();
    }
    const float diff = 100.f - red_s[0];
    __syncthreads();

    if (tid == 0 && i0 < NN) a0 += diff;
    if (i0 < NN) bw[b * NN + i0] = a0;
    if (i1 < NN) bw[b * NN + i1] = a1;
}

// ---------------- launch ----------------
extern "C" void kernel_launch(void* const* d_in, const int* in_sizes, int n_in,
                              void* d_out, int out_size)
{
    const float* x    = (const float*)d_in[0];
    const int*   sel  = (const int*)  d_in[1];
    const float* W_in = (const float*)d_in[2];
    const float* b_in = (const float*)d_in[3];
    const float* Wqkv = (const float*)d_in[4];
    const float* bqkv = (const float*)d_in[5];
    const float* Wo   = (const float*)d_in[6];
    const float* bo   = (const float*)d_in[7];
    const float* ln1g = (const float*)d_in[8];
    const float* ln1b = (const float*)d_in[9];
    const float* W1   = (const float*)d_in[10];
    const float* b1   = (const float*)d_in[11];
    const float* W2   = (const float*)d_in[12];
    const float* b2   = (const float*)d_in[13];
    const float* ln2g = (const float*)d_in[14];
    const float* ln2b = (const float*)d_in[15];
    const float* Wc   = (const float*)d_in[16];
    const float* bc   = (const float*)d_in[17];

    float *h, *tmp;
    bf16 *xh, *xl, *hbh, *hbl, *qh, *ql, *ah, *al, *fh, *fl, *wh, *wl;
    cudaGetSymbolAddress((void**)&h,   g_h);   cudaGetSymbolAddress((void**)&tmp, g_tmp);
    cudaGetSymbolAddress((void**)&xh,  g_xh);  cudaGetSymbolAddress((void**)&xl,  g_xl);
    cudaGetSymbolAddress((void**)&hbh, g_hbh); cudaGetSymbolAddress((void**)&hbl, g_hbl);
    cudaGetSymbolAddress((void**)&qh,  g_qh);  cudaGetSymbolAddress((void**)&ql,  g_ql);
    cudaGetSymbolAddress((void**)&ah,  g_ah);  cudaGetSymbolAddress((void**)&al,  g_al);
    cudaGetSymbolAddress((void**)&fh,  g_fh);  cudaGetSymbolAddress((void**)&fl,  g_fl);
    cudaGetSymbolAddress((void**)&wh,  g_wh);  cudaGetSymbolAddress((void**)&wl,  g_wl);

    const int GSM = 8 * PLB;     // 81920
    const int ASM_ = 8 * PLV;    // 40960 -> 4 CTAs/SM (with reg cap 128)
    cudaFuncSetAttribute(gemm_mma, cudaFuncAttributeMaxDynamicSharedMemorySize, GSM);
    cudaFuncSetAttribute(attn_mma, cudaFuncAttributeMaxDynamicSharedMemorySize, ASM_);

    Segs S;
    S.seg[0] = { x, xh, xl, 0, 0, 1, (TOK * DIN) / 1024 };
    S.seg[1] = { W_in, wh + WOFF_IN, wl + WOFF_IN, DIN, HH, 0, (DIN/32)*(HH/32) };
    for (int l = 0; l < LL; l++) {
        S.seg[2+l] = { Wqkv + (size_t)l*HH*3*HH, wh + WOFF_QKV + l*HH*3*HH,
                       wl + WOFF_QKV + l*HH*3*HH, HH, 3*HH, 0, (HH/32)*(3*HH/32) };
        S.seg[4+l] = { Wo + (size_t)l*HH*HH, wh + WOFF_O + l*HH*HH,
                       wl + WOFF_O + l*HH*HH, HH, HH, 0, (HH/32)*(HH/32) };
        S.seg[6+l] = { W1 + (size_t)l*HH*FF, wh + WOFF_1 + l*HH*FF,
                       wl + WOFF_1 + l*HH*FF, HH, FF, 0, (HH/32)*(FF/32) };
        S.seg[8+l] = { W2 + (size_t)l*FF*HH, wh + WOFF_2 + l*FF*HH,
                       wl + WOFF_2 + l*FF*HH, FF, HH, 0, (FF/32)*(HH/32) };
    }
    prep_kernel<<<dim3(1024, 10), dim3(32, 8)>>>(S);

    gemm_mma<<<dim3(HH/128, TOK/128), 128, GSM>>>(
        xh, xl, wh + WOFF_IN, wl + WOFF_IN, b_in, nullptr, h, hbh, hbl, DIN, HH, 0);

    for (int l = 0; l < LL; l++) {
        gemm_mma<<<dim3(3*HH/128, TOK/128), 128, GSM>>>(
            hbh, hbl, wh + WOFF_QKV + l*HH*3*HH, wl + WOFF_QKV + l*HH*3*HH,
            bqkv + l*3*HH, nullptr, nullptr, qh, ql, HH, 3*HH, 0);
        attn_mma<<<dim3(NN/128, BB*8), 128, ASM_>>>(qh, ql, ah, al);
        gemm_mma<<<dim3(HH/128, TOK/128), 128, GSM>>>(
            ah, al, wh + WOFF_O + l*HH*HH, wl + WOFF_O + l*HH*HH,
            bo + l*HH, h, tmp, nullptr, nullptr, HH, HH, 0);
        ln_kernel<<<TOK/8, 256>>>(tmp, ln1g + l*HH, ln1b + l*HH, h, hbh, hbl);
        gemm_mma<<<dim3(FF/128, TOK/128), 128, GSM>>>(
            hbh, hbl, wh + WOFF_1 + l*HH*FF, wl + WOFF_1 + l*HH*FF,
            b1 + l*FF, nullptr, nullptr, fh, fl, HH, FF, 1);
        gemm_mma<<<dim3(HH/128, TOK/128), 128, GSM>>>(
            fh, fl, wh + WOFF_2 + l*FF*HH, wl + WOFF_2 + l*FF*HH,
            b2 + l*HH, h, tmp, nullptr, nullptr, FF, HH, 0);
        ln_kernel<<<TOK/8, 256>>>(tmp, ln2g + l*HH, ln2b + l*HH, h, hbh, hbl);
    }

    float* outf = (float*)d_out;
    const int idx_elems = BB * KKc, bw_elems = BB * NN;
    const int both = (out_size >= idx_elems + bw_elems) ? 1 : 0;
    float* bw = both ? (outf + idx_elems) : outf;
    init_out_kernel<<<(out_size + 255) / 256, 256>>>(sel, outf, out_size, both);
    alloc_kernel<<<BB, 256>>>(h, sel, Wc, bc, bw);
}

// round 11
// speedup vs baseline: 3.6519x; 1.0553x over previous
#include <cuda_runtime.h>
#include <cuda_bf16.h>
#include <cstdint>

#define BB 16
#define NN 1024
#define KKc 512
#define DIN 64
#define HH 256
#define FF 1024
#define LL 2
#define TOK (BB*NN)

typedef __nv_bfloat16 bf16;

#define WOFF_IN 0
#define WOFF_QKV (WOFF_IN + DIN*HH)
#define WOFF_O (WOFF_QKV + LL*HH*3*HH)
#define WOFF_1 (WOFF_O + LL*HH*HH)
#define WOFF_2 (WOFF_1 + LL*HH*FF)
#define WTOT (WOFF_2 + LL*FF*HH)

__device__ __align__(16) float g_h[TOK*HH], g_tmp[TOK*HH];
__device__ __align__(16) bf16 g_xh[TOK*DIN], g_xl[TOK*DIN];
__device__ __align__(16) bf16 g_hbh[TOK*HH], g_hbl[TOK*HH];
__device__ __align__(16) bf16 g_qh[TOK*768], g_ql[TOK*768];
__device__ __align__(16) bf16 g_ah[TOK*HH], g_al[TOK*HH];
__device__ __align__(16) bf16 g_fh[TOK*FF], g_fl[TOK*FF];
__device__ __align__(16) bf16 g_wh[WTOT], g_wl[WTOT];

// ---------------- helpers ----------------
__device__ __forceinline__ uint32_t smem_u32(const void* p) {
    uint32_t a;
    asm("{ .reg .u64 t; cvta.to.shared.u64 t, %1; cvt.u32.u64 %0, t; }" : "=r"(a) : "l"(p));
    return a;
}
__device__ __forceinline__ void cp16(uint32_t d, const void* s) {
    asm volatile("cp.async.cg.shared.global [%0], [%1], 16;" :: "r"(d), "l"(s));
}
#define CPCOMMIT() asm volatile("cp.async.commit_group;" ::: "memory")
#define CPWAIT(n)  asm volatile("cp.async.wait_group %0;" :: "n"(n) : "memory")

__device__ __forceinline__ void ldm4(uint32_t* r, uint32_t a) {
    asm volatile("ldmatrix.sync.aligned.m8n8.x4.shared.b16 {%0,%1,%2,%3}, [%4];"
                 : "=r"(r[0]), "=r"(r[1]), "=r"(r[2]), "=r"(r[3]) : "r"(a));
}
__device__ __forceinline__ void ldm4t(uint32_t* r, uint32_t a) {
    asm volatile("ldmatrix.sync.aligned.m8n8.x4.trans.shared.b16 {%0,%1,%2,%3}, [%4];"
                 : "=r"(r[0]), "=r"(r[1]), "=r"(r[2]), "=r"(r[3]) : "r"(a));
}
__device__ __forceinline__ void mma_b16(float* c, const uint32_t* a, const uint32_t* b) {
    asm volatile("mma.sync.aligned.m16n8k16.row.col.f32.bf16.bf16.f32 "
                 "{%0,%1,%2,%3},{%4,%5,%6,%7},{%8,%9},{%0,%1,%2,%3};"
                 : "+f"(c[0]), "+f"(c[1]), "+f"(c[2]), "+f"(c[3])
                 : "r"(a[0]), "r"(a[1]), "r"(a[2]), "r"(a[3]), "r"(b[0]), "r"(b[1]));
}
__device__ __forceinline__ uint32_t bf2(float lo, float hi) {
    uint32_t r;
    asm("cvt.rn.bf16x2.f32 %0, %1, %2;" : "=r"(r) : "f"(hi), "f"(lo));
    return r;
}
__device__ __forceinline__ void split_pack(float a, float b, uint32_t& hi, uint32_t& lo) {
    float ah = __bfloat162float(__float2bfloat16(a));
    float bh = __bfloat162float(__float2bfloat16(b));
    hi = bf2(ah, bh); lo = bf2(a - ah, b - bh);
}

#define RS 40        // smem row stride (bf16): 80B, conflict-free ldmatrix
#define PLB 10240    // 128-row plane bytes (128*RS*2)
#define PLV 5120     // 64-row plane bytes (64*RS*2)

// ---------------- prep: weight transpose/split + x split ----------------
struct Seg { const float* s; bf16 *dh, *dl; int K, N, mode, ntiles; };
struct Segs { Seg seg[10]; };

__global__ void prep_kernel(Segs S) {
    Seg sg = S.seg[blockIdx.y];
    if ((int)blockIdx.x >= sg.ntiles) return;
    const int tx = threadIdx.x, ty = threadIdx.y;
    if (sg.mode == 1) {
        int off = blockIdx.x * 1024 + ty * 128 + tx * 4;
        float4 v = *(const float4*)(sg.s + off);
        float a[4] = {v.x, v.y, v.z, v.w};
        #pragma unroll
        for (int i = 0; i < 4; i++) {
            bf16 h = __float2bfloat16(a[i]);
            sg.dh[off + i] = h;
            sg.dl[off + i] = __float2bfloat16(a[i] - __bfloat162float(h));
        }
    } else {
        __shared__ float tile[32][33];
        int kt = blockIdx.x % (sg.K / 32), nt = blockIdx.x / (sg.K / 32);
        int k0 = kt * 32, n0 = nt * 32;
        #pragma unroll
        for (int i = 0; i < 4; i++)
            tile[ty * 4 + i][tx] = sg.s[(size_t)(k0 + ty * 4 + i) * sg.N + n0 + tx];
        __syncthreads();
        #pragma unroll
        for (int i = 0; i < 4; i++) {
            float v = tile[tx][ty * 4 + i];
            bf16 h = __float2bfloat16(v);
            size_t d = (size_t)(n0 + ty * 4 + i) * sg.K + k0 + tx;
            sg.dh[d] = h;
            sg.dl[d] = __float2bfloat16(v - __bfloat162float(h));
        }
    }
}

// ---------------- split-bf16 HMMA GEMM, 128x128 block, 64x64 warp, 128 thr --
// (proven config) smem planes @ (p*2+buf)*PLB, p={Ah,Al,Bh,Bl}. 80KB.
__global__ __launch_bounds__(128) void gemm_mma(
    const bf16* __restrict__ Ah, const bf16* __restrict__ Al,
    const bf16* __restrict__ Bh, const bf16* __restrict__ Bl,
    const float* __restrict__ bias, const float* __restrict__ res,
    float* __restrict__ Cf, bf16* __restrict__ Cbh, bf16* __restrict__ Cbl,
    int K, int N, int relu)
{
    extern __shared__ __align__(16) bf16 smr[];
    const int tid = threadIdx.x, lane = tid & 31, wid = tid >> 5;
    const int m0 = blockIdx.y << 7, n0 = blockIdx.x << 7;
    const int wm = (wid & 1) << 6, wn = (wid >> 1) << 6;
    const uint32_t sb = smem_u32(smr);
    const uint32_t sbA = sb, sbAl = sb + 2 * PLB;
    const uint32_t sbB = sb + 4 * PLB, sbBl = sb + 6 * PLB;

    float acc[4][8][4];
    #pragma unroll
    for (int a = 0; a < 4; a++)
        #pragma unroll
        for (int b = 0; b < 8; b++)
            #pragma unroll
            for (int c = 0; c < 4; c++) acc[a][b][c] = 0.f;

    const int nst = K >> 5;

    #pragma unroll 1
    for (int sp = 0; sp <= nst; sp++) {
        if (sp < nst) {
            const int k0 = sp << 5, buf = sp & 1;
            #pragma unroll
            for (int i = 0; i < 8; i++) {
                int idx = tid + (i << 7);
                int pl = idx >> 9, rest = idx & 511;
                int r = rest >> 2, c8 = (rest & 3) << 3;
                uint32_t so = (uint32_t)(r * RS + c8) << 1;
                const bf16* src = (pl ? Al : Ah) + (size_t)(m0 + r) * K + k0 + c8;
                cp16((pl ? sbAl : sbA) + buf * PLB + so, src);
            }
            #pragma unroll
            for (int i = 0; i < 8; i++) {
                int idx = tid + (i << 7);
                int pl = idx >> 9, rest = idx & 511;
                int r = rest >> 2, c8 = (rest & 3) << 3;
                uint32_t so = (uint32_t)(r * RS + c8) << 1;
                const bf16* src = (pl ? Bl : Bh) + (size_t)(n0 + r) * K + k0 + c8;
                cp16((pl ? sbBl : sbB) + buf * PLB + so, src);
            }
            CPCOMMIT();
        }
        if (sp == 0) continue;
        const int s = sp - 1;
        if (sp < nst) { CPWAIT(1); } else { CPWAIT(0); }
        __syncthreads();

        const int buf = s & 1;
        const uint32_t pAh = sbA + buf * PLB, pAl = sbAl + buf * PLB;
        const uint32_t pBh = sbB + buf * PLB, pBl = sbBl + buf * PLB;
        #pragma unroll
        for (int ks = 0; ks < 2; ks++) {
            uint32_t ah[4][4], al[4][4];
            #pragma unroll
            for (int mt = 0; mt < 4; mt++) {
                uint32_t off = (uint32_t)((wm + mt * 16 + (lane & 15)) * RS
                                          + ks * 16 + ((lane >> 4) << 3)) << 1;
                ldm4(ah[mt], pAh + off); ldm4(al[mt], pAl + off);
            }
            #pragma unroll
            for (int nt = 0; nt < 4; nt++) {
                uint32_t bh[4], bl[4];
                uint32_t off = (uint32_t)((wn + nt * 16 + (lane & 7) + ((lane >> 4) << 3)) * RS
                                          + ks * 16 + ((lane >> 3) & 1) * 8) << 1;
                ldm4(bh, pBh + off); ldm4(bl, pBl + off);
                #pragma unroll
                for (int mt = 0; mt < 4; mt++)
                    #pragma unroll
                    for (int t = 0; t < 2; t++) {
                        float* c = acc[mt][nt * 2 + t];
                        mma_b16(c, ah[mt], bh + 2 * t);
                        mma_b16(c, ah[mt], bl + 2 * t);
                        mma_b16(c, al[mt], bh + 2 * t);
                    }
            }
        }
        __syncthreads();
    }

    #pragma unroll
    for (int mt = 0; mt < 4; mt++)
        #pragma unroll
        for (int nt = 0; nt < 8; nt++) {
            int r0 = m0 + wm + mt * 16 + (lane >> 2);
            int c  = n0 + wn + nt * 8 + ((lane & 3) << 1);
            float* a = acc[mt][nt];
            float b0 = bias[c], b1 = bias[c + 1];
            float v0 = a[0] + b0, v1 = a[1] + b1, v2 = a[2] + b0, v3 = a[3] + b1;
            if (res) {
                float2 q0 = *(const float2*)(res + (size_t)r0 * N + c);
                float2 q1 = *(const float2*)(res + (size_t)(r0 + 8) * N + c);
                v0 += q0.x; v1 += q0.y; v2 += q1.x; v3 += q1.y;
            }
            if (relu) {
                v0 = fmaxf(v0, 0.f); v1 = fmaxf(v1, 0.f);
                v2 = fmaxf(v2, 0.f); v3 = fmaxf(v3, 0.f);
            }
            if (Cf) {
                *(float2*)(Cf + (size_t)r0 * N + c)       = make_float2(v0, v1);
                *(float2*)(Cf + (size_t)(r0 + 8) * N + c) = make_float2(v2, v3);
            }
            if (Cbh) {
                uint32_t h0, l0, h1, l1;
                split_pack(v0, v1, h0, l0); split_pack(v2, v3, h1, l1);
                *(uint32_t*)(Cbh + (size_t)r0 * N + c) = h0;
                *(uint32_t*)(Cbl + (size_t)r0 * N + c) = l0;
                *(uint32_t*)(Cbh + (size_t)(r0 + 8) * N + c) = h1;
                *(uint32_t*)(Cbl + (size_t)(r0 + 8) * N + c) = l1;
            }
        }
}

// ---------------- fused HMMA flash attention (round-10 proven) -------------
__global__ __launch_bounds__(128, 4) void attn_mma(
    const bf16* __restrict__ qh, const bf16* __restrict__ ql,
    bf16* __restrict__ oh, bf16* __restrict__ ol)
{
    extern __shared__ __align__(16) bf16 smr[];
    const int tid = threadIdx.x, lane = tid & 31, wid = tid >> 5;
    const int bhn = blockIdx.y, b = bhn >> 3, h = bhn & 7;
    const int q0 = blockIdx.x << 7;
    const size_t base = (size_t)b * NN;
    const uint32_t sb = smem_u32(smr);
    const float SC = 0.17677669529663687f;

    #pragma unroll
    for (int i = 0; i < 8; i++) {
        int idx = tid + (i << 7);
        int pl = idx >> 9, rest = idx & 511;
        int r = rest >> 2, c8 = (rest & 3) << 3;
        uint32_t so = (uint32_t)(r * RS + c8) << 1;
        const bf16* src = (pl ? ql : qh) + (base + q0 + r) * 768 + h * 32 + c8;
        cp16(sb + pl * (2 * PLV) + so, src);
    }
    #pragma unroll
    for (int i = 0; i < 8; i++) {
        int idx = tid + (i << 7);
        int pl = idx >> 8, rest = idx & 255;
        int r = rest >> 2, c8 = (rest & 3) << 3;
        uint32_t so = (uint32_t)(r * RS + c8) << 1;
        int fo = (pl >> 1) ? 512 : 256;
        const bf16* src = ((pl & 1) ? ql : qh) + (base + r) * 768 + fo + h * 32 + c8;
        cp16(sb + 4 * PLV + pl * PLV + so, src);
    }
    CPCOMMIT();

    uint32_t qfh[2][2][4], qfl[2][2][4];
    float oacc[2][4][4];
    #pragma unroll
    for (int m = 0; m < 2; m++)
        #pragma unroll
        for (int a = 0; a < 4; a++)
            #pragma unroll
            for (int c = 0; c < 4; c++) oacc[m][a][c] = 0.f;
    float rs[2][2] = {{0.f, 0.f}, {0.f, 0.f}};

    CPWAIT(0);
    __syncthreads();
    #pragma unroll
    for (int mt = 0; mt < 2; mt++)
        #pragma unroll
        for (int ks = 0; ks < 2; ks++) {
            uint32_t off = (uint32_t)((wid * 32 + mt * 16 + (lane & 15)) * RS
                                      + ks * 16 + ((lane >> 4) << 3)) << 1;
            ldm4(qfh[mt][ks], sb + off);
            ldm4(qfl[mt][ks], sb + 2 * PLV + off);
        }
    __syncthreads();

    for (int s = 0; s < 16; s++) {
        if (s < 15) {
            const int kv0 = (s + 1) << 6;
            const uint32_t dstb = ((s + 1) & 1) ? sb : sb + 4 * PLV;
            #pragma unroll
            for (int i = 0; i < 8; i++) {
                int idx = tid + (i << 7);
                int pl = idx >> 8, rest = idx & 255;
                int r = rest >> 2, c8 = (rest & 3) << 3;
                uint32_t so = (uint32_t)(r * RS + c8) << 1;
                int fo = (pl >> 1) ? 512 : 256;
                const bf16* src = ((pl & 1) ? ql : qh) + (base + kv0 + r) * 768 + fo + h * 32 + c8;
                cp16(dstb + pl * PLV + so, src);
            }
            CPCOMMIT();
            CPWAIT(1);
        } else {
            CPWAIT(0);
        }
        __syncthreads();

        const uint32_t kH = (s & 1) ? sb : sb + 4 * PLV;
        const uint32_t kL = kH + PLV, vH = kH + 2 * PLV, vL = kH + 3 * PLV;

        #pragma unroll
        for (int kk = 0; kk < 4; kk++) {
            float sv[2][2][4];
            #pragma unroll
            for (int m = 0; m < 2; m++)
                #pragma unroll
                for (int t = 0; t < 2; t++)
                    #pragma unroll
                    for (int c = 0; c < 4; c++) sv[m][t][c] = 0.f;
            #pragma unroll
            for (int ks = 0; ks < 2; ks++) {
                uint32_t bh[4], bl[4];
                uint32_t off = (uint32_t)((kk * 16 + (lane & 7) + ((lane >> 4) << 3)) * RS
                                          + ks * 16 + ((lane >> 3) & 1) * 8) << 1;
                ldm4(bh, kH + off); ldm4(bl, kL + off);
                #pragma unroll
                for (int mt = 0; mt < 2; mt++)
                    #pragma unroll
                    for (int t = 0; t < 2; t++) {
                        float* c = sv[mt][t];
                        mma_b16(c, qfh[mt][ks], bh + 2 * t);
                        mma_b16(c, qfh[mt][ks], bl + 2 * t);
                        mma_b16(c, qfl[mt][ks], bh + 2 * t);
                    }
            }
            uint32_t va[4], vb[4], vc[4], vd[4];
            {
                uint32_t ro = kk * 16 + (lane & 7) + (((lane >> 3) & 1) << 3);
                uint32_t ofa = (uint32_t)(ro * RS + ((lane >> 4) << 3)) << 1;
                uint32_t ofb = (uint32_t)(ro * RS + 16 + ((lane >> 4) << 3)) << 1;
                ldm4t(va, vH + ofa); ldm4t(vb, vH + ofb);
                ldm4t(vc, vL + ofa); ldm4t(vd, vL + ofb);
            }
            #pragma unroll
            for (int mt = 0; mt < 2; mt++) {
                float e00 = __expf(sv[mt][0][0] * SC), e01 = __expf(sv[mt][0][1] * SC);
                float e02 = __expf(sv[mt][0][2] * SC), e03 = __expf(sv[mt][0][3] * SC);
                float e10 = __expf(sv[mt][1][0] * SC), e11 = __expf(sv[mt][1][1] * SC);
                float e12 = __expf(sv[mt][1][2] * SC), e13 = __expf(sv[mt][1][3] * SC);
                rs[mt][0] += e00 + e01 + e10 + e11;
                rs[mt][1] += e02 + e03 + e12 + e13;
                uint32_t pah[4], pal[4];
                split_pack(e00, e01, pah[0], pal[0]);
                split_pack(e02, e03, pah[1], pal[1]);
                split_pack(e10, e11, pah[2], pal[2]);
                split_pack(e12, e13, pah[3], pal[3]);
                float* o = (float*)oacc[mt];
                mma_b16(o + 0,  pah, va);     mma_b16(o + 0,  pah, vc);     mma_b16(o + 0,  pal, va);
                mma_b16(o + 4,  pah, va + 2); mma_b16(o + 4,  pah, vc + 2); mma_b16(o + 4,  pal, va + 2);
                mma_b16(o + 8,  pah, vb);     mma_b16(o + 8,  pah, vd);     mma_b16(o + 8,  pal, vb);
                mma_b16(o + 12, pah, vb + 2); mma_b16(o + 12, pah, vd + 2); mma_b16(o + 12, pal, vb + 2);
            }
        }
        __syncthreads();
    }

    #pragma unroll
    for (int mt = 0; mt < 2; mt++) {
        float r0 = rs[mt][0], r1 = rs[mt][1];
        r0 += __shfl_xor_sync(0xffffffffu, r0, 1);
        r0 += __shfl_xor_sync(0xffffffffu, r0, 2);
        r1 += __shfl_xor_sync(0xffffffffu, r1, 1);
        r1 += __shfl_xor_sync(0xffffffffu, r1, 2);
        const float i0 = 1.f / r0, i1 = 1.f / r1;
        #pragma unroll
        for (int nt = 0; nt < 4; nt++) {
            int row = q0 + wid * 32 + mt * 16 + (lane >> 2);
            int c   = h * 32 + nt * 8 + ((lane & 3) << 1);
            float v0 = oacc[mt][nt][0] * i0, v1 = oacc[mt][nt][1] * i0;
            float v2 = oacc[mt][nt][2] * i1, v3 = oacc[mt][nt][3] * i1;
            uint32_t h0, l0, h1, l1;
            split_pack(v0, v1, h0, l0); split_pack(v2, v3, h1, l1);
            *(uint32_t*)(oh + (base + row) * HH + c) = h0;
            *(uint32_t*)(ol + (base + row) * HH + c) = l0;
            *(uint32_t*)(oh + (base + row + 8) * HH + c) = h1;
            *(uint32_t*)(ol + (base + row + 8) * HH + c) = l1;
        }
    }
}

// ---------------- LayerNorm: fp32 in -> fp32 + bf16 hi/lo ----------------
__global__ __launch_bounds__(256) void ln_kernel(
    const float* __restrict__ x, const float* __restrict__ gam,
    const float* __restrict__ bet, float* __restrict__ out,
    bf16* __restrict__ ohp, bf16* __restrict__ olp)
{
    const int row = blockIdx.x * 8 + (threadIdx.x >> 5);
    const int lane = threadIdx.x & 31;
    const float* xr = x + (size_t)row * HH;
    float v[8], sum = 0.f;
    #pragma unroll
    for (int i = 0; i < 8; i++) { v[i] = xr[lane + i * 32]; sum += v[i]; }
    #pragma unroll
    for (int o = 16; o; o >>= 1) sum += __shfl_xor_sync(0xffffffffu, sum, o);
    const float mean = sum * (1.f / HH);
    float var = 0.f;
    #pragma unroll
    for (int i = 0; i < 8; i++) { float d = v[i] - mean; var += d * d; }
    #pragma unroll
    for (int o = 16; o; o >>= 1) var += __shfl_xor_sync(0xffffffffu, var, o);
    const float inv = rsqrtf(var * (1.f / HH) + 1e-5f);
    #pragma unroll
    for (int i = 0; i < 8; i++) {
        const int c = lane + i * 32;
        float val = (v[i] - mean) * inv * gam[c] + bet[c];
        out[(size_t)row * HH + c] = val;
        bf16 hb = __float2bfloat16(val);
        ohp[(size_t)row * HH + c] = hb;
        olp[(size_t)row * HH + c] = __float2bfloat16(val - __bfloat162float(hb));
    }
}

// ---------------- fallback init (only for unexpected out_size) -------------
__global__ void init_out_kernel(float* __restrict__ out, int out_size)
{
    const int i = blockIdx.x * 256 + threadIdx.x;
    if (i < out_size) out[i] = 0.f;
}

// ---------------- allocation (1024 threads, fused output init) -------------
// grid (BB). Zeroes its bw row, writes its idx segment, computes allocation.
__global__ __launch_bounds__(1024) void alloc_kernel(
    const float* __restrict__ enc, const int* __restrict__ sel,
    const float* __restrict__ Wc, const float* __restrict__ bc,
    float* __restrict__ outf, int both)
{
    __shared__ float part_s[4][HH];
    __shared__ float mean_s[HH], ctx_s[HH];
    __shared__ float sc_s[KKc];
    __shared__ float red_s[1024];
    __shared__ int   idx_s[KKc];
    __shared__ int   cnt_s[4];

    const int b = blockIdx.x, tid = threadIdx.x;
    float* bw = both ? (outf + BB * KKc) : outf;

    if (tid < KKc) idx_s[tid] = sel[b * KKc + tid];
    // fused init: zero my bw row; write my idx segment (as float)
    bw[b * NN + tid] = 0.f;
    __syncthreads();
    if (both && tid < KKc) outf[b * KKc + tid] = (float)idx_s[tid];

    // phase 1: masked mean — 4-way k-split
    const int c = tid & 255, grp = tid >> 8;
    {
        float acc = 0.f; int cnt = 0;
        const int kb = grp << 7;
        #pragma unroll 4
        for (int k = kb; k < kb + 128; k++) {
            const int idx = idx_s[k];
            if (idx < NN) { acc += enc[((size_t)b * NN + idx) * HH + c]; cnt++; }
        }
        part_s[grp][c] = acc;
        if (c == 0) cnt_s[grp] = cnt;
    }
    __syncthreads();
    const int cntT = cnt_s[0] + cnt_s[1] + cnt_s[2] + cnt_s[3];
    if (tid < HH)
        mean_s[tid] = ((part_s[0][tid] + part_s[1][tid]) + (part_s[2][tid] + part_s[3][tid]))
                      / (float)(cntT > 0 ? cntT : 1);
    __syncthreads();

    // phase 2: ctx = mean @ Wc + bc — 4-way i-split
    {
        float p = 0.f;
        const int ib = grp << 6;
        #pragma unroll 4
        for (int i = ib; i < ib + 64; i++) p += mean_s[i] * Wc[i * HH + c];
        part_s[grp][c] = p;
    }
    __syncthreads();
    if (tid < HH)
        ctx_s[tid] = ((part_s[0][tid] + part_s[1][tid]) + (part_s[2][tid] + part_s[3][tid]))
                     + bc[tid];
    __syncthreads();

    // phase 3: scores — 32 warps
    const int wid = tid >> 5, lane = tid & 31;
    for (int k = wid; k < KKc; k += 32) {
        const int idx = idx_s[k];
        float s = -1e30f;
        if (idx < NN) {
            const float* row = enc + ((size_t)b * NN + idx) * HH;
            float part = 0.f;
            #pragma unroll
            for (int i = 0; i < 8; i++) part += ctx_s[lane + i * 32] * row[lane + i * 32];
            #pragma unroll
            for (int o = 16; o; o >>= 1) part += __shfl_xor_sync(0xffffffffu, part, o);
            s = part;
        }
        if (lane == 0) sc_s[k] = s;
    }
    __syncthreads();

    // max over 512
    red_s[tid] = (tid < KKc) ? sc_s[tid] : -1e30f;
    __syncthreads();
    for (int st = 512; st; st >>= 1) {
        if (tid < st) red_s[tid] = fmaxf(red_s[tid], red_s[tid + st]);
        __syncthreads();
    }
    const float m = red_s[0];
    __syncthreads();

    // exp + sum
    const int myidx = (tid < KKc) ? idx_s[tid] : NN;
    const float e = (myidx < NN) ? expf(sc_s[tid] - m) : 0.f;
    red_s[tid] = e;
    __syncthreads();
    for (int st = 512; st; st >>= 1) {
        if (tid < st) red_s[tid] += red_s[tid + st];
        __syncthreads();
    }
    const float denom = red_s[0];
    __syncthreads();

    // round + fixup sum
    float a = rintf(e / denom * 100.f);
    red_s[tid] = a;
    __syncthreads();
    for (int st = 512; st; st >>= 1) {
        if (tid < st) red_s[tid] += red_s[tid + st];
        __syncthreads();
    }
    const float diff = 100.f - red_s[0];
    __syncthreads();

    if (tid == 0 && myidx < NN) a += diff;
    if (myidx < NN) bw[b * NN + myidx] = a;
}

// ---------------- launch ----------------
extern "C" void kernel_launch(void* const* d_in, const int* in_sizes, int n_in,
                              void* d_out, int out_size)
{
    const float* x    = (const float*)d_in[0];
    const int*   sel  = (const int*)  d_in[1];
    const float* W_in = (const float*)d_in[2];
    const float* b_in = (const float*)d_in[3];
    const float* Wqkv = (const float*)d_in[4];
    const float* bqkv = (const float*)d_in[5];
    const float* Wo   = (const float*)d_in[6];
    const float* bo   = (const float*)d_in[7];
    const float* ln1g = (const float*)d_in[8];
    const float* ln1b = (const float*)d_in[9];
    const float* W1   = (const float*)d_in[10];
    const float* b1   = (const float*)d_in[11];
    const float* W2   = (const float*)d_in[12];
    const float* b2   = (const float*)d_in[13];
    const float* ln2g = (const float*)d_in[14];
    const float* ln2b = (const float*)d_in[15];
    const float* Wc   = (const float*)d_in[16];
    const float* bc   = (const float*)d_in[17];

    float *h, *tmp;
    bf16 *xh, *xl, *hbh, *hbl, *qh, *ql, *ah, *al, *fh, *fl, *wh, *wl;
    cudaGetSymbolAddress((void**)&h,   g_h);   cudaGetSymbolAddress((void**)&tmp, g_tmp);
    cudaGetSymbolAddress((void**)&xh,  g_xh);  cudaGetSymbolAddress((void**)&xl,  g_xl);
    cudaGetSymbolAddress((void**)&hbh, g_hbh); cudaGetSymbolAddress((void**)&hbl, g_hbl);
    cudaGetSymbolAddress((void**)&qh,  g_qh);  cudaGetSymbolAddress((void**)&ql,  g_ql);
    cudaGetSymbolAddress((void**)&ah,  g_ah);  cudaGetSymbolAddress((void**)&al,  g_al);
    cudaGetSymbolAddress((void**)&fh,  g_fh);  cudaGetSymbolAddress((void**)&fl,  g_fl);
    cudaGetSymbolAddress((void**)&wh,  g_wh);  cudaGetSymbolAddress((void**)&wl,  g_wl);

    const int GSM = 8 * PLB;     // 81920
    const int ASM_ = 8 * PLV;    // 40960
    cudaFuncSetAttribute(gemm_mma, cudaFuncAttributeMaxDynamicSharedMemorySize, GSM);
    cudaFuncSetAttribute(attn_mma, cudaFuncAttributeMaxDynamicSharedMemorySize, ASM_);

    Segs S;
    S.seg[0] = { x, xh, xl, 0, 0, 1, (TOK * DIN) / 1024 };
    S.seg[1] = { W_in, wh + WOFF_IN, wl + WOFF_IN, DIN, HH, 0, (DIN/32)*(HH/32) };
    for (int l = 0; l < LL; l++) {
        S.seg[2+l] = { Wqkv + (size_t)l*HH*3*HH, wh + WOFF_QKV + l*HH*3*HH,
                       wl + WOFF_QKV + l*HH*3*HH, HH, 3*HH, 0, (HH/32)*(3*HH/32) };
        S.seg[4+l] = { Wo + (size_t)l*HH*HH, wh + WOFF_O + l*HH*HH,
                       wl + WOFF_O + l*HH*HH, HH, HH, 0, (HH/32)*(HH/32) };
        S.seg[6+l] = { W1 + (size_t)l*HH*FF, wh + WOFF_1 + l*HH*FF,
                       wl + WOFF_1 + l*HH*FF, HH, FF, 0, (HH/32)*(FF/32) };
        S.seg[8+l] = { W2 + (size_t)l*FF*HH, wh + WOFF_2 + l*FF*HH,
                       wl + WOFF_2 + l*FF*HH, FF, HH, 0, (FF/32)*(HH/32) };
    }
    prep_kernel<<<dim3(1024, 10), dim3(32, 8)>>>(S);

    gemm_mma<<<dim3(HH/128, TOK/128), 128, GSM>>>(
        xh, xl, wh + WOFF_IN, wl + WOFF_IN, b_in, nullptr, h, hbh, hbl, DIN, HH, 0);

    for (int l = 0; l < LL; l++) {
        gemm_mma<<<dim3(3*HH/128, TOK/128), 128, GSM>>>(
            hbh, hbl, wh + WOFF_QKV + l*HH*3*HH, wl + WOFF_QKV + l*HH*3*HH,
            bqkv + l*3*HH, nullptr, nullptr, qh, ql, HH, 3*HH, 0);
        attn_mma<<<dim3(NN/128, BB*8), 128, ASM_>>>(qh, ql, ah, al);
        gemm_mma<<<dim3(HH/128, TOK/128), 128, GSM>>>(
            ah, al, wh + WOFF_O + l*HH*HH, wl + WOFF_O + l*HH*HH,
            bo + l*HH, h, tmp, nullptr, nullptr, HH, HH, 0);
        ln_kernel<<<TOK/8, 256>>>(tmp, ln1g + l*HH, ln1b + l*HH, h, hbh, hbl);
        gemm_mma<<<dim3(FF/128, TOK/128), 128, GSM>>>(
            hbh, hbl, wh + WOFF_1 + l*HH*FF, wl + WOFF_1 + l*HH*FF,
            b1 + l*FF, nullptr, nullptr, fh, fl, HH, FF, 1);
        gemm_mma<<<dim3(HH/128, TOK/128), 128, GSM>>>(
            fh, fl, wh + WOFF_2 + l*FF*HH, wl + WOFF_2 + l*FF*HH,
            b2 + l*HH, h, tmp, nullptr, nullptr, FF, HH, 0);
        ln_kernel<<<TOK/8, 256>>>(tmp, ln2g + l*HH, ln2b + l*HH, h, hbh, hbl);
    }

    float* outf = (float*)d_out;
    const int idx_elems = BB * KKc, bw_elems = BB * NN;
    const int both = (out_size >= idx_elems + bw_elems) ? 1 : 0;

    // alloc covers exactly [idx | bw] (or [bw]); zero any unexpected surplus
    const int covered = both ? (idx_elems + bw_elems) : bw_elems;
    if (out_size > covered)
        init_out_kernel<<<(out_size + 255) / 256, 256>>>(outf, out_size);

    alloc_kernel<<<BB, 1024>>>(h, sel, Wc, bc, outf, both);
}

// round 12
// speedup vs baseline: 3.6702x; 1.0050x over previous
#include <cuda_runtime.h>
#include <cuda_bf16.h>
#include <cstdint>

#define BB 16
#define NN 1024
#define KKc 512
#define DIN 64
#define HH 256
#define FF 1024
#define LL 2
#define TOK (BB*NN)

typedef __nv_bfloat16 bf16;

#define WOFF_IN 0
#define WOFF_QKV (WOFF_IN + DIN*HH)
#define WOFF_O (WOFF_QKV + LL*HH*3*HH)
#define WOFF_1 (WOFF_O + LL*HH*HH)
#define WOFF_2 (WOFF_1 + LL*HH*FF)
#define WTOT (WOFF_2 + LL*FF*HH)

__device__ __align__(16) float g_h[TOK*HH], g_tmp[TOK*HH];
__device__ __align__(16) bf16 g_xh[TOK*DIN], g_xl[TOK*DIN];
__device__ __align__(16) bf16 g_hbh[TOK*HH], g_hbl[TOK*HH];
__device__ __align__(16) bf16 g_qh[TOK*768], g_ql[TOK*768];
__device__ __align__(16) bf16 g_ah[TOK*HH], g_al[TOK*HH];
__device__ __align__(16) bf16 g_fh[TOK*FF], g_fl[TOK*FF];
__device__ __align__(16) bf16 g_wh[WTOT], g_wl[WTOT];

// ---------------- helpers ----------------
__device__ __forceinline__ uint32_t smem_u32(const void* p) {
    uint32_t a;
    asm("{ .reg .u64 t; cvta.to.shared.u64 t, %1; cvt.u32.u64 %0, t; }" : "=r"(a) : "l"(p));
    return a;
}
__device__ __forceinline__ void cp16(uint32_t d, const void* s) {
    asm volatile("cp.async.cg.shared.global [%0], [%1], 16;" :: "r"(d), "l"(s));
}
#define CPCOMMIT() asm volatile("cp.async.commit_group;" ::: "memory")
#define CPWAIT(n)  asm volatile("cp.async.wait_group %0;" :: "n"(n) : "memory")

__device__ __forceinline__ void ldm4(uint32_t* r, uint32_t a) {
    asm volatile("ldmatrix.sync.aligned.m8n8.x4.shared.b16 {%0,%1,%2,%3}, [%4];"
                 : "=r"(r[0]), "=r"(r[1]), "=r"(r[2]), "=r"(r[3]) : "r"(a));
}
__device__ __forceinline__ void ldm4t(uint32_t* r, uint32_t a) {
    asm volatile("ldmatrix.sync.aligned.m8n8.x4.trans.shared.b16 {%0,%1,%2,%3}, [%4];"
                 : "=r"(r[0]), "=r"(r[1]), "=r"(r[2]), "=r"(r[3]) : "r"(a));
}
__device__ __forceinline__ void mma_b16(float* c, const uint32_t* a, const uint32_t* b) {
    asm volatile("mma.sync.aligned.m16n8k16.row.col.f32.bf16.bf16.f32 "
                 "{%0,%1,%2,%3},{%4,%5,%6,%7},{%8,%9},{%0,%1,%2,%3};"
                 : "+f"(c[0]), "+f"(c[1]), "+f"(c[2]), "+f"(c[3])
                 : "r"(a[0]), "r"(a[1]), "r"(a[2]), "r"(a[3]), "r"(b[0]), "r"(b[1]));
}
__device__ __forceinline__ uint32_t bf2(float lo, float hi) {
    uint32_t r;
    asm("cvt.rn.bf16x2.f32 %0, %1, %2;" : "=r"(r) : "f"(hi), "f"(lo));
    return r;
}
__device__ __forceinline__ void split_pack(float a, float b, uint32_t& hi, uint32_t& lo) {
    float ah = __bfloat162float(__float2bfloat16(a));
    float bh = __bfloat162float(__float2bfloat16(b));
    hi = bf2(ah, bh); lo = bf2(a - ah, b - bh);
}

#define RS 40        // smem row stride (bf16): 80B, conflict-free ldmatrix
#define PLB 10240    // 128-row plane bytes (128*RS*2)
#define PLV 5120     // 64-row plane bytes (64*RS*2)

// ---------------- prep: weight transpose/split + x split ----------------
struct Seg { const float* s; bf16 *dh, *dl; int K, N, mode, ntiles; };
struct Segs { Seg seg[10]; };

__global__ void prep_kernel(Segs S) {
    Seg sg = S.seg[blockIdx.y];
    if ((int)blockIdx.x >= sg.ntiles) return;
    const int tx = threadIdx.x, ty = threadIdx.y;
    if (sg.mode == 1) {
        int off = blockIdx.x * 1024 + ty * 128 + tx * 4;
        float4 v = *(const float4*)(sg.s + off);
        float a[4] = {v.x, v.y, v.z, v.w};
        #pragma unroll
        for (int i = 0; i < 4; i++) {
            bf16 h = __float2bfloat16(a[i]);
            sg.dh[off + i] = h;
            sg.dl[off + i] = __float2bfloat16(a[i] - __bfloat162float(h));
        }
    } else {
        __shared__ float tile[32][33];
        int kt = blockIdx.x % (sg.K / 32), nt = blockIdx.x / (sg.K / 32);
        int k0 = kt * 32, n0 = nt * 32;
        #pragma unroll
        for (int i = 0; i < 4; i++)
            tile[ty * 4 + i][tx] = sg.s[(size_t)(k0 + ty * 4 + i) * sg.N + n0 + tx];
        __syncthreads();
        #pragma unroll
        for (int i = 0; i < 4; i++) {
            float v = tile[tx][ty * 4 + i];
            bf16 h = __float2bfloat16(v);
            size_t d = (size_t)(n0 + ty * 4 + i) * sg.K + k0 + tx;
            sg.dh[d] = h;
            sg.dl[d] = __float2bfloat16(v - __bfloat162float(h));
        }
    }
}

// ---------------- split-bf16 HMMA GEMM, 128x128 block, 64x32 warp, 256 thr --
// smem planes @ (p*2+buf)*PLB, p={Ah,Al,Bh,Bl}. 80KB -> 2 CTA/SM = 16 warps.
__global__ __launch_bounds__(256, 2) void gemm_mma(
    const bf16* __restrict__ Ah, const bf16* __restrict__ Al,
    const bf16* __restrict__ Bh, const bf16* __restrict__ Bl,
    const float* __restrict__ bias, const float* __restrict__ res,
    float* __restrict__ Cf, bf16* __restrict__ Cbh, bf16* __restrict__ Cbl,
    int K, int N, int relu)
{
    extern __shared__ __align__(16) bf16 smr[];
    const int tid = threadIdx.x, lane = tid & 31, wid = tid >> 5;
    const int m0 = blockIdx.y << 7, n0 = blockIdx.x << 7;
    const int wm = (wid & 1) << 6, wn = (wid >> 1) << 5;
    const uint32_t sb = smem_u32(smr);
    const uint32_t sbA = sb, sbAl = sb + 2 * PLB;
    const uint32_t sbB = sb + 4 * PLB, sbBl = sb + 6 * PLB;

    float acc[4][4][4];
    #pragma unroll
    for (int a = 0; a < 4; a++)
        #pragma unroll
        for (int b = 0; b < 4; b++)
            #pragma unroll
            for (int c = 0; c < 4; c++) acc[a][b][c] = 0.f;

    const int nst = K >> 5;

    #pragma unroll 1
    for (int sp = 0; sp <= nst; sp++) {
        if (sp < nst) {
            const int k0 = sp << 5, buf = sp & 1;
            #pragma unroll
            for (int i = 0; i < 4; i++) {   // A hi+lo: 1024 chunks
                int idx = tid + (i << 8);
                int pl = idx >> 9, rest = idx & 511;
                int r = rest >> 2, c8 = (rest & 3) << 3;
                uint32_t so = (uint32_t)(r * RS + c8) << 1;
                const bf16* src = (pl ? Al : Ah) + (size_t)(m0 + r) * K + k0 + c8;
                cp16((pl ? sbAl : sbA) + buf * PLB + so, src);
            }
            #pragma unroll
            for (int i = 0; i < 4; i++) {   // B hi+lo: 1024 chunks
                int idx = tid + (i << 8);
                int pl = idx >> 9, rest = idx & 511;
                int r = rest >> 2, c8 = (rest & 3) << 3;
                uint32_t so = (uint32_t)(r * RS + c8) << 1;
                const bf16* src = (pl ? Bl : Bh) + (size_t)(n0 + r) * K + k0 + c8;
                cp16((pl ? sbBl : sbB) + buf * PLB + so, src);
            }
            CPCOMMIT();
        }
        if (sp == 0) continue;
        const int s = sp - 1;
        if (sp < nst) { CPWAIT(1); } else { CPWAIT(0); }
        __syncthreads();

        const int buf = s & 1;
        const uint32_t pAh = sbA + buf * PLB, pAl = sbAl + buf * PLB;
        const uint32_t pBh = sbB + buf * PLB, pBl = sbBl + buf * PLB;
        #pragma unroll
        for (int ks = 0; ks < 2; ks++) {
            uint32_t ah[4][4], al[4][4];
            #pragma unroll
            for (int mt = 0; mt < 4; mt++) {
                uint32_t off = (uint32_t)((wm + mt * 16 + (lane & 15)) * RS
                                          + ks * 16 + ((lane >> 4) << 3)) << 1;
                ldm4(ah[mt], pAh + off); ldm4(al[mt], pAl + off);
            }
            #pragma unroll
            for (int nt = 0; nt < 2; nt++) {
                uint32_t bh[4], bl[4];
                uint32_t off = (uint32_t)((wn + nt * 16 + (lane & 7) + ((lane >> 4) << 3)) * RS
                                          + ks * 16 + ((lane >> 3) & 1) * 8) << 1;
                ldm4(bh, pBh + off); ldm4(bl, pBl + off);
                #pragma unroll
                for (int mt = 0; mt < 4; mt++)
                    #pragma unroll
                    for (int t = 0; t < 2; t++) {
                        float* c = acc[mt][nt * 2 + t];
                        mma_b16(c, ah[mt], bh + 2 * t);
                        mma_b16(c, ah[mt], bl + 2 * t);
                        mma_b16(c, al[mt], bh + 2 * t);
                    }
            }
        }
        __syncthreads();
    }

    #pragma unroll
    for (int mt = 0; mt < 4; mt++)
        #pragma unroll
        for (int nt = 0; nt < 4; nt++) {
            int r0 = m0 + wm + mt * 16 + (lane >> 2);
            int c  = n0 + wn + nt * 8 + ((lane & 3) << 1);
            float* a = acc[mt][nt];
            float b0 = bias[c], b1 = bias[c + 1];
            float v0 = a[0] + b0, v1 = a[1] + b1, v2 = a[2] + b0, v3 = a[3] + b1;
            if (res) {
                float2 q0 = *(const float2*)(res + (size_t)r0 * N + c);
                float2 q1 = *(const float2*)(res + (size_t)(r0 + 8) * N + c);
                v0 += q0.x; v1 += q0.y; v2 += q1.x; v3 += q1.y;
            }
            if (relu) {
                v0 = fmaxf(v0, 0.f); v1 = fmaxf(v1, 0.f);
                v2 = fmaxf(v2, 0.f); v3 = fmaxf(v3, 0.f);
            }
            if (Cf) {
                *(float2*)(Cf + (size_t)r0 * N + c)       = make_float2(v0, v1);
                *(float2*)(Cf + (size_t)(r0 + 8) * N + c) = make_float2(v2, v3);
            }
            if (Cbh) {
                uint32_t h0, l0, h1, l1;
                split_pack(v0, v1, h0, l0); split_pack(v2, v3, h1, l1);
                *(uint32_t*)(Cbh + (size_t)r0 * N + c) = h0;
                *(uint32_t*)(Cbl + (size_t)r0 * N + c) = l0;
                *(uint32_t*)(Cbh + (size_t)(r0 + 8) * N + c) = h1;
                *(uint32_t*)(Cbl + (size_t)(r0 + 8) * N + c) = l1;
            }
        }
}

// ---------------- fused HMMA flash attention (round-10 proven) -------------
__global__ __launch_bounds__(128, 4) void attn_mma(
    const bf16* __restrict__ qh, const bf16* __restrict__ ql,
    bf16* __restrict__ oh, bf16* __restrict__ ol)
{
    extern __shared__ __align__(16) bf16 smr[];
    const int tid = threadIdx.x, lane = tid & 31, wid = tid >> 5;
    const int bhn = blockIdx.y, b = bhn >> 3, h = bhn & 7;
    const int q0 = blockIdx.x << 7;
    const size_t base = (size_t)b * NN;
    const uint32_t sb = smem_u32(smr);
    const float SC = 0.17677669529663687f;

    #pragma unroll
    for (int i = 0; i < 8; i++) {
        int idx = tid + (i << 7);
        int pl = idx >> 9, rest = idx & 511;
        int r = rest >> 2, c8 = (rest & 3) << 3;
        uint32_t so = (uint32_t)(r * RS + c8) << 1;
        const bf16* src = (pl ? ql : qh) + (base + q0 + r) * 768 + h * 32 + c8;
        cp16(sb + pl * (2 * PLV) + so, src);
    }
    #pragma unroll
    for (int i = 0; i < 8; i++) {
        int idx = tid + (i << 7);
        int pl = idx >> 8, rest = idx & 255;
        int r = rest >> 2, c8 = (rest & 3) << 3;
        uint32_t so = (uint32_t)(r * RS + c8) << 1;
        int fo = (pl >> 1) ? 512 : 256;
        const bf16* src = ((pl & 1) ? ql : qh) + (base + r) * 768 + fo + h * 32 + c8;
        cp16(sb + 4 * PLV + pl * PLV + so, src);
    }
    CPCOMMIT();

    uint32_t qfh[2][2][4], qfl[2][2][4];
    float oacc[2][4][4];
    #pragma unroll
    for (int m = 0; m < 2; m++)
        #pragma unroll
        for (int a = 0; a < 4; a++)
            #pragma unroll
            for (int c = 0; c < 4; c++) oacc[m][a][c] = 0.f;
    float rs[2][2] = {{0.f, 0.f}, {0.f, 0.f}};

    CPWAIT(0);
    __syncthreads();
    #pragma unroll
    for (int mt = 0; mt < 2; mt++)
        #pragma unroll
        for (int ks = 0; ks < 2; ks++) {
            uint32_t off = (uint32_t)((wid * 32 + mt * 16 + (lane & 15)) * RS
                                      + ks * 16 + ((lane >> 4) << 3)) << 1;
            ldm4(qfh[mt][ks], sb + off);
            ldm4(qfl[mt][ks], sb + 2 * PLV + off);
        }
    __syncthreads();

    for (int s = 0; s < 16; s++) {
        if (s < 15) {
            const int kv0 = (s + 1) << 6;
            const uint32_t dstb = ((s + 1) & 1) ? sb : sb + 4 * PLV;
            #pragma unroll
            for (int i = 0; i < 8; i++) {
                int idx = tid + (i << 7);
                int pl = idx >> 8, rest = idx & 255;
                int r = rest >> 2, c8 = (rest & 3) << 3;
                uint32_t so = (uint32_t)(r * RS + c8) << 1;
                int fo = (pl >> 1) ? 512 : 256;
                const bf16* src = ((pl & 1) ? ql : qh) + (base + kv0 + r) * 768 + fo + h * 32 + c8;
                cp16(dstb + pl * PLV + so, src);
            }
            CPCOMMIT();
            CPWAIT(1);
        } else {
            CPWAIT(0);
        }
        __syncthreads();

        const uint32_t kH = (s & 1) ? sb : sb + 4 * PLV;
        const uint32_t kL = kH + PLV, vH = kH + 2 * PLV, vL = kH + 3 * PLV;

        #pragma unroll
        for (int kk = 0; kk < 4; kk++) {
            float sv[2][2][4];
            #pragma unroll
            for (int m = 0; m < 2; m++)
                #pragma unroll
                for (int t = 0; t < 2; t++)
                    #pragma unroll
                    for (int c = 0; c < 4; c++) sv[m][t][c] = 0.f;
            #pragma unroll
            for (int ks = 0; ks < 2; ks++) {
                uint32_t bh[4], bl[4];
                uint32_t off = (uint32_t)((kk * 16 + (lane & 7) + ((lane >> 4) << 3)) * RS
                                          + ks * 16 + ((lane >> 3) & 1) * 8) << 1;
                ldm4(bh, kH + off); ldm4(bl, kL + off);
                #pragma unroll
                for (int mt = 0; mt < 2; mt++)
                    #pragma unroll
                    for (int t = 0; t < 2; t++) {
                        float* c = sv[mt][t];
                        mma_b16(c, qfh[mt][ks], bh + 2 * t);
                        mma_b16(c, qfh[mt][ks], bl + 2 * t);
                        mma_b16(c, qfl[mt][ks], bh + 2 * t);
                    }
            }
            uint32_t va[4], vb[4], vc[4], vd[4];
            {
                uint32_t ro = kk * 16 + (lane & 7) + (((lane >> 3) & 1) << 3);
                uint32_t ofa = (uint32_t)(ro * RS + ((lane >> 4) << 3)) << 1;
                uint32_t ofb = (uint32_t)(ro * RS + 16 + ((lane >> 4) << 3)) << 1;
                ldm4t(va, vH + ofa); ldm4t(vb, vH + ofb);
                ldm4t(vc, vL + ofa); ldm4t(vd, vL + ofb);
            }
            #pragma unroll
            for (int mt = 0; mt < 2; mt++) {
                float e00 = __expf(sv[mt][0][0] * SC), e01 = __expf(sv[mt][0][1] * SC);
                float e02 = __expf(sv[mt][0][2] * SC), e03 = __expf(sv[mt][0][3] * SC);
                float e10 = __expf(sv[mt][1][0] * SC), e11 = __expf(sv[mt][1][1] * SC);
                float e12 = __expf(sv[mt][1][2] * SC), e13 = __expf(sv[mt][1][3] * SC);
                rs[mt][0] += e00 + e01 + e10 + e11;
                rs[mt][1] += e02 + e03 + e12 + e13;
                uint32_t pah[4], pal[4];
                split_pack(e00, e01, pah[0], pal[0]);
                split_pack(e02, e03, pah[1], pal[1]);
                split_pack(e10, e11, pah[2], pal[2]);
                split_pack(e12, e13, pah[3], pal[3]);
                float* o = (float*)oacc[mt];
                mma_b16(o + 0,  pah, va);     mma_b16(o + 0,  pah, vc);     mma_b16(o + 0,  pal, va);
                mma_b16(o + 4,  pah, va + 2); mma_b16(o + 4,  pah, vc + 2); mma_b16(o + 4,  pal, va + 2);
                mma_b16(o + 8,  pah, vb);     mma_b16(o + 8,  pah, vd);     mma_b16(o + 8,  pal, vb);
                mma_b16(o + 12, pah, vb + 2); mma_b16(o + 12, pah, vd + 2); mma_b16(o + 12, pal, vb + 2);
            }
        }
        __syncthreads();
    }

    #pragma unroll
    for (int mt = 0; mt < 2; mt++) {
        float r0 = rs[mt][0], r1 = rs[mt][1];
        r0 += __shfl_xor_sync(0xffffffffu, r0, 1);
        r0 += __shfl_xor_sync(0xffffffffu, r0, 2);
        r1 += __shfl_xor_sync(0xffffffffu, r1, 1);
        r1 += __shfl_xor_sync(0xffffffffu, r1, 2);
        const float i0 = 1.f / r0, i1 = 1.f / r1;
        #pragma unroll
        for (int nt = 0; nt < 4; nt++) {
            int row = q0 + wid * 32 + mt * 16 + (lane >> 2);
            int c   = h * 32 + nt * 8 + ((lane & 3) << 1);
            float v0 = oacc[mt][nt][0] * i0, v1 = oacc[mt][nt][1] * i0;
            float v2 = oacc[mt][nt][2] * i1, v3 = oacc[mt][nt][3] * i1;
            uint32_t h0, l0, h1, l1;
            split_pack(v0, v1, h0, l0); split_pack(v2, v3, h1, l1);
            *(uint32_t*)(oh + (base + row) * HH + c) = h0;
            *(uint32_t*)(ol + (base + row) * HH + c) = l0;
            *(uint32_t*)(oh + (base + row + 8) * HH + c) = h1;
            *(uint32_t*)(ol + (base + row + 8) * HH + c) = l1;
        }
    }
}

// ---------------- LayerNorm: fp32 in -> fp32 + bf16 hi/lo ----------------
__global__ __launch_bounds__(256) void ln_kernel(
    const float* __restrict__ x, const float* __restrict__ gam,
    const float* __restrict__ bet, float* __restrict__ out,
    bf16* __restrict__ ohp, bf16* __restrict__ olp)
{
    const int row = blockIdx.x * 8 + (threadIdx.x >> 5);
    const int lane = threadIdx.x & 31;
    const float* xr = x + (size_t)row * HH;
    float v[8], sum = 0.f;
    #pragma unroll
    for (int i = 0; i < 8; i++) { v[i] = xr[lane + i * 32]; sum += v[i]; }
    #pragma unroll
    for (int o = 16; o; o >>= 1) sum += __shfl_xor_sync(0xffffffffu, sum, o);
    const float mean = sum * (1.f / HH);
    float var = 0.f;
    #pragma unroll
    for (int i = 0; i < 8; i++) { float d = v[i] - mean; var += d * d; }
    #pragma unroll
    for (int o = 16; o; o >>= 1) var += __shfl_xor_sync(0xffffffffu, var, o);
    const float inv = rsqrtf(var * (1.f / HH) + 1e-5f);
    #pragma unroll
    for (int i = 0; i < 8; i++) {
        const int c = lane + i * 32;
        float val = (v[i] - mean) * inv * gam[c] + bet[c];
        out[(size_t)row * HH + c] = val;
        bf16 hb = __float2bfloat16(val);
        ohp[(size_t)row * HH + c] = hb;
        olp[(size_t)row * HH + c] = __float2bfloat16(val - __bfloat162float(hb));
    }
}

// ---------------- fallback init (only for unexpected out_size) -------------
__global__ void init_out_kernel(float* __restrict__ out, int out_size)
{
    const int i = blockIdx.x * 256 + threadIdx.x;
    if (i < out_size) out[i] = 0.f;
}

// ---------------- allocation (1024 threads, fused output init) -------------
__global__ __launch_bounds__(1024) void alloc_kernel(
    const float* __restrict__ enc, const int* __restrict__ sel,
    const float* __restrict__ Wc, const float* __restrict__ bc,
    float* __restrict__ outf, int both)
{
    __shared__ float part_s[4][HH];
    __shared__ float mean_s[HH], ctx_s[HH];
    __shared__ float sc_s[KKc];
    __shared__ float red_s[1024];
    __shared__ int   idx_s[KKc];
    __shared__ int   cnt_s[4];

    const int b = blockIdx.x, tid = threadIdx.x;
    float* bw = both ? (outf + BB * KKc) : outf;

    if (tid < KKc) idx_s[tid] = sel[b * KKc + tid];
    bw[b * NN + tid] = 0.f;
    __syncthreads();
    if (both && tid < KKc) outf[b * KKc + tid] = (float)idx_s[tid];

    const int c = tid & 255, grp = tid >> 8;
    {
        float acc = 0.f; int cnt = 0;
        const int kb = grp << 7;
        #pragma unroll 4
        for (int k = kb; k < kb + 128; k++) {
            const int idx = idx_s[k];
            if (idx < NN) { acc += enc[((size_t)b * NN + idx) * HH + c]; cnt++; }
        }
        part_s[grp][c] = acc;
        if (c == 0) cnt_s[grp] = cnt;
    }
    __syncthreads();
    const int cntT = cnt_s[0] + cnt_s[1] + cnt_s[2] + cnt_s[3];
    if (tid < HH)
        mean_s[tid] = ((part_s[0][tid] + part_s[1][tid]) + (part_s[2][tid] + part_s[3][tid]))
                      / (float)(cntT > 0 ? cntT : 1);
    __syncthreads();

    {
        float p = 0.f;
        const int ib = grp << 6;
        #pragma unroll 4
        for (int i = ib; i < ib + 64; i++) p += mean_s[i] * Wc[i * HH + c];
        part_s[grp][c] = p;
    }
    __syncthreads();
    if (tid < HH)
        ctx_s[tid] = ((part_s[0][tid] + part_s[1][tid]) + (part_s[2][tid] + part_s[3][tid]))
                     + bc[tid];
    __syncthreads();

    const int wid = tid >> 5, lane = tid & 31;
    for (int k = wid; k < KKc; k += 32) {
        const int idx = idx_s[k];
        float s = -1e30f;
        if (idx < NN) {
            const float* row = enc + ((size_t)b * NN + idx) * HH;
            float part = 0.f;
            #pragma unroll
            for (int i = 0; i < 8; i++) part += ctx_s[lane + i * 32] * row[lane + i * 32];
            #pragma unroll
            for (int o = 16; o; o >>= 1) part += __shfl_xor_sync(0xffffffffu, part, o);
            s = part;
        }
        if (lane == 0) sc_s[k] = s;
    }
    __syncthreads();

    red_s[tid] = (tid < KKc) ? sc_s[tid] : -1e30f;
    __syncthreads();
    for (int st = 512; st; st >>= 1) {
        if (tid < st) red_s[tid] = fmaxf(red_s[tid], red_s[tid + st]);
        __syncthreads();
    }
    const float m = red_s[0];
    __syncthreads();

    const int myidx = (tid < KKc) ? idx_s[tid] : NN;
    const float e = (myidx < NN) ? expf(sc_s[tid] - m) : 0.f;
    red_s[tid] = e;
    __syncthreads();
    for (int st = 512; st; st >>= 1) {
        if (tid < st) red_s[tid] += red_s[tid + st];
        __syncthreads();
    }
    const float denom = red_s[0];
    __syncthreads();

    float a = rintf(e / denom * 100.f);
    red_s[tid] = a;
    __syncthreads();
    for (int st = 512; st; st >>= 1) {
        if (tid < st) red_s[tid] += red_s[tid + st];
        __syncthreads();
    }
    const float diff = 100.f - red_s[0];
    __syncthreads();

    if (tid == 0 && myidx < NN) a += diff;
    if (myidx < NN) bw[b * NN + myidx] = a;
}

// ---------------- launch ----------------
extern "C" void kernel_launch(void* const* d_in, const int* in_sizes, int n_in,
                              void* d_out, int out_size)
{
    const float* x    = (const float*)d_in[0];
    const int*   sel  = (const int*)  d_in[1];
    const float* W_in = (const float*)d_in[2];
    const float* b_in = (const float*)d_in[3];
    const float* Wqkv = (const float*)d_in[4];
    const float* bqkv = (const float*)d_in[5];
    const float* Wo   = (const float*)d_in[6];
    const float* bo   = (const float*)d_in[7];
    const float* ln1g = (const float*)d_in[8];
    const float* ln1b = (const float*)d_in[9];
    const float* W1   = (const float*)d_in[10];
    const float* b1   = (const float*)d_in[11];
    const float* W2   = (const float*)d_in[12];
    const float* b2   = (const float*)d_in[13];
    const float* ln2g = (const float*)d_in[14];
    const float* ln2b = (const float*)d_in[15];
    const float* Wc   = (const float*)d_in[16];
    const float* bc   = (const float*)d_in[17];

    float *h, *tmp;
    bf16 *xh, *xl, *hbh, *hbl, *qh, *ql, *ah, *al, *fh, *fl, *wh, *wl;
    cudaGetSymbolAddress((void**)&h,   g_h);   cudaGetSymbolAddress((void**)&tmp, g_tmp);
    cudaGetSymbolAddress((void**)&xh,  g_xh);  cudaGetSymbolAddress((void**)&xl,  g_xl);
    cudaGetSymbolAddress((void**)&hbh, g_hbh); cudaGetSymbolAddress((void**)&hbl, g_hbl);
    cudaGetSymbolAddress((void**)&qh,  g_qh);  cudaGetSymbolAddress((void**)&ql,  g_ql);
    cudaGetSymbolAddress((void**)&ah,  g_ah);  cudaGetSymbolAddress((void**)&al,  g_al);
    cudaGetSymbolAddress((void**)&fh,  g_fh);  cudaGetSymbolAddress((void**)&fl,  g_fl);
    cudaGetSymbolAddress((void**)&wh,  g_wh);  cudaGetSymbolAddress((void**)&wl,  g_wl);

    const int GSM = 8 * PLB;     // 81920
    const int ASM_ = 8 * PLV;    // 40960
    cudaFuncSetAttribute(gemm_mma, cudaFuncAttributeMaxDynamicSharedMemorySize, GSM);
    cudaFuncSetAttribute(attn_mma, cudaFuncAttributeMaxDynamicSharedMemorySize, ASM_);

    Segs S;
    S.seg[0] = { x, xh, xl, 0, 0, 1, (TOK * DIN) / 1024 };
    S.seg[1] = { W_in, wh + WOFF_IN, wl + WOFF_IN, DIN, HH, 0, (DIN/32)*(HH/32) };
    for (int l = 0; l < LL; l++) {
        S.seg[2+l] = { Wqkv + (size_t)l*HH*3*HH, wh + WOFF_QKV + l*HH*3*HH,
                       wl + WOFF_QKV + l*HH*3*HH, HH, 3*HH, 0, (HH/32)*(3*HH/32) };
        S.seg[4+l] = { Wo + (size_t)l*HH*HH, wh + WOFF_O + l*HH*HH,
                       wl + WOFF_O + l*HH*HH, HH, HH, 0, (HH/32)*(HH/32) };
        S.seg[6+l] = { W1 + (size_t)l*HH*FF, wh + WOFF_1 + l*HH*FF,
                       wl + WOFF_1 + l*HH*FF, HH, FF, 0, (HH/32)*(FF/32) };
        S.seg[8+l] = { W2 + (size_t)l*FF*HH, wh + WOFF_2 + l*FF*HH,
                       wl + WOFF_2 + l*FF*HH, FF, HH, 0, (FF/32)*(HH/32) };
    }
    prep_kernel<<<dim3(1024, 10), dim3(32, 8)>>>(S);

    gemm_mma<<<dim3(HH/128, TOK/128), 256, GSM>>>(
        xh, xl, wh + WOFF_IN, wl + WOFF_IN, b_in, nullptr, h, hbh, hbl, DIN, HH, 0);

    for (int l = 0; l < LL; l++) {
        gemm_mma<<<dim3(3*HH/128, TOK/128), 256, GSM>>>(
            hbh, hbl, wh + WOFF_QKV + l*HH*3*HH, wl + WOFF_QKV + l*HH*3*HH,
            bqkv + l*3*HH, nullptr, nullptr, qh, ql, HH, 3*HH, 0);
        attn_mma<<<dim3(NN/128, BB*8), 128, ASM_>>>(qh, ql, ah, al);
        gemm_mma<<<dim3(HH/128, TOK/128), 256, GSM>>>(
            ah, al, wh + WOFF_O + l*HH*HH, wl + WOFF_O + l*HH*HH,
            bo + l*HH, h, tmp, nullptr, nullptr, HH, HH, 0);
        ln_kernel<<<TOK/8, 256>>>(tmp, ln1g + l*HH, ln1b + l*HH, h, hbh, hbl);
        gemm_mma<<<dim3(FF/128, TOK/128), 256, GSM>>>(
            hbh, hbl, wh + WOFF_1 + l*HH*FF, wl + WOFF_1 + l*HH*FF,
            b1 + l*FF, nullptr, nullptr, fh, fl, HH, FF, 1);
        gemm_mma<<<dim3(HH/128, TOK/128), 256, GSM>>>(
            fh, fl, wh + WOFF_2 + l*FF*HH, wl + WOFF_2 + l*FF*HH,
            b2 + l*HH, h, tmp, nullptr, nullptr, FF, HH, 0);
        ln_kernel<<<TOK/8, 256>>>(tmp, ln2g + l*HH, ln2b + l*HH, h, hbh, hbl);
    }

    float* outf = (float*)d_out;
    const int idx_elems = BB * KKc, bw_elems = BB * NN;
    const int both = (out_size >= idx_elems + bw_elems) ? 1 : 0;

    const int covered = both ? (idx_elems + bw_elems) : bw_elems;
    if (out_size > covered)
        init_out_kernel<<<(out_size + 255) / 256, 256>>>(outf, out_size);

    alloc_kernel<<<BB, 1024>>>(h, sel, Wc, bc, outf, both);
}

// round 13
// speedup vs baseline: 3.7456x; 1.0205x over previous
#include <cuda_runtime.h>
#include <cuda_bf16.h>
#include <cstdint>

#define BB 16
#define NN 1024
#define KKc 512
#define DIN 64
#define HH 256
#define FF 1024
#define LL 2
#define TOK (BB*NN)

typedef __nv_bfloat16 bf16;

#define WOFF_IN 0
#define WOFF_QKV (WOFF_IN + DIN*HH)
#define WOFF_O (WOFF_QKV + LL*HH*3*HH)
#define WOFF_1 (WOFF_O + LL*HH*HH)
#define WOFF_2 (WOFF_1 + LL*HH*FF)
#define WTOT (WOFF_2 + LL*FF*HH)

__device__ __align__(16) float g_h[TOK*HH], g_tmp[TOK*HH];
__device__ __align__(16) bf16 g_xh[TOK*DIN], g_xl[TOK*DIN];
__device__ __align__(16) bf16 g_hbh[TOK*HH], g_hbl[TOK*HH];
__device__ __align__(16) bf16 g_qh[TOK*768], g_ql[TOK*768];
__device__ __align__(16) bf16 g_ah[TOK*HH], g_al[TOK*HH];
__device__ __align__(16) bf16 g_fh[TOK*FF], g_fl[TOK*FF];
__device__ __align__(16) bf16 g_wh[WTOT], g_wl[WTOT];

// ---------------- helpers ----------------
__device__ __forceinline__ uint32_t smem_u32(const void* p) {
    uint32_t a;
    asm("{ .reg .u64 t; cvta.to.shared.u64 t, %1; cvt.u32.u64 %0, t; }" : "=r"(a) : "l"(p));
    return a;
}
__device__ __forceinline__ void cp16(uint32_t d, const void* s) {
    asm volatile("cp.async.cg.shared.global [%0], [%1], 16;" :: "r"(d), "l"(s));
}
#define CPCOMMIT() asm volatile("cp.async.commit_group;" ::: "memory")
#define CPWAIT(n)  asm volatile("cp.async.wait_group %0;" :: "n"(n) : "memory")

__device__ __forceinline__ void ldm4(uint32_t* r, uint32_t a) {
    asm volatile("ldmatrix.sync.aligned.m8n8.x4.shared.b16 {%0,%1,%2,%3}, [%4];"
                 : "=r"(r[0]), "=r"(r[1]), "=r"(r[2]), "=r"(r[3]) : "r"(a));
}
__device__ __forceinline__ void ldm4t(uint32_t* r, uint32_t a) {
    asm volatile("ldmatrix.sync.aligned.m8n8.x4.trans.shared.b16 {%0,%1,%2,%3}, [%4];"
                 : "=r"(r[0]), "=r"(r[1]), "=r"(r[2]), "=r"(r[3]) : "r"(a));
}
__device__ __forceinline__ void mma_b16(float* c, const uint32_t* a, const uint32_t* b) {
    asm volatile("mma.sync.aligned.m16n8k16.row.col.f32.bf16.bf16.f32 "
                 "{%0,%1,%2,%3},{%4,%5,%6,%7},{%8,%9},{%0,%1,%2,%3};"
                 : "+f"(c[0]), "+f"(c[1]), "+f"(c[2]), "+f"(c[3])
                 : "r"(a[0]), "r"(a[1]), "r"(a[2]), "r"(a[3]), "r"(b[0]), "r"(b[1]));
}
__device__ __forceinline__ uint32_t bf2(float lo, float hi) {
    uint32_t r;
    asm("cvt.rn.bf16x2.f32 %0, %1, %2;" : "=r"(r) : "f"(hi), "f"(lo));
    return r;
}
__device__ __forceinline__ void split_pack(float a, float b, uint32_t& hi, uint32_t& lo) {
    float ah = __bfloat162float(__float2bfloat16(a));
    float bh = __bfloat162float(__float2bfloat16(b));
    hi = bf2(ah, bh); lo = bf2(a - ah, b - bh);
}

#define RS 40        // smem row stride (bf16): 80B, conflict-free ldmatrix
#define PLB 10240    // 128-row plane bytes (128*RS*2)
#define PLV 5120     // 64-row plane bytes (64*RS*2)

// ---------------- prep: weight transpose/split + x split ----------------
struct Seg { const float* s; bf16 *dh, *dl; int K, N, mode, ntiles; };
struct Segs { Seg seg[10]; };

__global__ void prep_kernel(Segs S) {
    Seg sg = S.seg[blockIdx.y];
    if ((int)blockIdx.x >= sg.ntiles) return;
    const int tx = threadIdx.x, ty = threadIdx.y;
    if (sg.mode == 1) {
        int off = blockIdx.x * 1024 + ty * 128 + tx * 4;
        float4 v = *(const float4*)(sg.s + off);
        float a[4] = {v.x, v.y, v.z, v.w};
        #pragma unroll
        for (int i = 0; i < 4; i++) {
            bf16 h = __float2bfloat16(a[i]);
            sg.dh[off + i] = h;
            sg.dl[off + i] = __float2bfloat16(a[i] - __bfloat162float(h));
        }
    } else {
        __shared__ float tile[32][33];
        int kt = blockIdx.x % (sg.K / 32), nt = blockIdx.x / (sg.K / 32);
        int k0 = kt * 32, n0 = nt * 32;
        #pragma unroll
        for (int i = 0; i < 4; i++)
            tile[ty * 4 + i][tx] = sg.s[(size_t)(k0 + ty * 4 + i) * sg.N + n0 + tx];
        __syncthreads();
        #pragma unroll
        for (int i = 0; i < 4; i++) {
            float v = tile[tx][ty * 4 + i];
            bf16 h = __float2bfloat16(v);
            size_t d = (size_t)(n0 + ty * 4 + i) * sg.K + k0 + tx;
            sg.dh[d] = h;
            sg.dl[d] = __float2bfloat16(v - __bfloat162float(h));
        }
    }
}

// ---------------- split-bf16 HMMA GEMM, 128x128 block, 64x32 warp, 256 thr --
// Single __syncthreads per stage. smem planes @ (p*2+buf)*PLB. 80KB -> 2 CTA/SM.
__global__ __launch_bounds__(256, 2) void gemm_mma(
    const bf16* __restrict__ Ah, const bf16* __restrict__ Al,
    const bf16* __restrict__ Bh, const bf16* __restrict__ Bl,
    const float* __restrict__ bias, const float* __restrict__ res,
    float* __restrict__ Cf, bf16* __restrict__ Cbh, bf16* __restrict__ Cbl,
    int K, int N, int relu)
{
    extern __shared__ __align__(16) bf16 smr[];
    const int tid = threadIdx.x, lane = tid & 31, wid = tid >> 5;
    const int m0 = blockIdx.y << 7, n0 = blockIdx.x << 7;
    const int wm = (wid & 1) << 6, wn = (wid >> 1) << 5;
    const uint32_t sb = smem_u32(smr);
    const uint32_t sbA = sb, sbAl = sb + 2 * PLB;
    const uint32_t sbB = sb + 4 * PLB, sbBl = sb + 6 * PLB;

    float acc[4][4][4];
    #pragma unroll
    for (int a = 0; a < 4; a++)
        #pragma unroll
        for (int b = 0; b < 4; b++)
            #pragma unroll
            for (int c = 0; c < 4; c++) acc[a][b][c] = 0.f;

    const int nst = K >> 5;

    // prologue: stage 0
    {
        #pragma unroll
        for (int i = 0; i < 4; i++) {
            int idx = tid + (i << 8);
            int pl = idx >> 9, rest = idx & 511;
            int r = rest >> 2, c8 = (rest & 3) << 3;
            uint32_t so = (uint32_t)(r * RS + c8) << 1;
            cp16((pl ? sbAl : sbA) + so, (pl ? Al : Ah) + (size_t)(m0 + r) * K + c8);
        }
        #pragma unroll
        for (int i = 0; i < 4; i++) {
            int idx = tid + (i << 8);
            int pl = idx >> 9, rest = idx & 511;
            int r = rest >> 2, c8 = (rest & 3) << 3;
            uint32_t so = (uint32_t)(r * RS + c8) << 1;
            cp16((pl ? sbBl : sbB) + so, (pl ? Bl : Bh) + (size_t)(n0 + r) * K + c8);
        }
        CPCOMMIT();
    }

    #pragma unroll 1
    for (int s = 0; s < nst; s++) {
        CPWAIT(0);
        __syncthreads();      // publishes buffer s; compute s-1 done (prev iter)
        if (s + 1 < nst) {    // issue s+1 into buffer (s+1)&1 (read by compute s-1)
            const int k0 = (s + 1) << 5, buf = (s + 1) & 1;
            #pragma unroll
            for (int i = 0; i < 4; i++) {
                int idx = tid + (i << 8);
                int pl = idx >> 9, rest = idx & 511;
                int r = rest >> 2, c8 = (rest & 3) << 3;
                uint32_t so = (uint32_t)(r * RS + c8) << 1;
                cp16((pl ? sbAl : sbA) + buf * PLB + so,
                     (pl ? Al : Ah) + (size_t)(m0 + r) * K + k0 + c8);
            }
            #pragma unroll
            for (int i = 0; i < 4; i++) {
                int idx = tid + (i << 8);
                int pl = idx >> 9, rest = idx & 511;
                int r = rest >> 2, c8 = (rest & 3) << 3;
                uint32_t so = (uint32_t)(r * RS + c8) << 1;
                cp16((pl ? sbBl : sbB) + buf * PLB + so,
                     (pl ? Bl : Bh) + (size_t)(n0 + r) * K + k0 + c8);
            }
            CPCOMMIT();
        }

        const int buf = s & 1;
        const uint32_t pAh = sbA + buf * PLB, pAl = sbAl + buf * PLB;
        const uint32_t pBh = sbB + buf * PLB, pBl = sbBl + buf * PLB;
        #pragma unroll
        for (int ks = 0; ks < 2; ks++) {
            uint32_t ah[4][4], al[4][4];
            #pragma unroll
            for (int mt = 0; mt < 4; mt++) {
                uint32_t off = (uint32_t)((wm + mt * 16 + (lane & 15)) * RS
                                          + ks * 16 + ((lane >> 4) << 3)) << 1;
                ldm4(ah[mt], pAh + off); ldm4(al[mt], pAl + off);
            }
            #pragma unroll
            for (int nt = 0; nt < 2; nt++) {
                uint32_t bh[4], bl[4];
                uint32_t off = (uint32_t)((wn + nt * 16 + (lane & 7) + ((lane >> 4) << 3)) * RS
                                          + ks * 16 + ((lane >> 3) & 1) * 8) << 1;
                ldm4(bh, pBh + off); ldm4(bl, pBl + off);
                #pragma unroll
                for (int mt = 0; mt < 4; mt++)
                    #pragma unroll
                    for (int t = 0; t < 2; t++) {
                        float* c = acc[mt][nt * 2 + t];
                        mma_b16(c, ah[mt], bh + 2 * t);
                        mma_b16(c, ah[mt], bl + 2 * t);
                        mma_b16(c, al[mt], bh + 2 * t);
                    }
            }
        }
    }

    #pragma unroll
    for (int mt = 0; mt < 4; mt++)
        #pragma unroll
        for (int nt = 0; nt < 4; nt++) {
            int r0 = m0 + wm + mt * 16 + (lane >> 2);
            int c  = n0 + wn + nt * 8 + ((lane & 3) << 1);
            float* a = acc[mt][nt];
            float b0 = bias[c], b1 = bias[c + 1];
            float v0 = a[0] + b0, v1 = a[1] + b1, v2 = a[2] + b0, v3 = a[3] + b1;
            if (res) {
                float2 q0 = *(const float2*)(res + (size_t)r0 * N + c);
                float2 q1 = *(const float2*)(res + (size_t)(r0 + 8) * N + c);
                v0 += q0.x; v1 += q0.y; v2 += q1.x; v3 += q1.y;
            }
            if (relu) {
                v0 = fmaxf(v0, 0.f); v1 = fmaxf(v1, 0.f);
                v2 = fmaxf(v2, 0.f); v3 = fmaxf(v3, 0.f);
            }
            if (Cf) {
                *(float2*)(Cf + (size_t)r0 * N + c)       = make_float2(v0, v1);
                *(float2*)(Cf + (size_t)(r0 + 8) * N + c) = make_float2(v2, v3);
            }
            if (Cbh) {
                uint32_t h0, l0, h1, l1;
                split_pack(v0, v1, h0, l0); split_pack(v2, v3, h1, l1);
                *(uint32_t*)(Cbh + (size_t)r0 * N + c) = h0;
                *(uint32_t*)(Cbl + (size_t)r0 * N + c) = l0;
                *(uint32_t*)(Cbh + (size_t)(r0 + 8) * N + c) = h1;
                *(uint32_t*)(Cbl + (size_t)(r0 + 8) * N + c) = l1;
            }
        }
}

// ---------------- fused HMMA flash attention, single sync per stage --------
__global__ __launch_bounds__(128, 4) void attn_mma(
    const bf16* __restrict__ qh, const bf16* __restrict__ ql,
    bf16* __restrict__ oh, bf16* __restrict__ ol)
{
    extern __shared__ __align__(16) bf16 smr[];
    const int tid = threadIdx.x, lane = tid & 31, wid = tid >> 5;
    const int bhn = blockIdx.y, b = bhn >> 3, h = bhn & 7;
    const int q0 = blockIdx.x << 7;
    const size_t base = (size_t)b * NN;
    const uint32_t sb = smem_u32(smr);
    const float SC = 0.17677669529663687f;

    // prologue: Q planes into [0,4*PLV) + KV stage 0 into buf0 @ 4*PLV
    #pragma unroll
    for (int i = 0; i < 8; i++) {
        int idx = tid + (i << 7);
        int pl = idx >> 9, rest = idx & 511;
        int r = rest >> 2, c8 = (rest & 3) << 3;
        uint32_t so = (uint32_t)(r * RS + c8) << 1;
        const bf16* src = (pl ? ql : qh) + (base + q0 + r) * 768 + h * 32 + c8;
        cp16(sb + pl * (2 * PLV) + so, src);
    }
    #pragma unroll
    for (int i = 0; i < 8; i++) {
        int idx = tid + (i << 7);
        int pl = idx >> 8, rest = idx & 255;
        int r = rest >> 2, c8 = (rest & 3) << 3;
        uint32_t so = (uint32_t)(r * RS + c8) << 1;
        int fo = (pl >> 1) ? 512 : 256;
        const bf16* src = ((pl & 1) ? ql : qh) + (base + r) * 768 + fo + h * 32 + c8;
        cp16(sb + 4 * PLV + pl * PLV + so, src);
    }
    CPCOMMIT();

    uint32_t qfh[2][2][4], qfl[2][2][4];
    float oacc[2][4][4];
    #pragma unroll
    for (int m = 0; m < 2; m++)
        #pragma unroll
        for (int a = 0; a < 4; a++)
            #pragma unroll
            for (int c = 0; c < 4; c++) oacc[m][a][c] = 0.f;
    float rs[2][2] = {{0.f, 0.f}, {0.f, 0.f}};

    CPWAIT(0);
    __syncthreads();
    #pragma unroll
    for (int mt = 0; mt < 2; mt++)
        #pragma unroll
        for (int ks = 0; ks < 2; ks++) {
            uint32_t off = (uint32_t)((wid * 32 + mt * 16 + (lane & 15)) * RS
                                      + ks * 16 + ((lane >> 4) << 3)) << 1;
            ldm4(qfh[mt][ks], sb + off);
            ldm4(qfl[mt][ks], sb + 2 * PLV + off);
        }

    for (int s = 0; s < 16; s++) {
        if (s > 0) CPWAIT(0);
        __syncthreads();   // s=0: Q-frag reads done before buf1 write; s>0: publish stage s + reuse guard
        if (s < 15) {
            const int kv0 = (s + 1) << 6;
            const uint32_t dstb = ((s + 1) & 1) ? sb : sb + 4 * PLV;
            #pragma unroll
            for (int i = 0; i < 8; i++) {
                int idx = tid + (i << 7);
                int pl = idx >> 8, rest = idx & 255;
                int r = rest >> 2, c8 = (rest & 3) << 3;
                uint32_t so = (uint32_t)(r * RS + c8) << 1;
                int fo = (pl >> 1) ? 512 : 256;
                const bf16* src = ((pl & 1) ? ql : qh) + (base + kv0 + r) * 768 + fo + h * 32 + c8;
                cp16(dstb + pl * PLV + so, src);
            }
            CPCOMMIT();
        }

        const uint32_t kH = (s & 1) ? sb : sb + 4 * PLV;
        const uint32_t kL = kH + PLV, vH = kH + 2 * PLV, vL = kH + 3 * PLV;

        #pragma unroll
        for (int kk = 0; kk < 4; kk++) {
            float sv[2][2][4];
            #pragma unroll
            for (int m = 0; m < 2; m++)
                #pragma unroll
                for (int t = 0; t < 2; t++)
                    #pragma unroll
                    for (int c = 0; c < 4; c++) sv[m][t][c] = 0.f;
            #pragma unroll
            for (int ks = 0; ks < 2; ks++) {
                uint32_t bh[4], bl[4];
                uint32_t off = (uint32_t)((kk * 16 + (lane & 7) + ((lane >> 4) << 3)) * RS
                                          + ks * 16 + ((lane >> 3) & 1) * 8) << 1;
                ldm4(bh, kH + off); ldm4(bl, kL + off);
                #pragma unroll
                for (int mt = 0; mt < 2; mt++)
                    #pragma unroll
                    for (int t = 0; t < 2; t++) {
                        float* c = sv[mt][t];
                        mma_b16(c, qfh[mt][ks], bh + 2 * t);
                        mma_b16(c, qfh[mt][ks], bl + 2 * t);
                        mma_b16(c, qfl[mt][ks], bh + 2 * t);
                    }
            }
            uint32_t va[4], vb[4], vc[4], vd[4];
            {
                uint32_t ro = kk * 16 + (lane & 7) + (((lane >> 3) & 1) << 3);
                uint32_t ofa = (uint32_t)(ro * RS + ((lane >> 4) << 3)) << 1;
                uint32_t ofb = (uint32_t)(ro * RS + 16 + ((lane >> 4) << 3)) << 1;
                ldm4t(va, vH + ofa); ldm4t(vb, vH + ofb);
                ldm4t(vc, vL + ofa); ldm4t(vd, vL + ofb);
            }
            #pragma unroll
            for (int mt = 0; mt < 2; mt++) {
                float e00 = __expf(sv[mt][0][0] * SC), e01 = __expf(sv[mt][0][1] * SC);
                float e02 = __expf(sv[mt][0][2] * SC), e03 = __expf(sv[mt][0][3] * SC);
                float e10 = __expf(sv[mt][1][0] * SC), e11 = __expf(sv[mt][1][1] * SC);
                float e12 = __expf(sv[mt][1][2] * SC), e13 = __expf(sv[mt][1][3] * SC);
                rs[mt][0] += e00 + e01 + e10 + e11;
                rs[mt][1] += e02 + e03 + e12 + e13;
                uint32_t pah[4], pal[4];
                split_pack(e00, e01, pah[0], pal[0]);
                split_pack(e02, e03, pah[1], pal[1]);
                split_pack(e10, e11, pah[2], pal[2]);
                split_pack(e12, e13, pah[3], pal[3]);
                float* o = (float*)oacc[mt];
                mma_b16(o + 0,  pah, va);     mma_b16(o + 0,  pah, vc);     mma_b16(o + 0,  pal, va);
                mma_b16(o + 4,  pah, va + 2); mma_b16(o + 4,  pah, vc + 2); mma_b16(o + 4,  pal, va + 2);
                mma_b16(o + 8,  pah, vb);     mma_b16(o + 8,  pah, vd);     mma_b16(o + 8,  pal, vb);
                mma_b16(o + 12, pah, vb + 2); mma_b16(o + 12, pah, vd + 2); mma_b16(o + 12, pal, vb + 2);
            }
        }
    }

    #pragma unroll
    for (int mt = 0; mt < 2; mt++) {
        float r0 = rs[mt][0], r1 = rs[mt][1];
        r0 += __shfl_xor_sync(0xffffffffu, r0, 1);
        r0 += __shfl_xor_sync(0xffffffffu, r0, 2);
        r1 += __shfl_xor_sync(0xffffffffu, r1, 1);
        r1 += __shfl_xor_sync(0xffffffffu, r1, 2);
        const float i0 = 1.f / r0, i1 = 1.f / r1;
        #pragma unroll
        for (int nt = 0; nt < 4; nt++) {
            int row = q0 + wid * 32 + mt * 16 + (lane >> 2);
            int c   = h * 32 + nt * 8 + ((lane & 3) << 1);
            float v0 = oacc[mt][nt][0] * i0, v1 = oacc[mt][nt][1] * i0;
            float v2 = oacc[mt][nt][2] * i1, v3 = oacc[mt][nt][3] * i1;
            uint32_t h0, l0, h1, l1;
            split_pack(v0, v1, h0, l0); split_pack(v2, v3, h1, l1);
            *(uint32_t*)(oh + (base + row) * HH + c) = h0;
            *(uint32_t*)(ol + (base + row) * HH + c) = l0;
            *(uint32_t*)(oh + (base + row + 8) * HH + c) = h1;
            *(uint32_t*)(ol + (base + row + 8) * HH + c) = l1;
        }
    }
}

// ---------------- LayerNorm: fp32 in -> fp32 + bf16 hi/lo ----------------
__global__ __launch_bounds__(256) void ln_kernel(
    const float* __restrict__ x, const float* __restrict__ gam,
    const float* __restrict__ bet, float* __restrict__ out,
    bf16* __restrict__ ohp, bf16* __restrict__ olp)
{
    const int row = blockIdx.x * 8 + (threadIdx.x >> 5);
    const int lane = threadIdx.x & 31;
    const float* xr = x + (size_t)row * HH;
    float v[8], sum = 0.f;
    #pragma unroll
    for (int i = 0; i < 8; i++) { v[i] = xr[lane + i * 32]; sum += v[i]; }
    #pragma unroll
    for (int o = 16; o; o >>= 1) sum += __shfl_xor_sync(0xffffffffu, sum, o);
    const float mean = sum * (1.f / HH);
    float var = 0.f;
    #pragma unroll
    for (int i = 0; i < 8; i++) { float d = v[i] - mean; var += d * d; }
    #pragma unroll
    for (int o = 16; o; o >>= 1) var += __shfl_xor_sync(0xffffffffu, var, o);
    const float inv = rsqrtf(var * (1.f / HH) + 1e-5f);
    #pragma unroll
    for (int i = 0; i < 8; i++) {
        const int c = lane + i * 32;
        float val = (v[i] - mean) * inv * gam[c] + bet[c];
        out[(size_t)row * HH + c] = val;
        bf16 hb = __float2bfloat16(val);
        ohp[(size_t)row * HH + c] = hb;
        olp[(size_t)row * HH + c] = __float2bfloat16(val - __bfloat162float(hb));
    }
}

// ---------------- fallback init (only for unexpected out_size) -------------
__global__ void init_out_kernel(float* __restrict__ out, int out_size)
{
    const int i = blockIdx.x * 256 + threadIdx.x;
    if (i < out_size) out[i] = 0.f;
}

// ---------------- allocation (1024 threads, fused output init) -------------
__global__ __launch_bounds__(1024) void alloc_kernel(
    const float* __restrict__ enc, const int* __restrict__ sel,
    const float* __restrict__ Wc, const float* __restrict__ bc,
    float* __restrict__ outf, int both)
{
    __shared__ float part_s[4][HH];
    __shared__ float mean_s[HH], ctx_s[HH];
    __shared__ float sc_s[KKc];
    __shared__ float red_s[1024];
    __shared__ int   idx_s[KKc];
    __shared__ int   cnt_s[4];

    const int b = blockIdx.x, tid = threadIdx.x;
    float* bw = both ? (outf + BB * KKc) : outf;

    if (tid < KKc) idx_s[tid] = sel[b * KKc + tid];
    bw[b * NN + tid] = 0.f;
    __syncthreads();
    if (both && tid < KKc) outf[b * KKc + tid] = (float)idx_s[tid];

    const int c = tid & 255, grp = tid >> 8;
    {
        float acc = 0.f; int cnt = 0;
        const int kb = grp << 7;
        #pragma unroll 4
        for (int k = kb; k < kb + 128; k++) {
            const int idx = idx_s[k];
            if (idx < NN) { acc += enc[((size_t)b * NN + idx) * HH + c]; cnt++; }
        }
        part_s[grp][c] = acc;
        if (c == 0) cnt_s[grp] = cnt;
    }
    __syncthreads();
    const int cntT = cnt_s[0] + cnt_s[1] + cnt_s[2] + cnt_s[3];
    if (tid < HH)
        mean_s[tid] = ((part_s[0][tid] + part_s[1][tid]) + (part_s[2][tid] + part_s[3][tid]))
                      / (float)(cntT > 0 ? cntT : 1);
    __syncthreads();

    {
        float p = 0.f;
        const int ib = grp << 6;
        #pragma unroll 4
        for (int i = ib; i < ib + 64; i++) p += mean_s[i] * Wc[i * HH + c];
        part_s[grp][c] = p;
    }
    __syncthreads();
    if (tid < HH)
        ctx_s[tid] = ((part_s[0][tid] + part_s[1][tid]) + (part_s[2][tid] + part_s[3][tid]))
                     + bc[tid];
    __syncthreads();

    const int wid = tid >> 5, lane = tid & 31;
    for (int k = wid; k < KKc; k += 32) {
        const int idx = idx_s[k];
        float s = -1e30f;
        if (idx < NN) {
            const float* row = enc + ((size_t)b * NN + idx) * HH;
            float part = 0.f;
            #pragma unroll
            for (int i = 0; i < 8; i++) part += ctx_s[lane + i * 32] * row[lane + i * 32];
            #pragma unroll
            for (int o = 16; o; o >>= 1) part += __shfl_xor_sync(0xffffffffu, part, o);
            s = part;
        }
        if (lane == 0) sc_s[k] = s;
    }
    __syncthreads();

    red_s[tid] = (tid < KKc) ? sc_s[tid] : -1e30f;
    __syncthreads();
    for (int st = 512; st; st >>= 1) {
        if (tid < st) red_s[tid] = fmaxf(red_s[tid], red_s[tid + st]);
        __syncthreads();
    }
    const float m = red_s[0];
    __syncthreads();

    const int myidx = (tid < KKc) ? idx_s[tid] : NN;
    const float e = (myidx < NN) ? expf(sc_s[tid] - m) : 0.f;
    red_s[tid] = e;
    __syncthreads();
    for (int st = 512; st; st >>= 1) {
        if (tid < st) red_s[tid] += red_s[tid + st];
        __syncthreads();
    }
    const float denom = red_s[0];
    __syncthreads();

    float a = rintf(e / denom * 100.f);
    red_s[tid] = a;
    __syncthreads();
    for (int st = 512; st; st >>= 1) {
        if (tid < st) red_s[tid] += red_s[tid + st];
        __syncthreads();
    }
    const float diff = 100.f - red_s[0];
    __syncthreads();

    if (tid == 0 && myidx < NN) a += diff;
    if (myidx < NN) bw[b * NN + myidx] = a;
}

// ---------------- launch ----------------
extern "C" void kernel_launch(void* const* d_in, const int* in_sizes, int n_in,
                              void* d_out, int out_size)
{
    const float* x    = (const float*)d_in[0];
    const int*   sel  = (const int*)  d_in[1];
    const float* W_in = (const float*)d_in[2];
    const float* b_in = (const float*)d_in[3];
    const float* Wqkv = (const float*)d_in[4];
    const float* bqkv = (const float*)d_in[5];
    const float* Wo   = (const float*)d_in[6];
    const float* bo   = (const float*)d_in[7];
    const float* ln1g = (const float*)d_in[8];
    const float* ln1b = (const float*)d_in[9];
    const float* W1   = (const float*)d_in[10];
    const float* b1   = (const float*)d_in[11];
    const float* W2   = (const float*)d_in[12];
    const float* b2   = (const float*)d_in[13];
    const float* ln2g = (const float*)d_in[14];
    const float* ln2b = (const float*)d_in[15];
    const float* Wc   = (const float*)d_in[16];
    const float* bc   = (const float*)d_in[17];

    float *h, *tmp;
    bf16 *xh, *xl, *hbh, *hbl, *qh, *ql, *ah, *al, *fh, *fl, *wh, *wl;
    cudaGetSymbolAddress((void**)&h,   g_h);   cudaGetSymbolAddress((void**)&tmp, g_tmp);
    cudaGetSymbolAddress((void**)&xh,  g_xh);  cudaGetSymbolAddress((void**)&xl,  g_xl);
    cudaGetSymbolAddress((void**)&hbh, g_hbh); cudaGetSymbolAddress((void**)&hbl, g_hbl);
    cudaGetSymbolAddress((void**)&qh,  g_qh);  cudaGetSymbolAddress((void**)&ql,  g_ql);
    cudaGetSymbolAddress((void**)&ah,  g_ah);  cudaGetSymbolAddress((void**)&al,  g_al);
    cudaGetSymbolAddress((void**)&fh,  g_fh);  cudaGetSymbolAddress((void**)&fl,  g_fl);
    cudaGetSymbolAddress((void**)&wh,  g_wh);  cudaGetSymbolAddress((void**)&wl,  g_wl);

    const int GSM = 8 * PLB;     // 81920
    const int ASM_ = 8 * PLV;    // 40960
    cudaFuncSetAttribute(gemm_mma, cudaFuncAttributeMaxDynamicSharedMemorySize, GSM);
    cudaFuncSetAttribute(attn_mma, cudaFuncAttributeMaxDynamicSharedMemorySize, ASM_);

    Segs S;
    S.seg[0] = { x, xh, xl, 0, 0, 1, (TOK * DIN) / 1024 };
    S.seg[1] = { W_in, wh + WOFF_IN, wl + WOFF_IN, DIN, HH, 0, (DIN/32)*(HH/32) };
    for (int l = 0; l < LL; l++) {
        S.seg[2+l] = { Wqkv + (size_t)l*HH*3*HH, wh + WOFF_QKV + l*HH*3*HH,
                       wl + WOFF_QKV + l*HH*3*HH, HH, 3*HH, 0, (HH/32)*(3*HH/32) };
        S.seg[4+l] = { Wo + (size_t)l*HH*HH, wh + WOFF_O + l*HH*HH,
                       wl + WOFF_O + l*HH*HH, HH, HH, 0, (HH/32)*(HH/32) };
        S.seg[6+l] = { W1 + (size_t)l*HH*FF, wh + WOFF_1 + l*HH*FF,
                       wl + WOFF_1 + l*HH*FF, HH, FF, 0, (HH/32)*(FF/32) };
        S.seg[8+l] = { W2 + (size_t)l*FF*HH, wh + WOFF_2 + l*FF*HH,
                       wl + WOFF_2 + l*FF*HH, FF, HH, 0, (FF/32)*(HH/32) };
    }
    prep_kernel<<<dim3(1024, 10), dim3(32, 8)>>>(S);

    gemm_mma<<<dim3(HH/128, TOK/128), 256, GSM>>>(
        xh, xl, wh + WOFF_IN, wl + WOFF_IN, b_in, nullptr, h, hbh, hbl, DIN, HH, 0);

    for (int l = 0; l < LL; l++) {
        gemm_mma<<<dim3(3*HH/128, TOK/128), 256, GSM>>>(
            hbh, hbl, wh + WOFF_QKV + l*HH*3*HH, wl + WOFF_QKV + l*HH*3*HH,
            bqkv + l*3*HH, nullptr, nullptr, qh, ql, HH, 3*HH, 0);
        attn_mma<<<dim3(NN/128, BB*8), 128, ASM_>>>(qh, ql, ah, al);
        gemm_mma<<<dim3(HH/128, TOK/128), 256, GSM>>>(
            ah, al, wh + WOFF_O + l*HH*HH, wl + WOFF_O + l*HH*HH,
            bo + l*HH, h, tmp, nullptr, nullptr, HH, HH, 0);
        ln_kernel<<<TOK/8, 256>>>(tmp, ln1g + l*HH, ln1b + l*HH, h, hbh, hbl);
        gemm_mma<<<dim3(FF/128, TOK/128), 256, GSM>>>(
            hbh, hbl, wh + WOFF_1 + l*HH*FF, wl + WOFF_1 + l*HH*FF,
            b1 + l*FF, nullptr, nullptr, fh, fl, HH, FF, 1);
        gemm_mma<<<dim3(HH/128, TOK/128), 256, GSM>>>(
            fh, fl, wh + WOFF_2 + l*FF*HH, wl + WOFF_2 + l*FF*HH,
            b2 + l*HH, h, tmp, nullptr, nullptr, FF, HH, 0);
        ln_kernel<<<TOK/8, 256>>>(tmp, ln2g + l*HH, ln2b + l*HH, h, hbh, hbl);
    }

    float* outf = (float*)d_out;
    const int idx_elems = BB * KKc, bw_elems = BB * NN;
    const int both = (out_size >= idx_elems + bw_elems) ? 1 : 0;

    const int covered = both ? (idx_elems + bw_elems) : bw_elems;
    if (out_size > covered)
        init_out_kernel<<<(out_size + 255) / 256, 256>>>(outf, out_size);

    alloc_kernel<<<BB, 1024>>>(h, sel, Wc, bc, outf, both);
}